// round 1
// baseline (speedup 1.0000x reference)
#include <cuda_runtime.h>
#include <math.h>
#include <math_constants.h>

#define BB 8
#define LL 1024
#define CC 768
#define NH 12
#define HD 64
#define M_TOT (BB*LL)      /* 8192 */
#define NQKV (3*CC)        /* 2304 */

// ---------------- scratch (device globals: no allocation allowed) ----------
__device__ float g_qkv[(size_t)M_TOT * NQKV];        // 75.5 MB
__device__ float g_q[(size_t)BB*NH*LL*HD];           // 25 MB, layout [b,h,l,e]
__device__ float g_k[(size_t)BB*NH*LL*HD];
__device__ float g_v[(size_t)BB*NH*LL*HD];
__device__ float g_ao[(size_t)M_TOT * CC];           // attention out [b,l,c]

// ---------------------------------------------------------------------------
// GEMM (NT): C[M,N] = A[M,K] * B[N,K]^T, fp32, BM=BN=128, BK=8, 256 thr, 8x8
// Requires M%128==0, N%128==0, K%8==0 (true for all uses here).
// ---------------------------------------------------------------------------
__global__ __launch_bounds__(256) void gemm_nt_kernel(
    const float* __restrict__ A, const float* __restrict__ B,
    float* __restrict__ C, int M, int N, int K)
{
    constexpr int BM = 128, BN = 128, BK = 8;
    __shared__ float As[BK][BM];
    __shared__ float Bs[BK][BN];

    const int tid = threadIdx.x;
    const int tx = tid & 15;        // 0..15  -> N direction
    const int ty = tid >> 4;        // 0..15  -> M direction
    const int row0 = blockIdx.y * BM;
    const int col0 = blockIdx.x * BN;

    const int lrow = tid >> 1;          // 0..127
    const int lk   = (tid & 1) * 4;     // 0 or 4
    const float* Ap = A + (size_t)(row0 + lrow) * K + lk;
    const float* Bp = B + (size_t)(col0 + lrow) * K + lk;

    float acc[8][8];
#pragma unroll
    for (int i = 0; i < 8; i++)
#pragma unroll
        for (int j = 0; j < 8; j++) acc[i][j] = 0.f;

    for (int k0 = 0; k0 < K; k0 += BK) {
        float4 a4 = *(const float4*)(Ap + k0);
        float4 b4 = *(const float4*)(Bp + k0);
        As[lk+0][lrow] = a4.x; As[lk+1][lrow] = a4.y;
        As[lk+2][lrow] = a4.z; As[lk+3][lrow] = a4.w;
        Bs[lk+0][lrow] = b4.x; Bs[lk+1][lrow] = b4.y;
        Bs[lk+2][lrow] = b4.z; Bs[lk+3][lrow] = b4.w;
        __syncthreads();
#pragma unroll
        for (int kk = 0; kk < BK; kk++) {
            float af[8], bf[8];
            *(float4*)(af)     = *(const float4*)(&As[kk][ty*8]);
            *(float4*)(af + 4) = *(const float4*)(&As[kk][ty*8 + 4]);
            *(float4*)(bf)     = *(const float4*)(&Bs[kk][tx*8]);
            *(float4*)(bf + 4) = *(const float4*)(&Bs[kk][tx*8 + 4]);
#pragma unroll
            for (int i = 0; i < 8; i++)
#pragma unroll
                for (int j = 0; j < 8; j++)
                    acc[i][j] = fmaf(af[i], bf[j], acc[i][j]);
        }
        __syncthreads();
    }

#pragma unroll
    for (int i = 0; i < 8; i++) {
        float* crow = C + (size_t)(row0 + ty*8 + i) * N + col0 + tx*8;
        *(float4*)(crow)     = make_float4(acc[i][0], acc[i][1], acc[i][2], acc[i][3]);
        *(float4*)(crow + 4) = make_float4(acc[i][4], acc[i][5], acc[i][6], acc[i][7]);
    }
}

// ---------------------------------------------------------------------------
// QKV epilogue: RMSNorm + RoPE for q/k, relayout q/k/v -> [b,h,l,e].
// One warp per (b,l,h). Lane j owns elements j and j+32 -> RoPE pair in regs.
// ---------------------------------------------------------------------------
__global__ __launch_bounds__(256) void qkv_post_kernel(
    const float* __restrict__ qg, const float* __restrict__ kg)
{
    const int widx = blockIdx.x * 8 + (threadIdx.x >> 5);  // 0 .. B*L*NH-1
    const int lane = threadIdx.x & 31;
    const int h = widx % NH;
    const int l = (widx / NH) % LL;
    const int b = widx / (NH * LL);

    const float* rowp = g_qkv + (size_t)(b * LL + l) * NQKV + h * HD;

    // inv_freq = 10000^(-lane/32); log2(10000) = 13.287712379549449
    const float ifr = exp2f(-13.287712379549449f * (float)lane * (1.0f / 32.0f));
    const float ang = (float)l * ifr;
    const float cs = cosf(ang), sn = sinf(ang);
    const size_t dsto = ((size_t)(b * NH + h) * LL + l) * HD;

    // ---- Q ----
    {
        float x1 = rowp[lane], x2 = rowp[lane + 32];
        float ss = x1 * x1 + x2 * x2;
#pragma unroll
        for (int o = 16; o; o >>= 1) ss += __shfl_xor_sync(0xffffffffu, ss, o);
        float r = rsqrtf(ss * (1.0f / HD) + 1e-6f);
        float n1 = x1 * r * qg[lane], n2 = x2 * r * qg[lane + 32];
        g_q[dsto + lane]      = n1 * cs - n2 * sn;
        g_q[dsto + lane + 32] = n1 * sn + n2 * cs;
    }
    // ---- K ----
    {
        float x1 = rowp[CC + lane], x2 = rowp[CC + lane + 32];
        float ss = x1 * x1 + x2 * x2;
#pragma unroll
        for (int o = 16; o; o >>= 1) ss += __shfl_xor_sync(0xffffffffu, ss, o);
        float r = rsqrtf(ss * (1.0f / HD) + 1e-6f);
        float n1 = x1 * r * kg[lane], n2 = x2 * r * kg[lane + 32];
        g_k[dsto + lane]      = n1 * cs - n2 * sn;
        g_k[dsto + lane + 32] = n1 * sn + n2 * cs;
    }
    // ---- V (copy/relayout) ----
    g_v[dsto + lane]      = rowp[2 * CC + lane];
    g_v[dsto + lane + 32] = rowp[2 * CC + lane + 32];
}

// ---------------------------------------------------------------------------
// Flash attention, fp32, Bq=Bk=64, hd=64. 256 threads (16x16), 4x4 microtile.
// Smem: Qs(16KB) + Ks(16KB, reused as P) + Vs(16KB) = 48KB static.
// K^T operand and P are XOR-swizzled at float4 granularity: f4 = e4 ^ (row>>2).
// Writes O (softmax-normalized) to g_ao in [b,l,c] layout.
// ---------------------------------------------------------------------------
__global__ __launch_bounds__(256) void attn_kernel()
{
    __shared__ float Qs[64 * 64];
    __shared__ float Ks[64 * 64];   // reused as P after S is computed
    __shared__ float Vs[64 * 64];

    const int tid = threadIdx.x;
    const int tx = tid & 15;        // column group (cols tx*4..tx*4+3)
    const int ty = tid >> 4;        // row group   (rows ty*4..ty*4+3)
    const int qt = blockIdx.x;      // q tile 0..15
    const int h  = blockIdx.y;
    const int b  = blockIdx.z;

    const float* Qg = g_q + ((size_t)(b * NH + h) * LL + qt * 64) * HD;
    const float* Kg = g_k + (size_t)(b * NH + h) * LL * HD;
    const float* Vg = g_v + (size_t)(b * NH + h) * LL * HD;

    // load Q tile (pre-scaled by 1/sqrt(hd) = 0.125)
    for (int i = tid; i < 64 * 16; i += 256) {
        int r = i >> 4, e4 = i & 15;
        float4 v = *(const float4*)(Qg + r * HD + e4 * 4);
        v.x *= 0.125f; v.y *= 0.125f; v.z *= 0.125f; v.w *= 0.125f;
        *(float4*)(&Qs[r * 64 + e4 * 4]) = v;
    }

    float m[4], lsum[4], O[4][4];
#pragma unroll
    for (int i = 0; i < 4; i++) {
        m[i] = -1e30f; lsum[i] = 0.f;
#pragma unroll
        for (int j = 0; j < 4; j++) O[i][j] = 0.f;
    }

    for (int kt = 0; kt < 16; kt++) {
        __syncthreads();   // prior-iter P/V reads done (and Q load visible, iter 0)
        // load K (swizzled) and V tiles
        for (int i = tid; i < 64 * 16; i += 256) {
            int c = i >> 4, e4 = i & 15;
            float4 kv = *(const float4*)(Kg + (size_t)(kt * 64 + c) * HD + e4 * 4);
            int f = e4 ^ (c >> 2);
            *(float4*)(&Ks[c * 64 + f * 4]) = kv;
            float4 vv = *(const float4*)(Vg + (size_t)(kt * 64 + c) * HD + e4 * 4);
            *(float4*)(&Vs[c * 64 + e4 * 4]) = vv;
        }
        __syncthreads();

        // ---- S = Q K^T (scaled) ----
        float S[4][4];
#pragma unroll
        for (int i = 0; i < 4; i++)
#pragma unroll
            for (int j = 0; j < 4; j++) S[i][j] = 0.f;

#pragma unroll 4
        for (int e = 0; e < 64; e++) {
            float af[4], bf[4];
#pragma unroll
            for (int i = 0; i < 4; i++) af[i] = Qs[(ty * 4 + i) * 64 + e];
            const int sw = (((e >> 2) ^ tx) << 2) + (e & 3);
#pragma unroll
            for (int j = 0; j < 4; j++) bf[j] = Ks[(tx * 4 + j) * 64 + sw];
#pragma unroll
            for (int i = 0; i < 4; i++)
#pragma unroll
                for (int j = 0; j < 4; j++)
                    S[i][j] = fmaf(af[i], bf[j], S[i][j]);
        }

        // ---- online softmax update ----
        float alpha[4];
#pragma unroll
        for (int i = 0; i < 4; i++) {
            float tm = fmaxf(fmaxf(S[i][0], S[i][1]), fmaxf(S[i][2], S[i][3]));
#pragma unroll
            for (int o = 8; o; o >>= 1) tm = fmaxf(tm, __shfl_xor_sync(0xffffffffu, tm, o));
            float mnew = fmaxf(m[i], tm);
            alpha[i] = expf(m[i] - mnew);
            float rs = 0.f;
#pragma unroll
            for (int j = 0; j < 4; j++) { S[i][j] = expf(S[i][j] - mnew); rs += S[i][j]; }
#pragma unroll
            for (int o = 8; o; o >>= 1) rs += __shfl_xor_sync(0xffffffffu, rs, o);
            lsum[i] = lsum[i] * alpha[i] + rs;
            m[i] = mnew;
#pragma unroll
            for (int j = 0; j < 4; j++) O[i][j] *= alpha[i];
        }

        __syncthreads();   // everyone done reading Ks
        // ---- write P into Ks buffer (swizzled) ----
#pragma unroll
        for (int i = 0; i < 4; i++) {
            int r = ty * 4 + i;
            int f = tx ^ ty;            // (r>>2) == ty
            *(float4*)(&Ks[r * 64 + f * 4]) =
                make_float4(S[i][0], S[i][1], S[i][2], S[i][3]);
        }
        __syncthreads();

        // ---- O += P V ----
#pragma unroll 4
        for (int c = 0; c < 64; c++) {
            float pf[4];
            const int sw = (((c >> 2) ^ ty) << 2) + (c & 3);
#pragma unroll
            for (int i = 0; i < 4; i++) pf[i] = Ks[(ty * 4 + i) * 64 + sw];
            float4 vv = *(const float4*)(&Vs[c * 64 + tx * 4]);
#pragma unroll
            for (int i = 0; i < 4; i++) {
                O[i][0] = fmaf(pf[i], vv.x, O[i][0]);
                O[i][1] = fmaf(pf[i], vv.y, O[i][1]);
                O[i][2] = fmaf(pf[i], vv.z, O[i][2]);
                O[i][3] = fmaf(pf[i], vv.w, O[i][3]);
            }
        }
    }

    // ---- normalize + store to [b, l, h*64+d] ----
#pragma unroll
    for (int i = 0; i < 4; i++) {
        float inv = 1.0f / lsum[i];
        float* outp = g_ao + ((size_t)b * LL + qt * 64 + ty * 4 + i) * CC + h * HD + tx * 4;
        *(float4*)outp = make_float4(O[i][0] * inv, O[i][1] * inv,
                                     O[i][2] * inv, O[i][3] * inv);
    }
}

// ---------------------------------------------------------------------------
extern "C" void kernel_launch(void* const* d_in, const int* in_sizes, int n_in,
                              void* d_out, int out_size)
{
    const float* x      = (const float*)d_in[0];  // [8,32,32,768]
    const float* w_qkv  = (const float*)d_in[1];  // [2304,768]
    const float* qgam   = (const float*)d_in[2];  // [64]
    const float* kgam   = (const float*)d_in[3];  // [64]
    const float* w_out  = (const float*)d_in[4];  // [768,768]
    float* out = (float*)d_out;                   // [8,32,32,768]

    float* qkv; cudaGetSymbolAddress((void**)&qkv, g_qkv);
    float* ao;  cudaGetSymbolAddress((void**)&ao,  g_ao);

    // 1) QKV projection: [8192,768] x [2304,768]^T -> [8192,2304]
    gemm_nt_kernel<<<dim3(NQKV / 128, M_TOT / 128), 256>>>(
        x, w_qkv, qkv, M_TOT, NQKV, CC);

    // 2) RMSNorm + RoPE + relayout
    qkv_post_kernel<<<(BB * LL * NH) / 8, 256>>>(qgam, kgam);

    // 3) Flash attention
    attn_kernel<<<dim3(LL / 64, NH, BB), 256>>>();

    // 4) Output projection: [8192,768] x [768,768]^T -> d_out
    gemm_nt_kernel<<<dim3(CC / 128, M_TOT / 128), 256>>>(
        ao, w_out, out, M_TOT, CC, CC);
}

// round 3
// speedup vs baseline: 1.4393x; 1.4393x over previous
#include <cuda_runtime.h>
#include <cuda_bf16.h>
#include <cstdint>
#include <math.h>

#define BB 8
#define LL 1024
#define CC 768
#define NH 12
#define HD 64
#define M_TOT (BB*LL)      /* 8192 */
#define NQKV (3*CC)        /* 2304 */

// ---------------- scratch (device globals: no allocation allowed) ----------
__device__ float g_qkv[(size_t)M_TOT * NQKV];
__device__ float g_q[(size_t)BB*NH*LL*HD];
__device__ float g_k[(size_t)BB*NH*LL*HD];
__device__ float g_v[(size_t)BB*NH*LL*HD];
__device__ float g_ao[(size_t)M_TOT * CC];

// ---------------------------------------------------------------------------
__device__ __forceinline__ float ex2f(float x) {
    float y;
    asm("ex2.approx.ftz.f32 %0, %1;" : "=f"(y) : "f"(x));
    return y;
}

// split fp32 -> (bf16 hi, bf16 lo) packed pairs (two floats -> one hi word, one lo word)
__device__ __forceinline__ void split2(float a, float b, uint32_t& hi, uint32_t& lo) {
    __nv_bfloat16 ha = __float2bfloat16_rn(a);
    __nv_bfloat16 hb = __float2bfloat16_rn(b);
    float ra = a - __bfloat162float(ha);
    float rb = b - __bfloat162float(hb);
    __nv_bfloat16 la = __float2bfloat16_rn(ra);
    __nv_bfloat16 lb = __float2bfloat16_rn(rb);
    hi = ((uint32_t)*(uint16_t*)&hb << 16) | (uint32_t)*(uint16_t*)&ha;
    lo = ((uint32_t)*(uint16_t*)&lb << 16) | (uint32_t)*(uint16_t*)&la;
}

#define MMA_BF16(Cr, A0, A1, A2, A3, B0, B1) \
    asm volatile("mma.sync.aligned.m16n8k16.row.col.f32.bf16.bf16.f32 " \
        "{%0,%1,%2,%3}, {%4,%5,%6,%7}, {%8,%9}, {%0,%1,%2,%3};" \
        : "+f"((Cr)[0]), "+f"((Cr)[1]), "+f"((Cr)[2]), "+f"((Cr)[3]) \
        : "r"(A0), "r"(A1), "r"(A2), "r"(A3), "r"(B0), "r"(B1))

// ===========================================================================
// GEMM (NT) via mma.sync bf16x3: C[M,N] = A[M,K]*B[N,K]^T, fp32-accurate.
// BM=BN=128, BK=32, 256 threads = 8 warps (2 x 4), warp tile 64x32.
// Smem rows padded to 80B (20 words): fragment LDS is bank-conflict-free.
// ===========================================================================
__global__ __launch_bounds__(256) void gemm_mma_kernel(
    const float* __restrict__ A, const float* __restrict__ B,
    float* __restrict__ C, int M, int N, int K)
{
    __shared__ uint32_t As_h[128 * 20];
    __shared__ uint32_t As_l[128 * 20];
    __shared__ uint32_t Bs_h[128 * 20];
    __shared__ uint32_t Bs_l[128 * 20];

    const int tid  = threadIdx.x;
    const int wid  = tid >> 5;
    const int lane = tid & 31;
    const int wm = wid & 1;          // 0..1 -> 64-row slab
    const int wn = wid >> 1;         // 0..3 -> 32-col slab
    const int row0 = blockIdx.y * 128;
    const int col0 = blockIdx.x * 128;

    const int lrow  = tid >> 1;      // 0..127
    const int lhalf = tid & 1;       // 0..1 -> 16-float half of the 32-float row

    float c[4][4][4];
#pragma unroll
    for (int m = 0; m < 4; m++)
#pragma unroll
        for (int n = 0; n < 4; n++)
#pragma unroll
            for (int q = 0; q < 4; q++) c[m][n][q] = 0.f;

    const int q4 = lane >> 2;        // fragment group id
    const int l3 = lane & 3;

    for (int k0 = 0; k0 < K; k0 += 32) {
        __syncthreads();
        // ---- load + split + store: each thread handles 16 floats of A, 16 of B
        {
            const float* ap = A + (size_t)(row0 + lrow) * K + k0 + lhalf * 16;
            const float* bp = B + (size_t)(col0 + lrow) * K + k0 + lhalf * 16;
            const int wbase = lrow * 20 + lhalf * 8;
#pragma unroll
            for (int j = 0; j < 4; j++) {
                float4 v = *(const float4*)(ap + j * 4);
                uint32_t h0, l0, h1, l1;
                split2(v.x, v.y, h0, l0);
                split2(v.z, v.w, h1, l1);
                As_h[wbase + j*2]     = h0;  As_h[wbase + j*2 + 1] = h1;
                As_l[wbase + j*2]     = l0;  As_l[wbase + j*2 + 1] = l1;
                float4 w = *(const float4*)(bp + j * 4);
                split2(w.x, w.y, h0, l0);
                split2(w.z, w.w, h1, l1);
                Bs_h[wbase + j*2]     = h0;  Bs_h[wbase + j*2 + 1] = h1;
                Bs_l[wbase + j*2]     = l0;  Bs_l[wbase + j*2 + 1] = l1;
            }
        }
        __syncthreads();

        // ---- compute: 2 k-steps of m16n8k16
#pragma unroll
        for (int ks = 0; ks < 2; ks++) {
            const int kb = ks * 8;
            uint32_t ah[4][4], al[4][4];
#pragma unroll
            for (int m = 0; m < 4; m++) {
                int base = (wm * 64 + m * 16 + q4) * 20 + kb + l3;
                ah[m][0] = As_h[base];       ah[m][1] = As_h[base + 160];
                ah[m][2] = As_h[base + 4];   ah[m][3] = As_h[base + 164];
                al[m][0] = As_l[base];       al[m][1] = As_l[base + 160];
                al[m][2] = As_l[base + 4];   al[m][3] = As_l[base + 164];
            }
#pragma unroll
            for (int n = 0; n < 4; n++) {
                int bbase = (wn * 32 + n * 8 + q4) * 20 + kb + l3;
                uint32_t bh0 = Bs_h[bbase], bh1 = Bs_h[bbase + 4];
                uint32_t bl0 = Bs_l[bbase], bl1 = Bs_l[bbase + 4];
#pragma unroll
                for (int m = 0; m < 4; m++) {
                    MMA_BF16(c[m][n], ah[m][0], ah[m][1], ah[m][2], ah[m][3], bh0, bh1);
                    MMA_BF16(c[m][n], ah[m][0], ah[m][1], ah[m][2], ah[m][3], bl0, bl1);
                    MMA_BF16(c[m][n], al[m][0], al[m][1], al[m][2], al[m][3], bh0, bh1);
                }
            }
        }
    }

    // ---- epilogue: write C fragments
#pragma unroll
    for (int m = 0; m < 4; m++) {
        const int r = row0 + wm * 64 + m * 16 + q4;
#pragma unroll
        for (int n = 0; n < 4; n++) {
            const int cc = col0 + wn * 32 + n * 8 + l3 * 2;
            *(float2*)(C + (size_t)r * N + cc)       = make_float2(c[m][n][0], c[m][n][1]);
            *(float2*)(C + (size_t)(r + 8) * N + cc) = make_float2(c[m][n][2], c[m][n][3]);
        }
    }
}

// ---------------------------------------------------------------------------
// QKV epilogue: RMSNorm + RoPE for q/k, relayout q/k/v -> [b,h,l,e].
// Q additionally prescaled by 0.125*log2(e) so attention works in log2 domain.
// ---------------------------------------------------------------------------
__global__ __launch_bounds__(256) void qkv_post_kernel(
    const float* __restrict__ qg, const float* __restrict__ kg)
{
    const int widx = blockIdx.x * 8 + (threadIdx.x >> 5);
    const int lane = threadIdx.x & 31;
    const int h = widx % NH;
    const int l = (widx / NH) % LL;
    const int b = widx / (NH * LL);

    const float* rowp = g_qkv + (size_t)(b * LL + l) * NQKV + h * HD;
    const float ifr = exp2f(-13.287712379549449f * (float)lane * (1.0f / 32.0f));
    const float ang = (float)l * ifr;
    const float cs = cosf(ang), sn = sinf(ang);
    const size_t dsto = ((size_t)(b * NH + h) * LL + l) * HD;

    {
        float x1 = rowp[lane], x2 = rowp[lane + 32];
        float ss = x1 * x1 + x2 * x2;
#pragma unroll
        for (int o = 16; o; o >>= 1) ss += __shfl_xor_sync(0xffffffffu, ss, o);
        float r = rsqrtf(ss * (1.0f / HD) + 1e-6f);
        float n1 = x1 * r * qg[lane], n2 = x2 * r * qg[lane + 32];
        g_q[dsto + lane]      = n1 * cs - n2 * sn;
        g_q[dsto + lane + 32] = n1 * sn + n2 * cs;
    }
    {
        float x1 = rowp[CC + lane], x2 = rowp[CC + lane + 32];
        float ss = x1 * x1 + x2 * x2;
#pragma unroll
        for (int o = 16; o; o >>= 1) ss += __shfl_xor_sync(0xffffffffu, ss, o);
        float r = rsqrtf(ss * (1.0f / HD) + 1e-6f);
        float n1 = x1 * r * kg[lane], n2 = x2 * r * kg[lane + 32];
        g_k[dsto + lane]      = n1 * cs - n2 * sn;
        g_k[dsto + lane + 32] = n1 * sn + n2 * cs;
    }
    g_v[dsto + lane]      = rowp[2 * CC + lane];
    g_v[dsto + lane + 32] = rowp[2 * CC + lane + 32];
}

// ---------------------------------------------------------------------------
// Flash attention, fp32 SIMT, softmax in log2 domain (ex2.approx).
// ---------------------------------------------------------------------------
__global__ __launch_bounds__(256) void attn_kernel()
{
    __shared__ float Qs[64 * 64];
    __shared__ float Ks[64 * 64];
    __shared__ float Vs[64 * 64];

    const int tid = threadIdx.x;
    const int tx = tid & 15;
    const int ty = tid >> 4;
    const int qt = blockIdx.x;
    const int h  = blockIdx.y;
    const int b  = blockIdx.z;

    const float* Qg = g_q + ((size_t)(b * NH + h) * LL + qt * 64) * HD;
    const float* Kg = g_k + (size_t)(b * NH + h) * LL * HD;
    const float* Vg = g_v + (size_t)(b * NH + h) * LL * HD;

    // Q prescaled by 0.125 * log2(e): softmax done with ex2
    const float qscale = 0.125f * 1.4426950408889634f;
    for (int i = tid; i < 64 * 16; i += 256) {
        int r = i >> 4, e4 = i & 15;
        float4 v = *(const float4*)(Qg + r * HD + e4 * 4);
        v.x *= qscale; v.y *= qscale; v.z *= qscale; v.w *= qscale;
        *(float4*)(&Qs[r * 64 + e4 * 4]) = v;
    }

    float m[4], lsum[4], O[4][4];
#pragma unroll
    for (int i = 0; i < 4; i++) {
        m[i] = -1e30f; lsum[i] = 0.f;
#pragma unroll
        for (int j = 0; j < 4; j++) O[i][j] = 0.f;
    }

    for (int kt = 0; kt < 16; kt++) {
        __syncthreads();
        for (int i = tid; i < 64 * 16; i += 256) {
            int c = i >> 4, e4 = i & 15;
            float4 kv = *(const float4*)(Kg + (size_t)(kt * 64 + c) * HD + e4 * 4);
            int f = e4 ^ (c >> 2);
            *(float4*)(&Ks[c * 64 + f * 4]) = kv;
            float4 vv = *(const float4*)(Vg + (size_t)(kt * 64 + c) * HD + e4 * 4);
            *(float4*)(&Vs[c * 64 + e4 * 4]) = vv;
        }
        __syncthreads();

        float S[4][4];
#pragma unroll
        for (int i = 0; i < 4; i++)
#pragma unroll
            for (int j = 0; j < 4; j++) S[i][j] = 0.f;

#pragma unroll 4
        for (int e = 0; e < 64; e++) {
            float af[4], bf[4];
#pragma unroll
            for (int i = 0; i < 4; i++) af[i] = Qs[(ty * 4 + i) * 64 + e];
            const int sw = (((e >> 2) ^ tx) << 2) + (e & 3);
#pragma unroll
            for (int j = 0; j < 4; j++) bf[j] = Ks[(tx * 4 + j) * 64 + sw];
#pragma unroll
            for (int i = 0; i < 4; i++)
#pragma unroll
                for (int j = 0; j < 4; j++)
                    S[i][j] = fmaf(af[i], bf[j], S[i][j]);
        }

        float alpha[4];
#pragma unroll
        for (int i = 0; i < 4; i++) {
            float tm = fmaxf(fmaxf(S[i][0], S[i][1]), fmaxf(S[i][2], S[i][3]));
#pragma unroll
            for (int o = 8; o; o >>= 1) tm = fmaxf(tm, __shfl_xor_sync(0xffffffffu, tm, o));
            float mnew = fmaxf(m[i], tm);
            alpha[i] = ex2f(m[i] - mnew);
            float rs = 0.f;
#pragma unroll
            for (int j = 0; j < 4; j++) { S[i][j] = ex2f(S[i][j] - mnew); rs += S[i][j]; }
#pragma unroll
            for (int o = 8; o; o >>= 1) rs += __shfl_xor_sync(0xffffffffu, rs, o);
            lsum[i] = lsum[i] * alpha[i] + rs;
            m[i] = mnew;
#pragma unroll
            for (int j = 0; j < 4; j++) O[i][j] *= alpha[i];
        }

        __syncthreads();
#pragma unroll
        for (int i = 0; i < 4; i++) {
            int r = ty * 4 + i;
            int f = tx ^ ty;
            *(float4*)(&Ks[r * 64 + f * 4]) =
                make_float4(S[i][0], S[i][1], S[i][2], S[i][3]);
        }
        __syncthreads();

#pragma unroll 4
        for (int cidx = 0; cidx < 64; cidx++) {
            float pf[4];
            const int sw = (((cidx >> 2) ^ ty) << 2) + (cidx & 3);
#pragma unroll
            for (int i = 0; i < 4; i++) pf[i] = Ks[(ty * 4 + i) * 64 + sw];
            float4 vv = *(const float4*)(&Vs[cidx * 64 + tx * 4]);
#pragma unroll
            for (int i = 0; i < 4; i++) {
                O[i][0] = fmaf(pf[i], vv.x, O[i][0]);
                O[i][1] = fmaf(pf[i], vv.y, O[i][1]);
                O[i][2] = fmaf(pf[i], vv.z, O[i][2]);
                O[i][3] = fmaf(pf[i], vv.w, O[i][3]);
            }
        }
    }

#pragma unroll
    for (int i = 0; i < 4; i++) {
        float inv = 1.0f / lsum[i];
        float* outp = g_ao + ((size_t)b * LL + qt * 64 + ty * 4 + i) * CC + h * HD + tx * 4;
        *(float4*)outp = make_float4(O[i][0] * inv, O[i][1] * inv,
                                     O[i][2] * inv, O[i][3] * inv);
    }
}

// ---------------------------------------------------------------------------
extern "C" void kernel_launch(void* const* d_in, const int* in_sizes, int n_in,
                              void* d_out, int out_size)
{
    const float* x      = (const float*)d_in[0];
    const float* w_qkv  = (const float*)d_in[1];
    const float* qgam   = (const float*)d_in[2];
    const float* kgam   = (const float*)d_in[3];
    const float* w_out  = (const float*)d_in[4];
    float* out = (float*)d_out;

    float* qkv; cudaGetSymbolAddress((void**)&qkv, g_qkv);
    float* ao;  cudaGetSymbolAddress((void**)&ao,  g_ao);

    // 1) QKV projection: [8192,768] x [2304,768]^T
    gemm_mma_kernel<<<dim3(NQKV / 128, M_TOT / 128), 256>>>(
        x, w_qkv, qkv, M_TOT, NQKV, CC);

    // 2) RMSNorm + RoPE + relayout (Q prescaled for log2-domain softmax)
    qkv_post_kernel<<<(BB * LL * NH) / 8, 256>>>(qgam, kgam);

    // 3) Flash attention (fp32 SIMT, ex2 softmax)
    attn_kernel<<<dim3(LL / 64, NH, BB), 256>>>();

    // 4) Output projection: [8192,768] x [768,768]^T
    gemm_mma_kernel<<<dim3(CC / 128, M_TOT / 128), 256>>>(
        ao, w_out, out, M_TOT, CC, CC);
}

// round 4
// speedup vs baseline: 2.5157x; 1.7478x over previous
#include <cuda_runtime.h>
#include <cuda_bf16.h>
#include <cstdint>
#include <math.h>

#define BB 8
#define LL 1024
#define CC 768
#define NH 12
#define HD 64
#define M_TOT (BB*LL)      /* 8192 */
#define NQKV (3*CC)        /* 2304 */

// ---------------- scratch (device globals: no allocation allowed) ----------
__device__ float g_qkv[(size_t)M_TOT * NQKV];
__device__ float g_ao[(size_t)M_TOT * CC];
// bf16 hi/lo splits, layout [b, h, l, e]
__device__ __nv_bfloat16 g_qh[(size_t)BB*NH*LL*HD];
__device__ __nv_bfloat16 g_ql[(size_t)BB*NH*LL*HD];
__device__ __nv_bfloat16 g_kh[(size_t)BB*NH*LL*HD];
__device__ __nv_bfloat16 g_kl[(size_t)BB*NH*LL*HD];
__device__ __nv_bfloat16 g_vh[(size_t)BB*NH*LL*HD];
__device__ __nv_bfloat16 g_vl[(size_t)BB*NH*LL*HD];

// ---------------------------------------------------------------------------
__device__ __forceinline__ float ex2f(float x) {
    float y;
    asm("ex2.approx.ftz.f32 %0, %1;" : "=f"(y) : "f"(x));
    return y;
}
__device__ __forceinline__ uint32_t smem_u32(const void* p) {
    uint32_t a;
    asm("{ .reg .u64 t; cvta.to.shared.u64 t, %1; cvt.u32.u64 %0, t; }"
        : "=r"(a) : "l"(p));
    return a;
}

// split fp32 pair -> packed bf16 hi word + bf16 lo (residual) word
__device__ __forceinline__ void split2(float a, float b, uint32_t& hi, uint32_t& lo) {
    __nv_bfloat16 ha = __float2bfloat16_rn(a);
    __nv_bfloat16 hb = __float2bfloat16_rn(b);
    float ra = a - __bfloat162float(ha);
    float rb = b - __bfloat162float(hb);
    __nv_bfloat16 la = __float2bfloat16_rn(ra);
    __nv_bfloat16 lb = __float2bfloat16_rn(rb);
    hi = ((uint32_t)*(uint16_t*)&hb << 16) | (uint32_t)*(uint16_t*)&ha;
    lo = ((uint32_t)*(uint16_t*)&lb << 16) | (uint32_t)*(uint16_t*)&la;
}

#define MMA_BF16(Cr, A0, A1, A2, A3, B0, B1) \
    asm volatile("mma.sync.aligned.m16n8k16.row.col.f32.bf16.bf16.f32 " \
        "{%0,%1,%2,%3}, {%4,%5,%6,%7}, {%8,%9}, {%0,%1,%2,%3};" \
        : "+f"((Cr)[0]), "+f"((Cr)[1]), "+f"((Cr)[2]), "+f"((Cr)[3]) \
        : "r"(A0), "r"(A1), "r"(A2), "r"(A3), "r"(B0), "r"(B1))

#define LDSM_X4_T(r0, r1, r2, r3, addr) \
    asm volatile("ldmatrix.sync.aligned.m8n8.x4.trans.shared.b16 {%0,%1,%2,%3}, [%4];" \
        : "=r"(r0), "=r"(r1), "=r"(r2), "=r"(r3) : "r"(addr))

#define CP_ASYNC16(dst, src) \
    asm volatile("cp.async.cg.shared.global [%0], [%1], 16;" \
                 :: "r"(dst), "l"(src) : "memory")
#define CP_COMMIT() asm volatile("cp.async.commit_group;" ::: "memory")
#define CP_WAIT0()  asm volatile("cp.async.wait_group 0;" ::: "memory")
#define CP_WAIT1()  asm volatile("cp.async.wait_group 1;" ::: "memory")

// ===========================================================================
// GEMM (NT) via mma.sync bf16x3 (unchanged from round 3)
// ===========================================================================
__global__ __launch_bounds__(256) void gemm_mma_kernel(
    const float* __restrict__ A, const float* __restrict__ B,
    float* __restrict__ C, int M, int N, int K)
{
    __shared__ uint32_t As_h[128 * 20];
    __shared__ uint32_t As_l[128 * 20];
    __shared__ uint32_t Bs_h[128 * 20];
    __shared__ uint32_t Bs_l[128 * 20];

    const int tid  = threadIdx.x;
    const int wid  = tid >> 5;
    const int lane = tid & 31;
    const int wm = wid & 1;
    const int wn = wid >> 1;
    const int row0 = blockIdx.y * 128;
    const int col0 = blockIdx.x * 128;
    const int lrow  = tid >> 1;
    const int lhalf = tid & 1;

    float c[4][4][4];
#pragma unroll
    for (int m = 0; m < 4; m++)
#pragma unroll
        for (int n = 0; n < 4; n++)
#pragma unroll
            for (int q = 0; q < 4; q++) c[m][n][q] = 0.f;

    const int q4 = lane >> 2;
    const int l3 = lane & 3;

    for (int k0 = 0; k0 < K; k0 += 32) {
        __syncthreads();
        {
            const float* ap = A + (size_t)(row0 + lrow) * K + k0 + lhalf * 16;
            const float* bp = B + (size_t)(col0 + lrow) * K + k0 + lhalf * 16;
            const int wbase = lrow * 20 + lhalf * 8;
#pragma unroll
            for (int j = 0; j < 4; j++) {
                float4 v = *(const float4*)(ap + j * 4);
                uint32_t h0, l0, h1, l1;
                split2(v.x, v.y, h0, l0);
                split2(v.z, v.w, h1, l1);
                As_h[wbase + j*2]     = h0;  As_h[wbase + j*2 + 1] = h1;
                As_l[wbase + j*2]     = l0;  As_l[wbase + j*2 + 1] = l1;
                float4 w = *(const float4*)(bp + j * 4);
                split2(w.x, w.y, h0, l0);
                split2(w.z, w.w, h1, l1);
                Bs_h[wbase + j*2]     = h0;  Bs_h[wbase + j*2 + 1] = h1;
                Bs_l[wbase + j*2]     = l0;  Bs_l[wbase + j*2 + 1] = l1;
            }
        }
        __syncthreads();

#pragma unroll
        for (int ks = 0; ks < 2; ks++) {
            const int kb = ks * 8;
            uint32_t ah[4][4], al[4][4];
#pragma unroll
            for (int m = 0; m < 4; m++) {
                int base = (wm * 64 + m * 16 + q4) * 20 + kb + l3;
                ah[m][0] = As_h[base];       ah[m][1] = As_h[base + 160];
                ah[m][2] = As_h[base + 4];   ah[m][3] = As_h[base + 164];
                al[m][0] = As_l[base];       al[m][1] = As_l[base + 160];
                al[m][2] = As_l[base + 4];   al[m][3] = As_l[base + 164];
            }
#pragma unroll
            for (int n = 0; n < 4; n++) {
                int bbase = (wn * 32 + n * 8 + q4) * 20 + kb + l3;
                uint32_t bh0 = Bs_h[bbase], bh1 = Bs_h[bbase + 4];
                uint32_t bl0 = Bs_l[bbase], bl1 = Bs_l[bbase + 4];
#pragma unroll
                for (int m = 0; m < 4; m++) {
                    MMA_BF16(c[m][n], ah[m][0], ah[m][1], ah[m][2], ah[m][3], bh0, bh1);
                    MMA_BF16(c[m][n], ah[m][0], ah[m][1], ah[m][2], ah[m][3], bl0, bl1);
                    MMA_BF16(c[m][n], al[m][0], al[m][1], al[m][2], al[m][3], bh0, bh1);
                }
            }
        }
    }

#pragma unroll
    for (int m = 0; m < 4; m++) {
        const int r = row0 + wm * 64 + m * 16 + q4;
#pragma unroll
        for (int n = 0; n < 4; n++) {
            const int cc = col0 + wn * 32 + n * 8 + l3 * 2;
            *(float2*)(C + (size_t)r * N + cc)       = make_float2(c[m][n][0], c[m][n][1]);
            *(float2*)(C + (size_t)(r + 8) * N + cc) = make_float2(c[m][n][2], c[m][n][3]);
        }
    }
}

// ---------------------------------------------------------------------------
// QKV epilogue: RMSNorm + RoPE, then bf16 hi/lo split to [b,h,l,e].
// Q pre-scaled by 0.125*log2(e) for log2-domain softmax.
// ---------------------------------------------------------------------------
__device__ __forceinline__ void store_split(__nv_bfloat16* ah, __nv_bfloat16* al,
                                            size_t idx, float v) {
    __nv_bfloat16 h = __float2bfloat16_rn(v);
    ah[idx] = h;
    al[idx] = __float2bfloat16_rn(v - __bfloat162float(h));
}

__global__ __launch_bounds__(256) void qkv_post_kernel(
    const float* __restrict__ qg, const float* __restrict__ kg)
{
    const int widx = blockIdx.x * 8 + (threadIdx.x >> 5);
    const int lane = threadIdx.x & 31;
    const int h = widx % NH;
    const int l = (widx / NH) % LL;
    const int b = widx / (NH * LL);

    const float* rowp = g_qkv + (size_t)(b * LL + l) * NQKV + h * HD;
    const float ifr = exp2f(-13.287712379549449f * (float)lane * (1.0f / 32.0f));
    const float ang = (float)l * ifr;
    const float cs = cosf(ang), sn = sinf(ang);
    const size_t dsto = ((size_t)(b * NH + h) * LL + l) * HD;
    const float QS = 0.125f * 1.4426950408889634f;

    {
        float x1 = rowp[lane], x2 = rowp[lane + 32];
        float ss = x1 * x1 + x2 * x2;
#pragma unroll
        for (int o = 16; o; o >>= 1) ss += __shfl_xor_sync(0xffffffffu, ss, o);
        float r = rsqrtf(ss * (1.0f / HD) + 1e-6f);
        float n1 = x1 * r * qg[lane], n2 = x2 * r * qg[lane + 32];
        store_split(g_qh, g_ql, dsto + lane,      (n1 * cs - n2 * sn) * QS);
        store_split(g_qh, g_ql, dsto + lane + 32, (n1 * sn + n2 * cs) * QS);
    }
    {
        float x1 = rowp[CC + lane], x2 = rowp[CC + lane + 32];
        float ss = x1 * x1 + x2 * x2;
#pragma unroll
        for (int o = 16; o; o >>= 1) ss += __shfl_xor_sync(0xffffffffu, ss, o);
        float r = rsqrtf(ss * (1.0f / HD) + 1e-6f);
        float n1 = x1 * r * kg[lane], n2 = x2 * r * kg[lane + 32];
        store_split(g_kh, g_kl, dsto + lane,      n1 * cs - n2 * sn);
        store_split(g_kh, g_kl, dsto + lane + 32, n1 * sn + n2 * cs);
    }
    store_split(g_vh, g_vl, dsto + lane,      rowp[2 * CC + lane]);
    store_split(g_vh, g_vl, dsto + lane + 32, rowp[2 * CC + lane + 32]);
}

// ===========================================================================
// Flash attention via mma.sync bf16x3.
// Block: 256 thr = 8 warps, 128 q-rows (16 per warp). kt loop over 16 K-tiles
// of 64. Double-buffered K/V smem (hi+lo), cp.async.cg. 144B-padded rows.
// Stage layout (36864B): Khi@0 Klo@9216 Vhi@18432 Vlo@27648, 64 rows x 144B.
// ===========================================================================
#define ASTAGE 36864
#define AROW   144       /* bytes per smem row (64 bf16 + 8 pad) */
#define AROWW  36        /* words per row */

__global__ __launch_bounds__(256) void attn_mma_kernel()
{
    extern __shared__ uint8_t smraw[];
    uint32_t* smw = (uint32_t*)smraw;
    const uint32_t sbase = smem_u32(smraw);

    const int tid  = threadIdx.x;
    const int w    = tid >> 5;
    const int lane = tid & 31;
    const int q4   = lane >> 2;
    const int l3   = lane & 3;
    const int qt = blockIdx.x, h = blockIdx.y, b = blockIdx.z;

    const size_t hb = (size_t)(b * NH + h) * LL * HD;
    const __nv_bfloat16* Qh = g_qh + hb + (size_t)qt * 128 * HD;
    const __nv_bfloat16* Ql = g_ql + hb + (size_t)qt * 128 * HD;
    const __nv_bfloat16* Kh = g_kh + hb;
    const __nv_bfloat16* Kl = g_kl + hb;
    const __nv_bfloat16* Vh = g_vh + hb;
    const __nv_bfloat16* Vl = g_vl + hb;

    // ---- stage Q (hi 128x144 @0, lo @18432) via cp.async, read frags ----
#pragma unroll
    for (int t = 0; t < 8; t++) {
        int i = tid + 256 * t;
        int a = i >> 10, r = (i >> 3) & 127, c = i & 7;
        const __nv_bfloat16* src = (a ? Ql : Qh) + (size_t)r * HD + c * 8;
        CP_ASYNC16(sbase + a * 18432 + r * AROW + c * 16, src);
    }
    CP_COMMIT(); CP_WAIT0();
    __syncthreads();

    uint32_t qhf[4][4], qlf[4][4];
#pragma unroll
    for (int ks = 0; ks < 4; ks++) {
        int base = (w * 16 + q4) * AROWW + ks * 8 + l3;
        qhf[ks][0] = smw[base];                qhf[ks][1] = smw[base + 8 * AROWW];
        qhf[ks][2] = smw[base + 4];            qhf[ks][3] = smw[base + 8 * AROWW + 4];
        qlf[ks][0] = smw[4608 + base];         qlf[ks][1] = smw[4608 + base + 8 * AROWW];
        qlf[ks][2] = smw[4608 + base + 4];     qlf[ks][3] = smw[4608 + base + 8 * AROWW + 4];
    }
    __syncthreads();

    float m0 = -1e30f, m1 = -1e30f, ls0 = 0.f, ls1 = 0.f;
    float O[8][4];
#pragma unroll
    for (int n = 0; n < 8; n++)
#pragma unroll
        for (int q = 0; q < 4; q++) O[n][q] = 0.f;

    // ---- issue kt=0 loads into stage 0 ----
#pragma unroll
    for (int t = 0; t < 8; t++) {
        int i = tid + 256 * t;
        int a = i >> 9, r = (i >> 3) & 63, c = i & 7;
        const __nv_bfloat16* base = (a == 0) ? Kh : (a == 1) ? Kl : (a == 2) ? Vh : Vl;
        CP_ASYNC16(sbase + a * 9216 + r * AROW + c * 16,
                   base + (size_t)r * HD + c * 8);
    }
    CP_COMMIT();

#pragma unroll 1
    for (int kt = 0; kt < 16; kt++) {
        if (kt < 15) {
            uint32_t dst = sbase + ((kt + 1) & 1) * ASTAGE;
            const int r0 = (kt + 1) * 64;
#pragma unroll
            for (int t = 0; t < 8; t++) {
                int i = tid + 256 * t;
                int a = i >> 9, r = (i >> 3) & 63, c = i & 7;
                const __nv_bfloat16* base = (a == 0) ? Kh : (a == 1) ? Kl : (a == 2) ? Vh : Vl;
                CP_ASYNC16(dst + a * 9216 + r * AROW + c * 16,
                           base + (size_t)(r0 + r) * HD + c * 8);
            }
            CP_COMMIT();
            CP_WAIT1();
        } else {
            CP_WAIT0();
        }
        __syncthreads();

        const uint32_t* KW = smw + (kt & 1) * (ASTAGE / 4);
        const uint32_t vbase = sbase + (kt & 1) * ASTAGE + 18432;

        // ---- S = Q K^T (3-term split) ----
        float S[8][4];
#pragma unroll
        for (int n = 0; n < 8; n++)
#pragma unroll
            for (int q = 0; q < 4; q++) S[n][q] = 0.f;

#pragma unroll
        for (int ks = 0; ks < 4; ks++) {
#pragma unroll
            for (int nt = 0; nt < 8; nt++) {
                int kb = (nt * 8 + q4) * AROWW + ks * 8 + l3;
                uint32_t bh0 = KW[kb], bh1 = KW[kb + 4];
                uint32_t bl0 = KW[2304 + kb], bl1 = KW[2304 + kb + 4];
                MMA_BF16(S[nt], qhf[ks][0], qhf[ks][1], qhf[ks][2], qhf[ks][3], bh0, bh1);
                MMA_BF16(S[nt], qhf[ks][0], qhf[ks][1], qhf[ks][2], qhf[ks][3], bl0, bl1);
                MMA_BF16(S[nt], qlf[ks][0], qlf[ks][1], qlf[ks][2], qlf[ks][3], bh0, bh1);
            }
        }

        // ---- online softmax (log2 domain) ----
        float mx0 = -1e30f, mx1 = -1e30f;
#pragma unroll
        for (int nt = 0; nt < 8; nt++) {
            mx0 = fmaxf(mx0, fmaxf(S[nt][0], S[nt][1]));
            mx1 = fmaxf(mx1, fmaxf(S[nt][2], S[nt][3]));
        }
        mx0 = fmaxf(mx0, __shfl_xor_sync(0xffffffffu, mx0, 1));
        mx0 = fmaxf(mx0, __shfl_xor_sync(0xffffffffu, mx0, 2));
        mx1 = fmaxf(mx1, __shfl_xor_sync(0xffffffffu, mx1, 1));
        mx1 = fmaxf(mx1, __shfl_xor_sync(0xffffffffu, mx1, 2));
        float mn0 = fmaxf(m0, mx0), mn1 = fmaxf(m1, mx1);
        float a0 = ex2f(m0 - mn0), a1 = ex2f(m1 - mn1);
        float rs0 = 0.f, rs1 = 0.f;
#pragma unroll
        for (int nt = 0; nt < 8; nt++) {
            S[nt][0] = ex2f(S[nt][0] - mn0); S[nt][1] = ex2f(S[nt][1] - mn0);
            S[nt][2] = ex2f(S[nt][2] - mn1); S[nt][3] = ex2f(S[nt][3] - mn1);
            rs0 += S[nt][0] + S[nt][1];
            rs1 += S[nt][2] + S[nt][3];
        }
        rs0 += __shfl_xor_sync(0xffffffffu, rs0, 1);
        rs0 += __shfl_xor_sync(0xffffffffu, rs0, 2);
        rs1 += __shfl_xor_sync(0xffffffffu, rs1, 1);
        rs1 += __shfl_xor_sync(0xffffffffu, rs1, 2);
        ls0 = ls0 * a0 + rs0;  ls1 = ls1 * a1 + rs1;
        m0 = mn0;  m1 = mn1;
#pragma unroll
        for (int nt = 0; nt < 8; nt++) {
            O[nt][0] *= a0; O[nt][1] *= a0;
            O[nt][2] *= a1; O[nt][3] *= a1;
        }

        // ---- pack P fragments (hi/lo) ----
        uint32_t ph[4][4], pl[4][4];
#pragma unroll
        for (int j = 0; j < 4; j++) {
            split2(S[2*j][0],   S[2*j][1],   ph[j][0], pl[j][0]);
            split2(S[2*j][2],   S[2*j][3],   ph[j][1], pl[j][1]);
            split2(S[2*j+1][0], S[2*j+1][1], ph[j][2], pl[j][2]);
            split2(S[2*j+1][2], S[2*j+1][3], ph[j][3], pl[j][3]);
        }

        // ---- O += P V (3-term split), V via ldmatrix.trans ----
        const uint32_t lrow = (lane & 15);
        const uint32_t lcol = ((lane >> 4) & 1) * 16;
#pragma unroll
        for (int j = 0; j < 4; j++) {
            uint32_t va = vbase + (16 * j + lrow) * AROW + lcol;
#pragma unroll
            for (int p = 0; p < 4; p++) {
                uint32_t addr = va + p * 32;
                uint32_t vh0, vh1, vh2, vh3, vl0, vl1, vl2, vl3;
                LDSM_X4_T(vh0, vh1, vh2, vh3, addr);
                LDSM_X4_T(vl0, vl1, vl2, vl3, addr + 9216);
                MMA_BF16(O[2*p],   ph[j][0], ph[j][1], ph[j][2], ph[j][3], vh0, vh1);
                MMA_BF16(O[2*p+1], ph[j][0], ph[j][1], ph[j][2], ph[j][3], vh2, vh3);
                MMA_BF16(O[2*p],   ph[j][0], ph[j][1], ph[j][2], ph[j][3], vl0, vl1);
                MMA_BF16(O[2*p+1], ph[j][0], ph[j][1], ph[j][2], ph[j][3], vl2, vl3);
                MMA_BF16(O[2*p],   pl[j][0], pl[j][1], pl[j][2], pl[j][3], vh0, vh1);
                MMA_BF16(O[2*p+1], pl[j][0], pl[j][1], pl[j][2], pl[j][3], vh2, vh3);
            }
        }
        __syncthreads();
    }

    // ---- epilogue: normalize, write to g_ao [b, l, c] ----
    const float inv0 = 1.0f / ls0, inv1 = 1.0f / ls1;
    const int row0 = qt * 128 + w * 16 + q4;
    float* out0 = g_ao + ((size_t)b * LL + row0) * CC + h * HD;
    float* out1 = out0 + 8 * CC;
#pragma unroll
    for (int nt = 0; nt < 8; nt++) {
        int cc = nt * 8 + 2 * l3;
        *(float2*)(out0 + cc) = make_float2(O[nt][0] * inv0, O[nt][1] * inv0);
        *(float2*)(out1 + cc) = make_float2(O[nt][2] * inv1, O[nt][3] * inv1);
    }
}

// ---------------------------------------------------------------------------
extern "C" void kernel_launch(void* const* d_in, const int* in_sizes, int n_in,
                              void* d_out, int out_size)
{
    const float* x      = (const float*)d_in[0];
    const float* w_qkv  = (const float*)d_in[1];
    const float* qgam   = (const float*)d_in[2];
    const float* kgam   = (const float*)d_in[3];
    const float* w_out  = (const float*)d_in[4];
    float* out = (float*)d_out;

    float* qkv; cudaGetSymbolAddress((void**)&qkv, g_qkv);
    float* ao;  cudaGetSymbolAddress((void**)&ao,  g_ao);

    cudaFuncSetAttribute(attn_mma_kernel,
                         cudaFuncAttributeMaxDynamicSharedMemorySize, 2 * ASTAGE);

    // 1) QKV projection
    gemm_mma_kernel<<<dim3(NQKV / 128, M_TOT / 128), 256>>>(
        x, w_qkv, qkv, M_TOT, NQKV, CC);

    // 2) RMSNorm + RoPE + bf16 split
    qkv_post_kernel<<<(BB * LL * NH) / 8, 256>>>(qgam, kgam);

    // 3) Flash attention (mma.sync bf16x3)
    attn_mma_kernel<<<dim3(LL / 128, NH, BB), 256, 2 * ASTAGE>>>();

    // 4) Output projection
    gemm_mma_kernel<<<dim3(CC / 128, M_TOT / 128), 256>>>(
        ao, w_out, out, M_TOT, CC, CC);
}

// round 5
// speedup vs baseline: 2.5671x; 1.0204x over previous
#include <cuda_runtime.h>
#include <cuda_bf16.h>
#include <cstdint>
#include <math.h>

#define BB 8
#define LL 1024
#define CC 768
#define NH 12
#define HD 64
#define M_TOT (BB*LL)      /* 8192 */
#define NQKV (3*CC)        /* 2304 */

// ---------------- scratch (device globals: no allocation allowed) ----------
__device__ float g_qkv[(size_t)M_TOT * NQKV];
// bf16 hi/lo splits of GEMM operands
__device__ __nv_bfloat16 g_xh[(size_t)M_TOT * CC],  g_xl[(size_t)M_TOT * CC];
__device__ __nv_bfloat16 g_wqh[(size_t)NQKV * CC],  g_wql[(size_t)NQKV * CC];
__device__ __nv_bfloat16 g_woh[(size_t)CC * CC],    g_wol[(size_t)CC * CC];
__device__ __nv_bfloat16 g_aoh[(size_t)M_TOT * CC], g_aol[(size_t)M_TOT * CC];
// bf16 hi/lo splits of q/k/v, layout [b, h, l, e]
__device__ __nv_bfloat16 g_qh[(size_t)BB*NH*LL*HD], g_ql[(size_t)BB*NH*LL*HD];
__device__ __nv_bfloat16 g_kh[(size_t)BB*NH*LL*HD], g_kl[(size_t)BB*NH*LL*HD];
__device__ __nv_bfloat16 g_vh[(size_t)BB*NH*LL*HD], g_vl[(size_t)BB*NH*LL*HD];

// ---------------------------------------------------------------------------
__device__ __forceinline__ float ex2f(float x) {
    float y;
    asm("ex2.approx.ftz.f32 %0, %1;" : "=f"(y) : "f"(x));
    return y;
}
__device__ __forceinline__ uint32_t smem_u32(const void* p) {
    uint32_t a;
    asm("{ .reg .u64 t; cvta.to.shared.u64 t, %1; cvt.u32.u64 %0, t; }"
        : "=r"(a) : "l"(p));
    return a;
}
__device__ __forceinline__ void split2(float a, float b, uint32_t& hi, uint32_t& lo) {
    __nv_bfloat16 ha = __float2bfloat16_rn(a);
    __nv_bfloat16 hb = __float2bfloat16_rn(b);
    float ra = a - __bfloat162float(ha);
    float rb = b - __bfloat162float(hb);
    __nv_bfloat16 la = __float2bfloat16_rn(ra);
    __nv_bfloat16 lb = __float2bfloat16_rn(rb);
    hi = ((uint32_t)*(uint16_t*)&hb << 16) | (uint32_t)*(uint16_t*)&ha;
    lo = ((uint32_t)*(uint16_t*)&lb << 16) | (uint32_t)*(uint16_t*)&la;
}

#define MMA_BF16(Cr, A0, A1, A2, A3, B0, B1) \
    asm volatile("mma.sync.aligned.m16n8k16.row.col.f32.bf16.bf16.f32 " \
        "{%0,%1,%2,%3}, {%4,%5,%6,%7}, {%8,%9}, {%0,%1,%2,%3};" \
        : "+f"((Cr)[0]), "+f"((Cr)[1]), "+f"((Cr)[2]), "+f"((Cr)[3]) \
        : "r"(A0), "r"(A1), "r"(A2), "r"(A3), "r"(B0), "r"(B1))

#define LDSM_X4_T(r0, r1, r2, r3, addr) \
    asm volatile("ldmatrix.sync.aligned.m8n8.x4.trans.shared.b16 {%0,%1,%2,%3}, [%4];" \
        : "=r"(r0), "=r"(r1), "=r"(r2), "=r"(r3) : "r"(addr))

#define CP_ASYNC16(dst, src) \
    asm volatile("cp.async.cg.shared.global [%0], [%1], 16;" \
                 :: "r"(dst), "l"(src) : "memory")
#define CP_COMMIT() asm volatile("cp.async.commit_group;" ::: "memory")
#define CP_WAIT0()  asm volatile("cp.async.wait_group 0;" ::: "memory")
#define CP_WAIT1()  asm volatile("cp.async.wait_group 1;" ::: "memory")

// ===========================================================================
// split: fp32 -> bf16 hi/lo (vectorized float4). n4 = n/4.
// ===========================================================================
__global__ __launch_bounds__(256) void split_kernel(
    const float* __restrict__ src, __nv_bfloat16* __restrict__ h,
    __nv_bfloat16* __restrict__ l, int n4)
{
    int i = blockIdx.x * 256 + threadIdx.x;
    if (i < n4) {
        float4 v = ((const float4*)src)[i];
        uint32_t h0, l0, h1, l1;
        split2(v.x, v.y, h0, l0);
        split2(v.z, v.w, h1, l1);
        ((uint2*)h)[i] = make_uint2(h0, h1);
        ((uint2*)l)[i] = make_uint2(l0, l1);
    }
}

// ===========================================================================
// Pipelined all-bf16 GEMM (NT) x3-split: C[M,N] = A[M,K]*B[N,K]^T (fp32 out).
// BM=BN=128, BK=32, 256 thr = 8 warps (2x4), warp tile 64x32.
// Dynamic smem: 2 stages x 40960B. Stage: Ah@0 Al@10240 Bh@20480 Bl@30720,
// each 128 rows x 80B (64B data + 16B pad; conflict-free fragment LDS).
// ===========================================================================
#define GSTG 40960

__global__ __launch_bounds__(256) void gemm_bf3_kernel(
    const __nv_bfloat16* __restrict__ Ah, const __nv_bfloat16* __restrict__ Al,
    const __nv_bfloat16* __restrict__ Bh, const __nv_bfloat16* __restrict__ Bl,
    float* __restrict__ C, int M, int N, int K)
{
    extern __shared__ uint8_t smraw[];
    uint32_t* smw = (uint32_t*)smraw;
    const uint32_t sbase = smem_u32(smraw);

    const int tid  = threadIdx.x;
    const int wid  = tid >> 5;
    const int lane = tid & 31;
    const int wm = wid & 1;
    const int wn = wid >> 1;
    const int row0 = blockIdx.y * 128;
    const int col0 = blockIdx.x * 128;
    const int q4 = lane >> 2;
    const int l3 = lane & 3;

    float c[4][4][4];
#pragma unroll
    for (int m = 0; m < 4; m++)
#pragma unroll
        for (int n = 0; n < 4; n++)
#pragma unroll
            for (int q = 0; q < 4; q++) c[m][n][q] = 0.f;

    const int nch = K / 32;

    // prefetch chunk 0
    {
        uint32_t dst = sbase;
#pragma unroll
        for (int j = 0; j < 8; j++) {
            int i = tid + 256 * j;
            int a = i >> 9, r = (i >> 2) & 127, cc = i & 3;
            const __nv_bfloat16* base = (a == 0) ? Ah : (a == 1) ? Al : (a == 2) ? Bh : Bl;
            int grow = ((a < 2) ? row0 : col0) + r;
            CP_ASYNC16(dst + a * 10240 + r * 80 + cc * 16,
                       base + (size_t)grow * K + cc * 8);
        }
        CP_COMMIT();
    }

#pragma unroll 1
    for (int ch = 0; ch < nch; ch++) {
        if (ch + 1 < nch) {
            uint32_t dst = sbase + ((ch + 1) & 1) * GSTG;
            const int k0 = (ch + 1) * 32;
#pragma unroll
            for (int j = 0; j < 8; j++) {
                int i = tid + 256 * j;
                int a = i >> 9, r = (i >> 2) & 127, cc = i & 3;
                const __nv_bfloat16* base = (a == 0) ? Ah : (a == 1) ? Al : (a == 2) ? Bh : Bl;
                int grow = ((a < 2) ? row0 : col0) + r;
                CP_ASYNC16(dst + a * 10240 + r * 80 + cc * 16,
                           base + (size_t)grow * K + k0 + cc * 8);
            }
            CP_COMMIT();
            CP_WAIT1();
        } else {
            CP_WAIT0();
        }
        __syncthreads();

        const uint32_t* SW = smw + (ch & 1) * (GSTG / 4);

#pragma unroll
        for (int ks = 0; ks < 2; ks++) {
            const int kb = ks * 8;
            uint32_t ah[4][4], al[4][4];
#pragma unroll
            for (int m = 0; m < 4; m++) {
                int base = (wm * 64 + m * 16 + q4) * 20 + kb + l3;
                ah[m][0] = SW[base];              ah[m][1] = SW[base + 160];
                ah[m][2] = SW[base + 4];          ah[m][3] = SW[base + 164];
                al[m][0] = SW[2560 + base];       al[m][1] = SW[2560 + base + 160];
                al[m][2] = SW[2560 + base + 4];   al[m][3] = SW[2560 + base + 164];
            }
#pragma unroll
            for (int n = 0; n < 4; n++) {
                int bbase = (wn * 32 + n * 8 + q4) * 20 + kb + l3;
                uint32_t bh0 = SW[5120 + bbase], bh1 = SW[5120 + bbase + 4];
                uint32_t bl0 = SW[7680 + bbase], bl1 = SW[7680 + bbase + 4];
#pragma unroll
                for (int m = 0; m < 4; m++) {
                    MMA_BF16(c[m][n], ah[m][0], ah[m][1], ah[m][2], ah[m][3], bh0, bh1);
                    MMA_BF16(c[m][n], ah[m][0], ah[m][1], ah[m][2], ah[m][3], bl0, bl1);
                    MMA_BF16(c[m][n], al[m][0], al[m][1], al[m][2], al[m][3], bh0, bh1);
                }
            }
        }
        __syncthreads();
    }

#pragma unroll
    for (int m = 0; m < 4; m++) {
        const int r = row0 + wm * 64 + m * 16 + q4;
#pragma unroll
        for (int n = 0; n < 4; n++) {
            const int cc = col0 + wn * 32 + n * 8 + l3 * 2;
            *(float2*)(C + (size_t)r * N + cc)       = make_float2(c[m][n][0], c[m][n][1]);
            *(float2*)(C + (size_t)(r + 8) * N + cc) = make_float2(c[m][n][2], c[m][n][3]);
        }
    }
}

// ---------------------------------------------------------------------------
// QKV epilogue: RMSNorm + RoPE, then bf16 hi/lo split to [b,h,l,e].
// Q pre-scaled by 0.125*log2(e).
// ---------------------------------------------------------------------------
__device__ __forceinline__ void store_split(__nv_bfloat16* ah, __nv_bfloat16* al,
                                            size_t idx, float v) {
    __nv_bfloat16 h = __float2bfloat16_rn(v);
    ah[idx] = h;
    al[idx] = __float2bfloat16_rn(v - __bfloat162float(h));
}

__global__ __launch_bounds__(256) void qkv_post_kernel(
    const float* __restrict__ qg, const float* __restrict__ kg)
{
    const int widx = blockIdx.x * 8 + (threadIdx.x >> 5);
    const int lane = threadIdx.x & 31;
    const int h = widx % NH;
    const int l = (widx / NH) % LL;
    const int b = widx / (NH * LL);

    const float* rowp = g_qkv + (size_t)(b * LL + l) * NQKV + h * HD;
    const float ifr = exp2f(-13.287712379549449f * (float)lane * (1.0f / 32.0f));
    const float ang = (float)l * ifr;
    const float cs = cosf(ang), sn = sinf(ang);
    const size_t dsto = ((size_t)(b * NH + h) * LL + l) * HD;
    const float QS = 0.125f * 1.4426950408889634f;

    {
        float x1 = rowp[lane], x2 = rowp[lane + 32];
        float ss = x1 * x1 + x2 * x2;
#pragma unroll
        for (int o = 16; o; o >>= 1) ss += __shfl_xor_sync(0xffffffffu, ss, o);
        float r = rsqrtf(ss * (1.0f / HD) + 1e-6f);
        float n1 = x1 * r * qg[lane], n2 = x2 * r * qg[lane + 32];
        store_split(g_qh, g_ql, dsto + lane,      (n1 * cs - n2 * sn) * QS);
        store_split(g_qh, g_ql, dsto + lane + 32, (n1 * sn + n2 * cs) * QS);
    }
    {
        float x1 = rowp[CC + lane], x2 = rowp[CC + lane + 32];
        float ss = x1 * x1 + x2 * x2;
#pragma unroll
        for (int o = 16; o; o >>= 1) ss += __shfl_xor_sync(0xffffffffu, ss, o);
        float r = rsqrtf(ss * (1.0f / HD) + 1e-6f);
        float n1 = x1 * r * kg[lane], n2 = x2 * r * kg[lane + 32];
        store_split(g_kh, g_kl, dsto + lane,      n1 * cs - n2 * sn);
        store_split(g_kh, g_kl, dsto + lane + 32, n1 * sn + n2 * cs);
    }
    store_split(g_vh, g_vl, dsto + lane,      rowp[2 * CC + lane]);
    store_split(g_vh, g_vl, dsto + lane + 32, rowp[2 * CC + lane + 32]);
}

// ===========================================================================
// Flash attention via mma.sync bf16x3 (round-4 core; epilogue now writes
// bf16 hi/lo directly so the out-proj GEMM needs no split pass).
// ===========================================================================
#define ASTAGE 36864
#define AROW   144
#define AROWW  36

__global__ __launch_bounds__(256) void attn_mma_kernel()
{
    extern __shared__ uint8_t smraw[];
    uint32_t* smw = (uint32_t*)smraw;
    const uint32_t sbase = smem_u32(smraw);

    const int tid  = threadIdx.x;
    const int w    = tid >> 5;
    const int lane = tid & 31;
    const int q4   = lane >> 2;
    const int l3   = lane & 3;
    const int qt = blockIdx.x, h = blockIdx.y, b = blockIdx.z;

    const size_t hb = (size_t)(b * NH + h) * LL * HD;
    const __nv_bfloat16* Qh = g_qh + hb + (size_t)qt * 128 * HD;
    const __nv_bfloat16* Ql = g_ql + hb + (size_t)qt * 128 * HD;
    const __nv_bfloat16* Kh = g_kh + hb;
    const __nv_bfloat16* Kl = g_kl + hb;
    const __nv_bfloat16* Vh = g_vh + hb;
    const __nv_bfloat16* Vl = g_vl + hb;

#pragma unroll
    for (int t = 0; t < 8; t++) {
        int i = tid + 256 * t;
        int a = i >> 10, r = (i >> 3) & 127, c = i & 7;
        const __nv_bfloat16* src = (a ? Ql : Qh) + (size_t)r * HD + c * 8;
        CP_ASYNC16(sbase + a * 18432 + r * AROW + c * 16, src);
    }
    CP_COMMIT(); CP_WAIT0();
    __syncthreads();

    uint32_t qhf[4][4], qlf[4][4];
#pragma unroll
    for (int ks = 0; ks < 4; ks++) {
        int base = (w * 16 + q4) * AROWW + ks * 8 + l3;
        qhf[ks][0] = smw[base];                qhf[ks][1] = smw[base + 8 * AROWW];
        qhf[ks][2] = smw[base + 4];            qhf[ks][3] = smw[base + 8 * AROWW + 4];
        qlf[ks][0] = smw[4608 + base];         qlf[ks][1] = smw[4608 + base + 8 * AROWW];
        qlf[ks][2] = smw[4608 + base + 4];     qlf[ks][3] = smw[4608 + base + 8 * AROWW + 4];
    }
    __syncthreads();

    float m0 = -1e30f, m1 = -1e30f, ls0 = 0.f, ls1 = 0.f;
    float O[8][4];
#pragma unroll
    for (int n = 0; n < 8; n++)
#pragma unroll
        for (int q = 0; q < 4; q++) O[n][q] = 0.f;

#pragma unroll
    for (int t = 0; t < 8; t++) {
        int i = tid + 256 * t;
        int a = i >> 9, r = (i >> 3) & 63, c = i & 7;
        const __nv_bfloat16* base = (a == 0) ? Kh : (a == 1) ? Kl : (a == 2) ? Vh : Vl;
        CP_ASYNC16(sbase + a * 9216 + r * AROW + c * 16,
                   base + (size_t)r * HD + c * 8);
    }
    CP_COMMIT();

#pragma unroll 1
    for (int kt = 0; kt < 16; kt++) {
        if (kt < 15) {
            uint32_t dst = sbase + ((kt + 1) & 1) * ASTAGE;
            const int r0 = (kt + 1) * 64;
#pragma unroll
            for (int t = 0; t < 8; t++) {
                int i = tid + 256 * t;
                int a = i >> 9, r = (i >> 3) & 63, c = i & 7;
                const __nv_bfloat16* base = (a == 0) ? Kh : (a == 1) ? Kl : (a == 2) ? Vh : Vl;
                CP_ASYNC16(dst + a * 9216 + r * AROW + c * 16,
                           base + (size_t)(r0 + r) * HD + c * 8);
            }
            CP_COMMIT();
            CP_WAIT1();
        } else {
            CP_WAIT0();
        }
        __syncthreads();

        const uint32_t* KW = smw + (kt & 1) * (ASTAGE / 4);
        const uint32_t vbase = sbase + (kt & 1) * ASTAGE + 18432;

        float S[8][4];
#pragma unroll
        for (int n = 0; n < 8; n++)
#pragma unroll
            for (int q = 0; q < 4; q++) S[n][q] = 0.f;

#pragma unroll
        for (int ks = 0; ks < 4; ks++) {
#pragma unroll
            for (int nt = 0; nt < 8; nt++) {
                int kb = (nt * 8 + q4) * AROWW + ks * 8 + l3;
                uint32_t bh0 = KW[kb], bh1 = KW[kb + 4];
                uint32_t bl0 = KW[2304 + kb], bl1 = KW[2304 + kb + 4];
                MMA_BF16(S[nt], qhf[ks][0], qhf[ks][1], qhf[ks][2], qhf[ks][3], bh0, bh1);
                MMA_BF16(S[nt], qhf[ks][0], qhf[ks][1], qhf[ks][2], qhf[ks][3], bl0, bl1);
                MMA_BF16(S[nt], qlf[ks][0], qlf[ks][1], qlf[ks][2], qlf[ks][3], bh0, bh1);
            }
        }

        float mx0 = -1e30f, mx1 = -1e30f;
#pragma unroll
        for (int nt = 0; nt < 8; nt++) {
            mx0 = fmaxf(mx0, fmaxf(S[nt][0], S[nt][1]));
            mx1 = fmaxf(mx1, fmaxf(S[nt][2], S[nt][3]));
        }
        mx0 = fmaxf(mx0, __shfl_xor_sync(0xffffffffu, mx0, 1));
        mx0 = fmaxf(mx0, __shfl_xor_sync(0xffffffffu, mx0, 2));
        mx1 = fmaxf(mx1, __shfl_xor_sync(0xffffffffu, mx1, 1));
        mx1 = fmaxf(mx1, __shfl_xor_sync(0xffffffffu, mx1, 2));
        float mn0 = fmaxf(m0, mx0), mn1 = fmaxf(m1, mx1);
        float a0 = ex2f(m0 - mn0), a1 = ex2f(m1 - mn1);
        float rs0 = 0.f, rs1 = 0.f;
#pragma unroll
        for (int nt = 0; nt < 8; nt++) {
            S[nt][0] = ex2f(S[nt][0] - mn0); S[nt][1] = ex2f(S[nt][1] - mn0);
            S[nt][2] = ex2f(S[nt][2] - mn1); S[nt][3] = ex2f(S[nt][3] - mn1);
            rs0 += S[nt][0] + S[nt][1];
            rs1 += S[nt][2] + S[nt][3];
        }
        rs0 += __shfl_xor_sync(0xffffffffu, rs0, 1);
        rs0 += __shfl_xor_sync(0xffffffffu, rs0, 2);
        rs1 += __shfl_xor_sync(0xffffffffu, rs1, 1);
        rs1 += __shfl_xor_sync(0xffffffffu, rs1, 2);
        ls0 = ls0 * a0 + rs0;  ls1 = ls1 * a1 + rs1;
        m0 = mn0;  m1 = mn1;
#pragma unroll
        for (int nt = 0; nt < 8; nt++) {
            O[nt][0] *= a0; O[nt][1] *= a0;
            O[nt][2] *= a1; O[nt][3] *= a1;
        }

        uint32_t ph[4][4], pl[4][4];
#pragma unroll
        for (int j = 0; j < 4; j++) {
            split2(S[2*j][0],   S[2*j][1],   ph[j][0], pl[j][0]);
            split2(S[2*j][2],   S[2*j][3],   ph[j][1], pl[j][1]);
            split2(S[2*j+1][0], S[2*j+1][1], ph[j][2], pl[j][2]);
            split2(S[2*j+1][2], S[2*j+1][3], ph[j][3], pl[j][3]);
        }

        const uint32_t lrow = (lane & 15);
        const uint32_t lcol = ((lane >> 4) & 1) * 16;
#pragma unroll
        for (int j = 0; j < 4; j++) {
            uint32_t va = vbase + (16 * j + lrow) * AROW + lcol;
#pragma unroll
            for (int p = 0; p < 4; p++) {
                uint32_t addr = va + p * 32;
                uint32_t vh0, vh1, vh2, vh3, vl0, vl1, vl2, vl3;
                LDSM_X4_T(vh0, vh1, vh2, vh3, addr);
                LDSM_X4_T(vl0, vl1, vl2, vl3, addr + 9216);
                MMA_BF16(O[2*p],   ph[j][0], ph[j][1], ph[j][2], ph[j][3], vh0, vh1);
                MMA_BF16(O[2*p+1], ph[j][0], ph[j][1], ph[j][2], ph[j][3], vh2, vh3);
                MMA_BF16(O[2*p],   ph[j][0], ph[j][1], ph[j][2], ph[j][3], vl0, vl1);
                MMA_BF16(O[2*p+1], ph[j][0], ph[j][1], ph[j][2], ph[j][3], vl2, vl3);
                MMA_BF16(O[2*p],   pl[j][0], pl[j][1], pl[j][2], pl[j][3], vh0, vh1);
                MMA_BF16(O[2*p+1], pl[j][0], pl[j][1], pl[j][2], pl[j][3], vh2, vh3);
            }
        }
        __syncthreads();
    }

    // ---- epilogue: normalize, split to bf16 hi/lo, write [b, l, c] ----
    const float inv0 = 1.0f / ls0, inv1 = 1.0f / ls1;
    const int row0 = qt * 128 + w * 16 + q4;
    const size_t o0 = ((size_t)b * LL + row0) * CC + h * HD;
    const size_t o1 = o0 + 8 * CC;
#pragma unroll
    for (int nt = 0; nt < 8; nt++) {
        int cc = nt * 8 + 2 * l3;
        uint32_t hw, lw;
        split2(O[nt][0] * inv0, O[nt][1] * inv0, hw, lw);
        *(uint32_t*)(g_aoh + o0 + cc) = hw;
        *(uint32_t*)(g_aol + o0 + cc) = lw;
        split2(O[nt][2] * inv1, O[nt][3] * inv1, hw, lw);
        *(uint32_t*)(g_aoh + o1 + cc) = hw;
        *(uint32_t*)(g_aol + o1 + cc) = lw;
    }
}

// ---------------------------------------------------------------------------
extern "C" void kernel_launch(void* const* d_in, const int* in_sizes, int n_in,
                              void* d_out, int out_size)
{
    const float* x      = (const float*)d_in[0];
    const float* w_qkv  = (const float*)d_in[1];
    const float* qgam   = (const float*)d_in[2];
    const float* kgam   = (const float*)d_in[3];
    const float* w_out  = (const float*)d_in[4];
    float* out = (float*)d_out;

    float* qkv; cudaGetSymbolAddress((void**)&qkv, g_qkv);
    __nv_bfloat16 *xh, *xl, *wqh, *wql, *woh, *wol, *aoh, *aol;
    cudaGetSymbolAddress((void**)&xh, g_xh);   cudaGetSymbolAddress((void**)&xl, g_xl);
    cudaGetSymbolAddress((void**)&wqh, g_wqh); cudaGetSymbolAddress((void**)&wql, g_wql);
    cudaGetSymbolAddress((void**)&woh, g_woh); cudaGetSymbolAddress((void**)&wol, g_wol);
    cudaGetSymbolAddress((void**)&aoh, g_aoh); cudaGetSymbolAddress((void**)&aol, g_aol);

    cudaFuncSetAttribute(gemm_bf3_kernel,
                         cudaFuncAttributeMaxDynamicSharedMemorySize, 2 * GSTG);
    cudaFuncSetAttribute(attn_mma_kernel,
                         cudaFuncAttributeMaxDynamicSharedMemorySize, 2 * ASTAGE);

    // 0) pre-split inputs to bf16 hi/lo
    split_kernel<<<(M_TOT * CC / 4 + 255) / 256, 256>>>(x, xh, xl, M_TOT * CC / 4);
    split_kernel<<<(NQKV * CC / 4 + 255) / 256, 256>>>(w_qkv, wqh, wql, NQKV * CC / 4);
    split_kernel<<<(CC * CC / 4 + 255) / 256, 256>>>(w_out, woh, wol, CC * CC / 4);

    // 1) QKV projection (pipelined bf16x3)
    gemm_bf3_kernel<<<dim3(NQKV / 128, M_TOT / 128), 256, 2 * GSTG>>>(
        xh, xl, wqh, wql, qkv, M_TOT, NQKV, CC);

    // 2) RMSNorm + RoPE + bf16 split
    qkv_post_kernel<<<(BB * LL * NH) / 8, 256>>>(qgam, kgam);

    // 3) Flash attention (mma.sync bf16x3, split bf16 output)
    attn_mma_kernel<<<dim3(LL / 128, NH, BB), 256, 2 * ASTAGE>>>();

    // 4) Output projection (pipelined bf16x3)
    gemm_bf3_kernel<<<dim3(CC / 128, M_TOT / 128), 256, 2 * GSTG>>>(
        aoh, aol, woh, wol, out, M_TOT, CC, CC);
}

// round 6
// speedup vs baseline: 2.5674x; 1.0001x over previous
#include <cuda_runtime.h>
#include <cuda_bf16.h>
#include <cstdint>
#include <math.h>

#define BB 8
#define LL 1024
#define CC 768
#define NH 12
#define HD 64
#define M_TOT (BB*LL)      /* 8192 */
#define NQKV (3*CC)        /* 2304 */

// ---------------- scratch (device globals: no allocation allowed) ----------
__device__ float g_qkv[(size_t)M_TOT * NQKV];
__device__ __nv_bfloat16 g_xh[(size_t)M_TOT * CC],  g_xl[(size_t)M_TOT * CC];
__device__ __nv_bfloat16 g_wqh[(size_t)NQKV * CC],  g_wql[(size_t)NQKV * CC];
__device__ __nv_bfloat16 g_woh[(size_t)CC * CC],    g_wol[(size_t)CC * CC];
__device__ __nv_bfloat16 g_aoh[(size_t)M_TOT * CC], g_aol[(size_t)M_TOT * CC];
__device__ __nv_bfloat16 g_qh[(size_t)BB*NH*LL*HD], g_ql[(size_t)BB*NH*LL*HD];
__device__ __nv_bfloat16 g_kh[(size_t)BB*NH*LL*HD], g_kl[(size_t)BB*NH*LL*HD];
__device__ __nv_bfloat16 g_vh[(size_t)BB*NH*LL*HD], g_vl[(size_t)BB*NH*LL*HD];

// ---------------------------------------------------------------------------
__device__ __forceinline__ float ex2f(float x) {
    float y;
    asm("ex2.approx.ftz.f32 %0, %1;" : "=f"(y) : "f"(x));
    return y;
}
__device__ __forceinline__ uint32_t smem_u32(const void* p) {
    uint32_t a;
    asm("{ .reg .u64 t; cvta.to.shared.u64 t, %1; cvt.u32.u64 %0, t; }"
        : "=r"(a) : "l"(p));
    return a;
}
__device__ __forceinline__ void split2(float a, float b, uint32_t& hi, uint32_t& lo) {
    __nv_bfloat16 ha = __float2bfloat16_rn(a);
    __nv_bfloat16 hb = __float2bfloat16_rn(b);
    float ra = a - __bfloat162float(ha);
    float rb = b - __bfloat162float(hb);
    __nv_bfloat16 la = __float2bfloat16_rn(ra);
    __nv_bfloat16 lb = __float2bfloat16_rn(rb);
    hi = ((uint32_t)*(uint16_t*)&hb << 16) | (uint32_t)*(uint16_t*)&ha;
    lo = ((uint32_t)*(uint16_t*)&lb << 16) | (uint32_t)*(uint16_t*)&la;
}

#define MMA_BF16(Cr, A0, A1, A2, A3, B0, B1) \
    asm volatile("mma.sync.aligned.m16n8k16.row.col.f32.bf16.bf16.f32 " \
        "{%0,%1,%2,%3}, {%4,%5,%6,%7}, {%8,%9}, {%0,%1,%2,%3};" \
        : "+f"((Cr)[0]), "+f"((Cr)[1]), "+f"((Cr)[2]), "+f"((Cr)[3]) \
        : "r"(A0), "r"(A1), "r"(A2), "r"(A3), "r"(B0), "r"(B1))

#define LDSM_X4(r0, r1, r2, r3, addr) \
    asm volatile("ldmatrix.sync.aligned.m8n8.x4.shared.b16 {%0,%1,%2,%3}, [%4];" \
        : "=r"(r0), "=r"(r1), "=r"(r2), "=r"(r3) : "r"(addr))

#define LDSM_X4_T(r0, r1, r2, r3, addr) \
    asm volatile("ldmatrix.sync.aligned.m8n8.x4.trans.shared.b16 {%0,%1,%2,%3}, [%4];" \
        : "=r"(r0), "=r"(r1), "=r"(r2), "=r"(r3) : "r"(addr))

#define CP_ASYNC16(dst, src) \
    asm volatile("cp.async.cg.shared.global [%0], [%1], 16;" \
                 :: "r"(dst), "l"(src) : "memory")
#define CP_COMMIT() asm volatile("cp.async.commit_group;" ::: "memory")
#define CP_WAIT0()  asm volatile("cp.async.wait_group 0;" ::: "memory")
#define CP_WAIT1()  asm volatile("cp.async.wait_group 1;" ::: "memory")

// ===========================================================================
// split: fp32 -> bf16 hi/lo
// ===========================================================================
__global__ __launch_bounds__(256) void split_kernel(
    const float* __restrict__ src, __nv_bfloat16* __restrict__ h,
    __nv_bfloat16* __restrict__ l, int n4)
{
    int i = blockIdx.x * 256 + threadIdx.x;
    if (i < n4) {
        float4 v = ((const float4*)src)[i];
        uint32_t h0, l0, h1, l1;
        split2(v.x, v.y, h0, l0);
        split2(v.z, v.w, h1, l1);
        ((uint2*)h)[i] = make_uint2(h0, h1);
        ((uint2*)l)[i] = make_uint2(l0, l1);
    }
}

// ===========================================================================
// Pipelined all-bf16 GEMM (NT) x3-split, ldmatrix fragments, 2 CTAs/SM.
// BM=BN=128, BK=32, 256 thr = 8 warps (2x4), warp tile 64x32.
// Stage (40960B): Ah@0 Al@10240 Bh@20480 Bl@30720, 128 rows x 80B.
// ===========================================================================
#define GSTG 40960

__global__ __launch_bounds__(256, 2) void gemm_bf3_kernel(
    const __nv_bfloat16* __restrict__ Ah, const __nv_bfloat16* __restrict__ Al,
    const __nv_bfloat16* __restrict__ Bh, const __nv_bfloat16* __restrict__ Bl,
    float* __restrict__ C, int M, int N, int K)
{
    extern __shared__ uint8_t smraw[];
    const uint32_t sbase = smem_u32(smraw);

    const int tid  = threadIdx.x;
    const int wid  = tid >> 5;
    const int lane = tid & 31;
    const int wm = wid & 1;
    const int wn = wid >> 1;
    const int row0 = blockIdx.y * 128;
    const int col0 = blockIdx.x * 128;
    const int q4 = lane >> 2;
    const int l3 = lane & 3;
    const int lr16  = lane & 15;        // ldmatrix row-within-tile
    const int lhalf = (lane >> 4) * 16; // ldmatrix 16B column half

    float c[4][4][4];
#pragma unroll
    for (int m = 0; m < 4; m++)
#pragma unroll
        for (int n = 0; n < 4; n++)
#pragma unroll
            for (int q = 0; q < 4; q++) c[m][n][q] = 0.f;

    const int nch = K / 32;

    // prefetch chunk 0
    {
        uint32_t dst = sbase;
#pragma unroll
        for (int j = 0; j < 8; j++) {
            int i = tid + 256 * j;
            int a = i >> 9, r = (i >> 2) & 127, cc = i & 3;
            const __nv_bfloat16* base = (a == 0) ? Ah : (a == 1) ? Al : (a == 2) ? Bh : Bl;
            int grow = ((a < 2) ? row0 : col0) + r;
            CP_ASYNC16(dst + a * 10240 + r * 80 + cc * 16,
                       base + (size_t)grow * K + cc * 8);
        }
        CP_COMMIT();
    }

#pragma unroll 1
    for (int ch = 0; ch < nch; ch++) {
        if (ch + 1 < nch) {
            uint32_t dst = sbase + ((ch + 1) & 1) * GSTG;
            const int k0 = (ch + 1) * 32;
#pragma unroll
            for (int j = 0; j < 8; j++) {
                int i = tid + 256 * j;
                int a = i >> 9, r = (i >> 2) & 127, cc = i & 3;
                const __nv_bfloat16* base = (a == 0) ? Ah : (a == 1) ? Al : (a == 2) ? Bh : Bl;
                int grow = ((a < 2) ? row0 : col0) + r;
                CP_ASYNC16(dst + a * 10240 + r * 80 + cc * 16,
                           base + (size_t)grow * K + k0 + cc * 8);
            }
            CP_COMMIT();
            CP_WAIT1();
        } else {
            CP_WAIT0();
        }
        __syncthreads();

        const uint32_t sst = sbase + (ch & 1) * GSTG;

#pragma unroll
        for (int ks = 0; ks < 2; ks++) {
            uint32_t ah[4][4], al[4][4];
#pragma unroll
            for (int m = 0; m < 4; m++) {
                uint32_t arow = sst + (wm * 64 + m * 16 + lr16) * 80 + lhalf + ks * 32;
                LDSM_X4(ah[m][0], ah[m][1], ah[m][2], ah[m][3], arow);
                LDSM_X4(al[m][0], al[m][1], al[m][2], al[m][3], arow + 10240);
            }
#pragma unroll
            for (int np = 0; np < 2; np++) {
                uint32_t brow = sst + 20480 + (wn * 32 + np * 16 + lr16) * 80 + lhalf + ks * 32;
                uint32_t h0, h1, h2, h3, L0, L1, L2, L3;
                LDSM_X4(h0, h1, h2, h3, brow);
                LDSM_X4(L0, L1, L2, L3, brow + 10240);
#pragma unroll
                for (int m = 0; m < 4; m++) {
                    MMA_BF16(c[m][2*np],   ah[m][0], ah[m][1], ah[m][2], ah[m][3], h0, h2);
                    MMA_BF16(c[m][2*np],   ah[m][0], ah[m][1], ah[m][2], ah[m][3], L0, L2);
                    MMA_BF16(c[m][2*np],   al[m][0], al[m][1], al[m][2], al[m][3], h0, h2);
                    MMA_BF16(c[m][2*np+1], ah[m][0], ah[m][1], ah[m][2], ah[m][3], h1, h3);
                    MMA_BF16(c[m][2*np+1], ah[m][0], ah[m][1], ah[m][2], ah[m][3], L1, L3);
                    MMA_BF16(c[m][2*np+1], al[m][0], al[m][1], al[m][2], al[m][3], h1, h3);
                }
            }
        }
        __syncthreads();
    }

#pragma unroll
    for (int m = 0; m < 4; m++) {
        const int r = row0 + wm * 64 + m * 16 + q4;
#pragma unroll
        for (int n = 0; n < 4; n++) {
            const int cc = col0 + wn * 32 + n * 8 + l3 * 2;
            *(float2*)(C + (size_t)r * N + cc)       = make_float2(c[m][n][0], c[m][n][1]);
            *(float2*)(C + (size_t)(r + 8) * N + cc) = make_float2(c[m][n][2], c[m][n][3]);
        }
    }
}

// ---------------------------------------------------------------------------
// QKV epilogue: RMSNorm + RoPE, bf16 hi/lo split to [b,h,l,e].
// ---------------------------------------------------------------------------
__device__ __forceinline__ void store_split(__nv_bfloat16* ah, __nv_bfloat16* al,
                                            size_t idx, float v) {
    __nv_bfloat16 h = __float2bfloat16_rn(v);
    ah[idx] = h;
    al[idx] = __float2bfloat16_rn(v - __bfloat162float(h));
}

__global__ __launch_bounds__(256) void qkv_post_kernel(
    const float* __restrict__ qg, const float* __restrict__ kg)
{
    const int widx = blockIdx.x * 8 + (threadIdx.x >> 5);
    const int lane = threadIdx.x & 31;
    const int h = widx % NH;
    const int l = (widx / NH) % LL;
    const int b = widx / (NH * LL);

    const float* rowp = g_qkv + (size_t)(b * LL + l) * NQKV + h * HD;
    const float ifr = exp2f(-13.287712379549449f * (float)lane * (1.0f / 32.0f));
    const float ang = (float)l * ifr;
    const float cs = cosf(ang), sn = sinf(ang);
    const size_t dsto = ((size_t)(b * NH + h) * LL + l) * HD;
    const float QS = 0.125f * 1.4426950408889634f;

    {
        float x1 = rowp[lane], x2 = rowp[lane + 32];
        float ss = x1 * x1 + x2 * x2;
#pragma unroll
        for (int o = 16; o; o >>= 1) ss += __shfl_xor_sync(0xffffffffu, ss, o);
        float r = rsqrtf(ss * (1.0f / HD) + 1e-6f);
        float n1 = x1 * r * qg[lane], n2 = x2 * r * qg[lane + 32];
        store_split(g_qh, g_ql, dsto + lane,      (n1 * cs - n2 * sn) * QS);
        store_split(g_qh, g_ql, dsto + lane + 32, (n1 * sn + n2 * cs) * QS);
    }
    {
        float x1 = rowp[CC + lane], x2 = rowp[CC + lane + 32];
        float ss = x1 * x1 + x2 * x2;
#pragma unroll
        for (int o = 16; o; o >>= 1) ss += __shfl_xor_sync(0xffffffffu, ss, o);
        float r = rsqrtf(ss * (1.0f / HD) + 1e-6f);
        float n1 = x1 * r * kg[lane], n2 = x2 * r * kg[lane + 32];
        store_split(g_kh, g_kl, dsto + lane,      n1 * cs - n2 * sn);
        store_split(g_kh, g_kl, dsto + lane + 32, n1 * sn + n2 * cs);
    }
    store_split(g_vh, g_vl, dsto + lane,      rowp[2 * CC + lane]);
    store_split(g_vh, g_vl, dsto + lane + 32, rowp[2 * CC + lane + 32]);
}

// ===========================================================================
// Flash attention via mma.sync bf16x3 (round-5 core, unchanged).
// ===========================================================================
#define ASTAGE 36864
#define AROW   144
#define AROWW  36

__global__ __launch_bounds__(256) void attn_mma_kernel()
{
    extern __shared__ uint8_t smraw[];
    uint32_t* smw = (uint32_t*)smraw;
    const uint32_t sbase = smem_u32(smraw);

    const int tid  = threadIdx.x;
    const int w    = tid >> 5;
    const int lane = tid & 31;
    const int q4   = lane >> 2;
    const int l3   = lane & 3;
    const int qt = blockIdx.x, h = blockIdx.y, b = blockIdx.z;

    const size_t hb = (size_t)(b * NH + h) * LL * HD;
    const __nv_bfloat16* Qh = g_qh + hb + (size_t)qt * 128 * HD;
    const __nv_bfloat16* Ql = g_ql + hb + (size_t)qt * 128 * HD;
    const __nv_bfloat16* Kh = g_kh + hb;
    const __nv_bfloat16* Kl = g_kl + hb;
    const __nv_bfloat16* Vh = g_vh + hb;
    const __nv_bfloat16* Vl = g_vl + hb;

#pragma unroll
    for (int t = 0; t < 8; t++) {
        int i = tid + 256 * t;
        int a = i >> 10, r = (i >> 3) & 127, c = i & 7;
        const __nv_bfloat16* src = (a ? Ql : Qh) + (size_t)r * HD + c * 8;
        CP_ASYNC16(sbase + a * 18432 + r * AROW + c * 16, src);
    }
    CP_COMMIT(); CP_WAIT0();
    __syncthreads();

    uint32_t qhf[4][4], qlf[4][4];
#pragma unroll
    for (int ks = 0; ks < 4; ks++) {
        int base = (w * 16 + q4) * AROWW + ks * 8 + l3;
        qhf[ks][0] = smw[base];                qhf[ks][1] = smw[base + 8 * AROWW];
        qhf[ks][2] = smw[base + 4];            qhf[ks][3] = smw[base + 8 * AROWW + 4];
        qlf[ks][0] = smw[4608 + base];         qlf[ks][1] = smw[4608 + base + 8 * AROWW];
        qlf[ks][2] = smw[4608 + base + 4];     qlf[ks][3] = smw[4608 + base + 8 * AROWW + 4];
    }
    __syncthreads();

    float m0 = -1e30f, m1 = -1e30f, ls0 = 0.f, ls1 = 0.f;
    float O[8][4];
#pragma unroll
    for (int n = 0; n < 8; n++)
#pragma unroll
        for (int q = 0; q < 4; q++) O[n][q] = 0.f;

#pragma unroll
    for (int t = 0; t < 8; t++) {
        int i = tid + 256 * t;
        int a = i >> 9, r = (i >> 3) & 63, c = i & 7;
        const __nv_bfloat16* base = (a == 0) ? Kh : (a == 1) ? Kl : (a == 2) ? Vh : Vl;
        CP_ASYNC16(sbase + a * 9216 + r * AROW + c * 16,
                   base + (size_t)r * HD + c * 8);
    }
    CP_COMMIT();

#pragma unroll 1
    for (int kt = 0; kt < 16; kt++) {
        if (kt < 15) {
            uint32_t dst = sbase + ((kt + 1) & 1) * ASTAGE;
            const int r0 = (kt + 1) * 64;
#pragma unroll
            for (int t = 0; t < 8; t++) {
                int i = tid + 256 * t;
                int a = i >> 9, r = (i >> 3) & 63, c = i & 7;
                const __nv_bfloat16* base = (a == 0) ? Kh : (a == 1) ? Kl : (a == 2) ? Vh : Vl;
                CP_ASYNC16(dst + a * 9216 + r * AROW + c * 16,
                           base + (size_t)(r0 + r) * HD + c * 8);
            }
            CP_COMMIT();
            CP_WAIT1();
        } else {
            CP_WAIT0();
        }
        __syncthreads();

        const uint32_t* KW = smw + (kt & 1) * (ASTAGE / 4);
        const uint32_t vbase = sbase + (kt & 1) * ASTAGE + 18432;

        float S[8][4];
#pragma unroll
        for (int n = 0; n < 8; n++)
#pragma unroll
            for (int q = 0; q < 4; q++) S[n][q] = 0.f;

#pragma unroll
        for (int ks = 0; ks < 4; ks++) {
#pragma unroll
            for (int nt = 0; nt < 8; nt++) {
                int kb = (nt * 8 + q4) * AROWW + ks * 8 + l3;
                uint32_t bh0 = KW[kb], bh1 = KW[kb + 4];
                uint32_t bl0 = KW[2304 + kb], bl1 = KW[2304 + kb + 4];
                MMA_BF16(S[nt], qhf[ks][0], qhf[ks][1], qhf[ks][2], qhf[ks][3], bh0, bh1);
                MMA_BF16(S[nt], qhf[ks][0], qhf[ks][1], qhf[ks][2], qhf[ks][3], bl0, bl1);
                MMA_BF16(S[nt], qlf[ks][0], qlf[ks][1], qlf[ks][2], qlf[ks][3], bh0, bh1);
            }
        }

        float mx0 = -1e30f, mx1 = -1e30f;
#pragma unroll
        for (int nt = 0; nt < 8; nt++) {
            mx0 = fmaxf(mx0, fmaxf(S[nt][0], S[nt][1]));
            mx1 = fmaxf(mx1, fmaxf(S[nt][2], S[nt][3]));
        }
        mx0 = fmaxf(mx0, __shfl_xor_sync(0xffffffffu, mx0, 1));
        mx0 = fmaxf(mx0, __shfl_xor_sync(0xffffffffu, mx0, 2));
        mx1 = fmaxf(mx1, __shfl_xor_sync(0xffffffffu, mx1, 1));
        mx1 = fmaxf(mx1, __shfl_xor_sync(0xffffffffu, mx1, 2));
        float mn0 = fmaxf(m0, mx0), mn1 = fmaxf(m1, mx1);
        float a0 = ex2f(m0 - mn0), a1 = ex2f(m1 - mn1);
        float rs0 = 0.f, rs1 = 0.f;
#pragma unroll
        for (int nt = 0; nt < 8; nt++) {
            S[nt][0] = ex2f(S[nt][0] - mn0); S[nt][1] = ex2f(S[nt][1] - mn0);
            S[nt][2] = ex2f(S[nt][2] - mn1); S[nt][3] = ex2f(S[nt][3] - mn1);
            rs0 += S[nt][0] + S[nt][1];
            rs1 += S[nt][2] + S[nt][3];
        }
        rs0 += __shfl_xor_sync(0xffffffffu, rs0, 1);
        rs0 += __shfl_xor_sync(0xffffffffu, rs0, 2);
        rs1 += __shfl_xor_sync(0xffffffffu, rs1, 1);
        rs1 += __shfl_xor_sync(0xffffffffu, rs1, 2);
        ls0 = ls0 * a0 + rs0;  ls1 = ls1 * a1 + rs1;
        m0 = mn0;  m1 = mn1;
#pragma unroll
        for (int nt = 0; nt < 8; nt++) {
            O[nt][0] *= a0; O[nt][1] *= a0;
            O[nt][2] *= a1; O[nt][3] *= a1;
        }

        uint32_t ph[4][4], pl[4][4];
#pragma unroll
        for (int j = 0; j < 4; j++) {
            split2(S[2*j][0],   S[2*j][1],   ph[j][0], pl[j][0]);
            split2(S[2*j][2],   S[2*j][3],   ph[j][1], pl[j][1]);
            split2(S[2*j+1][0], S[2*j+1][1], ph[j][2], pl[j][2]);
            split2(S[2*j+1][2], S[2*j+1][3], ph[j][3], pl[j][3]);
        }

        const uint32_t lrow = (lane & 15);
        const uint32_t lcol = ((lane >> 4) & 1) * 16;
#pragma unroll
        for (int j = 0; j < 4; j++) {
            uint32_t va = vbase + (16 * j + lrow) * AROW + lcol;
#pragma unroll
            for (int p = 0; p < 4; p++) {
                uint32_t addr = va + p * 32;
                uint32_t vh0, vh1, vh2, vh3, vl0, vl1, vl2, vl3;
                LDSM_X4_T(vh0, vh1, vh2, vh3, addr);
                LDSM_X4_T(vl0, vl1, vl2, vl3, addr + 9216);
                MMA_BF16(O[2*p],   ph[j][0], ph[j][1], ph[j][2], ph[j][3], vh0, vh1);
                MMA_BF16(O[2*p+1], ph[j][0], ph[j][1], ph[j][2], ph[j][3], vh2, vh3);
                MMA_BF16(O[2*p],   ph[j][0], ph[j][1], ph[j][2], ph[j][3], vl0, vl1);
                MMA_BF16(O[2*p+1], ph[j][0], ph[j][1], ph[j][2], ph[j][3], vl2, vl3);
                MMA_BF16(O[2*p],   pl[j][0], pl[j][1], pl[j][2], pl[j][3], vh0, vh1);
                MMA_BF16(O[2*p+1], pl[j][0], pl[j][1], pl[j][2], pl[j][3], vh2, vh3);
            }
        }
        __syncthreads();
    }

    const float inv0 = 1.0f / ls0, inv1 = 1.0f / ls1;
    const int row0 = qt * 128 + w * 16 + q4;
    const size_t o0 = ((size_t)b * LL + row0) * CC + h * HD;
    const size_t o1 = o0 + 8 * CC;
#pragma unroll
    for (int nt = 0; nt < 8; nt++) {
        int cc = nt * 8 + 2 * l3;
        uint32_t hw, lw;
        split2(O[nt][0] * inv0, O[nt][1] * inv0, hw, lw);
        *(uint32_t*)(g_aoh + o0 + cc) = hw;
        *(uint32_t*)(g_aol + o0 + cc) = lw;
        split2(O[nt][2] * inv1, O[nt][3] * inv1, hw, lw);
        *(uint32_t*)(g_aoh + o1 + cc) = hw;
        *(uint32_t*)(g_aol + o1 + cc) = lw;
    }
}

// ---------------------------------------------------------------------------
extern "C" void kernel_launch(void* const* d_in, const int* in_sizes, int n_in,
                              void* d_out, int out_size)
{
    const float* x      = (const float*)d_in[0];
    const float* w_qkv  = (const float*)d_in[1];
    const float* qgam   = (const float*)d_in[2];
    const float* kgam   = (const float*)d_in[3];
    const float* w_out  = (const float*)d_in[4];
    float* out = (float*)d_out;

    float* qkv; cudaGetSymbolAddress((void**)&qkv, g_qkv);
    __nv_bfloat16 *xh, *xl, *wqh, *wql, *woh, *wol, *aoh, *aol;
    cudaGetSymbolAddress((void**)&xh, g_xh);   cudaGetSymbolAddress((void**)&xl, g_xl);
    cudaGetSymbolAddress((void**)&wqh, g_wqh); cudaGetSymbolAddress((void**)&wql, g_wql);
    cudaGetSymbolAddress((void**)&woh, g_woh); cudaGetSymbolAddress((void**)&wol, g_wol);
    cudaGetSymbolAddress((void**)&aoh, g_aoh); cudaGetSymbolAddress((void**)&aol, g_aol);

    cudaFuncSetAttribute(gemm_bf3_kernel,
                         cudaFuncAttributeMaxDynamicSharedMemorySize, 2 * GSTG);
    cudaFuncSetAttribute(attn_mma_kernel,
                         cudaFuncAttributeMaxDynamicSharedMemorySize, 2 * ASTAGE);

    // 0) pre-split inputs to bf16 hi/lo
    split_kernel<<<(M_TOT * CC / 4 + 255) / 256, 256>>>(x, xh, xl, M_TOT * CC / 4);
    split_kernel<<<(NQKV * CC / 4 + 255) / 256, 256>>>(w_qkv, wqh, wql, NQKV * CC / 4);
    split_kernel<<<(CC * CC / 4 + 255) / 256, 256>>>(w_out, woh, wol, CC * CC / 4);

    // 1) QKV projection
    gemm_bf3_kernel<<<dim3(NQKV / 128, M_TOT / 128), 256, 2 * GSTG>>>(
        xh, xl, wqh, wql, qkv, M_TOT, NQKV, CC);

    // 2) RMSNorm + RoPE + bf16 split
    qkv_post_kernel<<<(BB * LL * NH) / 8, 256>>>(qgam, kgam);

    // 3) Flash attention
    attn_mma_kernel<<<dim3(LL / 128, NH, BB), 256, 2 * ASTAGE>>>();

    // 4) Output projection
    gemm_bf3_kernel<<<dim3(CC / 128, M_TOT / 128), 256, 2 * GSTG>>>(
        aoh, aol, woh, wol, out, M_TOT, CC, CC);
}

// round 7
// speedup vs baseline: 2.6806x; 1.0441x over previous
#include <cuda_runtime.h>
#include <cuda_bf16.h>
#include <cstdint>
#include <math.h>

#define BB 8
#define LL 1024
#define CC 768
#define NH 12
#define HD 64
#define M_TOT (BB*LL)      /* 8192 */
#define NQKV (3*CC)        /* 2304 */

// ---------------- scratch (device globals: no allocation allowed) ----------
__device__ float g_qkv[(size_t)M_TOT * NQKV];
__device__ __nv_bfloat16 g_xh[(size_t)M_TOT * CC],  g_xl[(size_t)M_TOT * CC];
__device__ __nv_bfloat16 g_wqh[(size_t)NQKV * CC],  g_wql[(size_t)NQKV * CC];
__device__ __nv_bfloat16 g_woh[(size_t)CC * CC],    g_wol[(size_t)CC * CC];
__device__ __nv_bfloat16 g_aoh[(size_t)M_TOT * CC], g_aol[(size_t)M_TOT * CC];
__device__ __nv_bfloat16 g_qh[(size_t)BB*NH*LL*HD], g_ql[(size_t)BB*NH*LL*HD];
__device__ __nv_bfloat16 g_kh[(size_t)BB*NH*LL*HD], g_kl[(size_t)BB*NH*LL*HD];
__device__ __nv_bfloat16 g_vh[(size_t)BB*NH*LL*HD], g_vl[(size_t)BB*NH*LL*HD];

// ---------------------------------------------------------------------------
__device__ __forceinline__ float ex2f(float x) {
    float y;
    asm("ex2.approx.ftz.f32 %0, %1;" : "=f"(y) : "f"(x));
    return y;
}
__device__ __forceinline__ uint32_t smem_u32(const void* p) {
    uint32_t a;
    asm("{ .reg .u64 t; cvta.to.shared.u64 t, %1; cvt.u32.u64 %0, t; }"
        : "=r"(a) : "l"(p));
    return a;
}
__device__ __forceinline__ void split2(float a, float b, uint32_t& hi, uint32_t& lo) {
    __nv_bfloat16 ha = __float2bfloat16_rn(a);
    __nv_bfloat16 hb = __float2bfloat16_rn(b);
    float ra = a - __bfloat162float(ha);
    float rb = b - __bfloat162float(hb);
    __nv_bfloat16 la = __float2bfloat16_rn(ra);
    __nv_bfloat16 lb = __float2bfloat16_rn(rb);
    hi = ((uint32_t)*(uint16_t*)&hb << 16) | (uint32_t)*(uint16_t*)&ha;
    lo = ((uint32_t)*(uint16_t*)&lb << 16) | (uint32_t)*(uint16_t*)&la;
}

#define MMA_BF16(Cr, A0, A1, A2, A3, B0, B1) \
    asm volatile("mma.sync.aligned.m16n8k16.row.col.f32.bf16.bf16.f32 " \
        "{%0,%1,%2,%3}, {%4,%5,%6,%7}, {%8,%9}, {%0,%1,%2,%3};" \
        : "+f"((Cr)[0]), "+f"((Cr)[1]), "+f"((Cr)[2]), "+f"((Cr)[3]) \
        : "r"(A0), "r"(A1), "r"(A2), "r"(A3), "r"(B0), "r"(B1))

#define LDSM_X4(r0, r1, r2, r3, addr) \
    asm volatile("ldmatrix.sync.aligned.m8n8.x4.shared.b16 {%0,%1,%2,%3}, [%4];" \
        : "=r"(r0), "=r"(r1), "=r"(r2), "=r"(r3) : "r"(addr))

#define LDSM_X4_T(r0, r1, r2, r3, addr) \
    asm volatile("ldmatrix.sync.aligned.m8n8.x4.trans.shared.b16 {%0,%1,%2,%3}, [%4];" \
        : "=r"(r0), "=r"(r1), "=r"(r2), "=r"(r3) : "r"(addr))

#define CP_ASYNC16(dst, src) \
    asm volatile("cp.async.cg.shared.global [%0], [%1], 16;" \
                 :: "r"(dst), "l"(src) : "memory")
#define CP_COMMIT() asm volatile("cp.async.commit_group;" ::: "memory")
#define CP_WAIT0()  asm volatile("cp.async.wait_group 0;" ::: "memory")
#define CP_WAIT1()  asm volatile("cp.async.wait_group 1;" ::: "memory")

// ===========================================================================
// split: fp32 -> bf16 hi/lo
// ===========================================================================
__global__ __launch_bounds__(256) void split_kernel(
    const float* __restrict__ src, __nv_bfloat16* __restrict__ h,
    __nv_bfloat16* __restrict__ l, int n4)
{
    int i = blockIdx.x * 256 + threadIdx.x;
    if (i < n4) {
        float4 v = ((const float4*)src)[i];
        uint32_t h0, l0, h1, l1;
        split2(v.x, v.y, h0, l0);
        split2(v.z, v.w, h1, l1);
        ((uint2*)h)[i] = make_uint2(h0, h1);
        ((uint2*)l)[i] = make_uint2(l0, l1);
    }
}

// ===========================================================================
// Pipelined all-bf16 GEMM (NT) x3-split, ldmatrix, term-outer MMA ordering.
// BM=BN=128, BK=32, 256 thr = 8 warps (2x4), warp tile 64x32, 2 CTAs/SM.
// Stage (40960B): Ah@0 Al@10240 Bh@20480 Bl@30720, 128 rows x 80B.
// ===========================================================================
#define GSTG 40960

__global__ __launch_bounds__(256, 2) void gemm_bf3_kernel(
    const __nv_bfloat16* __restrict__ Ah, const __nv_bfloat16* __restrict__ Al,
    const __nv_bfloat16* __restrict__ Bh, const __nv_bfloat16* __restrict__ Bl,
    float* __restrict__ C, int M, int N, int K)
{
    extern __shared__ uint8_t smraw[];
    const uint32_t sbase = smem_u32(smraw);

    const int tid  = threadIdx.x;
    const int wid  = tid >> 5;
    const int lane = tid & 31;
    const int wm = wid & 1;
    const int wn = wid >> 1;
    const int row0 = blockIdx.y * 128;
    const int col0 = blockIdx.x * 128;
    const int q4 = lane >> 2;
    const int l3 = lane & 3;
    const int lr16  = lane & 15;
    const int lhalf = (lane >> 4) * 16;

    float c[4][4][4];
#pragma unroll
    for (int m = 0; m < 4; m++)
#pragma unroll
        for (int n = 0; n < 4; n++)
#pragma unroll
            for (int q = 0; q < 4; q++) c[m][n][q] = 0.f;

    const int nch = K / 32;

    {
        uint32_t dst = sbase;
#pragma unroll
        for (int j = 0; j < 8; j++) {
            int i = tid + 256 * j;
            int a = i >> 9, r = (i >> 2) & 127, cc = i & 3;
            const __nv_bfloat16* base = (a == 0) ? Ah : (a == 1) ? Al : (a == 2) ? Bh : Bl;
            int grow = ((a < 2) ? row0 : col0) + r;
            CP_ASYNC16(dst + a * 10240 + r * 80 + cc * 16,
                       base + (size_t)grow * K + cc * 8);
        }
        CP_COMMIT();
    }

#pragma unroll 1
    for (int ch = 0; ch < nch; ch++) {
        if (ch + 1 < nch) {
            uint32_t dst = sbase + ((ch + 1) & 1) * GSTG;
            const int k0 = (ch + 1) * 32;
#pragma unroll
            for (int j = 0; j < 8; j++) {
                int i = tid + 256 * j;
                int a = i >> 9, r = (i >> 2) & 127, cc = i & 3;
                const __nv_bfloat16* base = (a == 0) ? Ah : (a == 1) ? Al : (a == 2) ? Bh : Bl;
                int grow = ((a < 2) ? row0 : col0) + r;
                CP_ASYNC16(dst + a * 10240 + r * 80 + cc * 16,
                           base + (size_t)grow * K + k0 + cc * 8);
            }
            CP_COMMIT();
            CP_WAIT1();
        } else {
            CP_WAIT0();
        }
        __syncthreads();

        const uint32_t sst = sbase + (ch & 1) * GSTG;

#pragma unroll
        for (int ks = 0; ks < 2; ks++) {
            uint32_t ah[4][4], al[4][4];
#pragma unroll
            for (int m = 0; m < 4; m++) {
                uint32_t arow = sst + (wm * 64 + m * 16 + lr16) * 80 + lhalf + ks * 32;
                LDSM_X4(ah[m][0], ah[m][1], ah[m][2], ah[m][3], arow);
                LDSM_X4(al[m][0], al[m][1], al[m][2], al[m][3], arow + 10240);
            }
#pragma unroll
            for (int np = 0; np < 2; np++) {
                uint32_t brow = sst + 20480 + (wn * 32 + np * 16 + lr16) * 80 + lhalf + ks * 32;
                uint32_t h0, h1, h2, h3, L0, L1, L2, L3;
                LDSM_X4(h0, h1, h2, h3, brow);
                LDSM_X4(L0, L1, L2, L3, brow + 10240);
                // term hh — 8 independent MMAs
#pragma unroll
                for (int m = 0; m < 4; m++)
                    MMA_BF16(c[m][2*np],   ah[m][0], ah[m][1], ah[m][2], ah[m][3], h0, h2);
#pragma unroll
                for (int m = 0; m < 4; m++)
                    MMA_BF16(c[m][2*np+1], ah[m][0], ah[m][1], ah[m][2], ah[m][3], h1, h3);
                // term hl
#pragma unroll
                for (int m = 0; m < 4; m++)
                    MMA_BF16(c[m][2*np],   ah[m][0], ah[m][1], ah[m][2], ah[m][3], L0, L2);
#pragma unroll
                for (int m = 0; m < 4; m++)
                    MMA_BF16(c[m][2*np+1], ah[m][0], ah[m][1], ah[m][2], ah[m][3], L1, L3);
                // term lh
#pragma unroll
                for (int m = 0; m < 4; m++)
                    MMA_BF16(c[m][2*np],   al[m][0], al[m][1], al[m][2], al[m][3], h0, h2);
#pragma unroll
                for (int m = 0; m < 4; m++)
                    MMA_BF16(c[m][2*np+1], al[m][0], al[m][1], al[m][2], al[m][3], h1, h3);
            }
        }
        __syncthreads();
    }

#pragma unroll
    for (int m = 0; m < 4; m++) {
        const int r = row0 + wm * 64 + m * 16 + q4;
#pragma unroll
        for (int n = 0; n < 4; n++) {
            const int cc = col0 + wn * 32 + n * 8 + l3 * 2;
            *(float2*)(C + (size_t)r * N + cc)       = make_float2(c[m][n][0], c[m][n][1]);
            *(float2*)(C + (size_t)(r + 8) * N + cc) = make_float2(c[m][n][2], c[m][n][3]);
        }
    }
}

// ---------------------------------------------------------------------------
// QKV epilogue: RMSNorm + RoPE, bf16 hi/lo split to [b,h,l,e].
// ---------------------------------------------------------------------------
__device__ __forceinline__ void store_split(__nv_bfloat16* ah, __nv_bfloat16* al,
                                            size_t idx, float v) {
    __nv_bfloat16 h = __float2bfloat16_rn(v);
    ah[idx] = h;
    al[idx] = __float2bfloat16_rn(v - __bfloat162float(h));
}

__global__ __launch_bounds__(256) void qkv_post_kernel(
    const float* __restrict__ qg, const float* __restrict__ kg)
{
    const int widx = blockIdx.x * 8 + (threadIdx.x >> 5);
    const int lane = threadIdx.x & 31;
    const int h = widx % NH;
    const int l = (widx / NH) % LL;
    const int b = widx / (NH * LL);

    const float* rowp = g_qkv + (size_t)(b * LL + l) * NQKV + h * HD;
    const float ifr = exp2f(-13.287712379549449f * (float)lane * (1.0f / 32.0f));
    const float ang = (float)l * ifr;
    const float cs = cosf(ang), sn = sinf(ang);
    const size_t dsto = ((size_t)(b * NH + h) * LL + l) * HD;
    const float QS = 0.125f * 1.4426950408889634f;

    {
        float x1 = rowp[lane], x2 = rowp[lane + 32];
        float ss = x1 * x1 + x2 * x2;
#pragma unroll
        for (int o = 16; o; o >>= 1) ss += __shfl_xor_sync(0xffffffffu, ss, o);
        float r = rsqrtf(ss * (1.0f / HD) + 1e-6f);
        float n1 = x1 * r * qg[lane], n2 = x2 * r * qg[lane + 32];
        store_split(g_qh, g_ql, dsto + lane,      (n1 * cs - n2 * sn) * QS);
        store_split(g_qh, g_ql, dsto + lane + 32, (n1 * sn + n2 * cs) * QS);
    }
    {
        float x1 = rowp[CC + lane], x2 = rowp[CC + lane + 32];
        float ss = x1 * x1 + x2 * x2;
#pragma unroll
        for (int o = 16; o; o >>= 1) ss += __shfl_xor_sync(0xffffffffu, ss, o);
        float r = rsqrtf(ss * (1.0f / HD) + 1e-6f);
        float n1 = x1 * r * kg[lane], n2 = x2 * r * kg[lane + 32];
        store_split(g_kh, g_kl, dsto + lane,      n1 * cs - n2 * sn);
        store_split(g_kh, g_kl, dsto + lane + 32, n1 * sn + n2 * cs);
    }
    store_split(g_vh, g_vl, dsto + lane,      rowp[2 * CC + lane]);
    store_split(g_vh, g_vl, dsto + lane + 32, rowp[2 * CC + lane + 32]);
}

// ===========================================================================
// Flash attention via mma.sync bf16x3, term-outer MMA ordering.
// ===========================================================================
#define ASTAGE 36864
#define AROW   144
#define AROWW  36

__global__ __launch_bounds__(256) void attn_mma_kernel()
{
    extern __shared__ uint8_t smraw[];
    uint32_t* smw = (uint32_t*)smraw;
    const uint32_t sbase = smem_u32(smraw);

    const int tid  = threadIdx.x;
    const int w    = tid >> 5;
    const int lane = tid & 31;
    const int q4   = lane >> 2;
    const int l3   = lane & 3;
    const int qt = blockIdx.x, h = blockIdx.y, b = blockIdx.z;

    const size_t hb = (size_t)(b * NH + h) * LL * HD;
    const __nv_bfloat16* Qh = g_qh + hb + (size_t)qt * 128 * HD;
    const __nv_bfloat16* Ql = g_ql + hb + (size_t)qt * 128 * HD;
    const __nv_bfloat16* Kh = g_kh + hb;
    const __nv_bfloat16* Kl = g_kl + hb;
    const __nv_bfloat16* Vh = g_vh + hb;
    const __nv_bfloat16* Vl = g_vl + hb;

#pragma unroll
    for (int t = 0; t < 8; t++) {
        int i = tid + 256 * t;
        int a = i >> 10, r = (i >> 3) & 127, c = i & 7;
        const __nv_bfloat16* src = (a ? Ql : Qh) + (size_t)r * HD + c * 8;
        CP_ASYNC16(sbase + a * 18432 + r * AROW + c * 16, src);
    }
    CP_COMMIT(); CP_WAIT0();
    __syncthreads();

    uint32_t qhf[4][4], qlf[4][4];
#pragma unroll
    for (int ks = 0; ks < 4; ks++) {
        int base = (w * 16 + q4) * AROWW + ks * 8 + l3;
        qhf[ks][0] = smw[base];                qhf[ks][1] = smw[base + 8 * AROWW];
        qhf[ks][2] = smw[base + 4];            qhf[ks][3] = smw[base + 8 * AROWW + 4];
        qlf[ks][0] = smw[4608 + base];         qlf[ks][1] = smw[4608 + base + 8 * AROWW];
        qlf[ks][2] = smw[4608 + base + 4];     qlf[ks][3] = smw[4608 + base + 8 * AROWW + 4];
    }
    __syncthreads();

    float m0 = -1e30f, m1 = -1e30f, ls0 = 0.f, ls1 = 0.f;
    float O[8][4];
#pragma unroll
    for (int n = 0; n < 8; n++)
#pragma unroll
        for (int q = 0; q < 4; q++) O[n][q] = 0.f;

#pragma unroll
    for (int t = 0; t < 8; t++) {
        int i = tid + 256 * t;
        int a = i >> 9, r = (i >> 3) & 63, c = i & 7;
        const __nv_bfloat16* base = (a == 0) ? Kh : (a == 1) ? Kl : (a == 2) ? Vh : Vl;
        CP_ASYNC16(sbase + a * 9216 + r * AROW + c * 16,
                   base + (size_t)r * HD + c * 8);
    }
    CP_COMMIT();

#pragma unroll 1
    for (int kt = 0; kt < 16; kt++) {
        if (kt < 15) {
            uint32_t dst = sbase + ((kt + 1) & 1) * ASTAGE;
            const int r0 = (kt + 1) * 64;
#pragma unroll
            for (int t = 0; t < 8; t++) {
                int i = tid + 256 * t;
                int a = i >> 9, r = (i >> 3) & 63, c = i & 7;
                const __nv_bfloat16* base = (a == 0) ? Kh : (a == 1) ? Kl : (a == 2) ? Vh : Vl;
                CP_ASYNC16(dst + a * 9216 + r * AROW + c * 16,
                           base + (size_t)(r0 + r) * HD + c * 8);
            }
            CP_COMMIT();
            CP_WAIT1();
        } else {
            CP_WAIT0();
        }
        __syncthreads();

        const uint32_t* KW = smw + (kt & 1) * (ASTAGE / 4);
        const uint32_t vbase = sbase + (kt & 1) * ASTAGE + 18432;

        // ---- S = Q K^T, term-outer over groups of 4 nt ----
        float S[8][4];
#pragma unroll
        for (int n = 0; n < 8; n++)
#pragma unroll
            for (int q = 0; q < 4; q++) S[n][q] = 0.f;

#pragma unroll
        for (int ks = 0; ks < 4; ks++) {
#pragma unroll
            for (int g = 0; g < 2; g++) {
                uint32_t bh[4][2], bl[4][2];
#pragma unroll
                for (int j = 0; j < 4; j++) {
                    int kb = ((g * 4 + j) * 8 + q4) * AROWW + ks * 8 + l3;
                    bh[j][0] = KW[kb];        bh[j][1] = KW[kb + 4];
                    bl[j][0] = KW[2304 + kb]; bl[j][1] = KW[2304 + kb + 4];
                }
#pragma unroll
                for (int j = 0; j < 4; j++)
                    MMA_BF16(S[g*4+j], qhf[ks][0], qhf[ks][1], qhf[ks][2], qhf[ks][3],
                             bh[j][0], bh[j][1]);
#pragma unroll
                for (int j = 0; j < 4; j++)
                    MMA_BF16(S[g*4+j], qhf[ks][0], qhf[ks][1], qhf[ks][2], qhf[ks][3],
                             bl[j][0], bl[j][1]);
#pragma unroll
                for (int j = 0; j < 4; j++)
                    MMA_BF16(S[g*4+j], qlf[ks][0], qlf[ks][1], qlf[ks][2], qlf[ks][3],
                             bh[j][0], bh[j][1]);
            }
        }

        // ---- online softmax (log2 domain) ----
        float mx0 = -1e30f, mx1 = -1e30f;
#pragma unroll
        for (int nt = 0; nt < 8; nt++) {
            mx0 = fmaxf(mx0, fmaxf(S[nt][0], S[nt][1]));
            mx1 = fmaxf(mx1, fmaxf(S[nt][2], S[nt][3]));
        }
        mx0 = fmaxf(mx0, __shfl_xor_sync(0xffffffffu, mx0, 1));
        mx0 = fmaxf(mx0, __shfl_xor_sync(0xffffffffu, mx0, 2));
        mx1 = fmaxf(mx1, __shfl_xor_sync(0xffffffffu, mx1, 1));
        mx1 = fmaxf(mx1, __shfl_xor_sync(0xffffffffu, mx1, 2));
        float mn0 = fmaxf(m0, mx0), mn1 = fmaxf(m1, mx1);
        float a0 = ex2f(m0 - mn0), a1 = ex2f(m1 - mn1);
        float rs0 = 0.f, rs1 = 0.f;
#pragma unroll
        for (int nt = 0; nt < 8; nt++) {
            S[nt][0] = ex2f(S[nt][0] - mn0); S[nt][1] = ex2f(S[nt][1] - mn0);
            S[nt][2] = ex2f(S[nt][2] - mn1); S[nt][3] = ex2f(S[nt][3] - mn1);
            rs0 += S[nt][0] + S[nt][1];
            rs1 += S[nt][2] + S[nt][3];
        }
        rs0 += __shfl_xor_sync(0xffffffffu, rs0, 1);
        rs0 += __shfl_xor_sync(0xffffffffu, rs0, 2);
        rs1 += __shfl_xor_sync(0xffffffffu, rs1, 1);
        rs1 += __shfl_xor_sync(0xffffffffu, rs1, 2);
        ls0 = ls0 * a0 + rs0;  ls1 = ls1 * a1 + rs1;
        m0 = mn0;  m1 = mn1;
#pragma unroll
        for (int nt = 0; nt < 8; nt++) {
            O[nt][0] *= a0; O[nt][1] *= a0;
            O[nt][2] *= a1; O[nt][3] *= a1;
        }

        uint32_t ph[4][4], pl[4][4];
#pragma unroll
        for (int j = 0; j < 4; j++) {
            split2(S[2*j][0],   S[2*j][1],   ph[j][0], pl[j][0]);
            split2(S[2*j][2],   S[2*j][3],   ph[j][1], pl[j][1]);
            split2(S[2*j+1][0], S[2*j+1][1], ph[j][2], pl[j][2]);
            split2(S[2*j+1][2], S[2*j+1][3], ph[j][3], pl[j][3]);
        }

        // ---- O += P V, term-outer over pairs of p (4 O accums) ----
        const uint32_t lrow = (lane & 15);
        const uint32_t lcol = ((lane >> 4) & 1) * 16;
#pragma unroll
        for (int j = 0; j < 4; j++) {
            uint32_t va = vbase + (16 * j + lrow) * AROW + lcol;
#pragma unroll
            for (int pp = 0; pp < 2; pp++) {
                uint32_t vh[2][4], vl[2][4];
#pragma unroll
                for (int t = 0; t < 2; t++) {
                    uint32_t addr = va + (pp * 2 + t) * 32;
                    LDSM_X4_T(vh[t][0], vh[t][1], vh[t][2], vh[t][3], addr);
                    LDSM_X4_T(vl[t][0], vl[t][1], vl[t][2], vl[t][3], addr + 9216);
                }
                // term ph*vh — 4 independent
#pragma unroll
                for (int t = 0; t < 2; t++) {
                    MMA_BF16(O[4*pp+2*t],   ph[j][0], ph[j][1], ph[j][2], ph[j][3],
                             vh[t][0], vh[t][1]);
                    MMA_BF16(O[4*pp+2*t+1], ph[j][0], ph[j][1], ph[j][2], ph[j][3],
                             vh[t][2], vh[t][3]);
                }
                // term ph*vl
#pragma unroll
                for (int t = 0; t < 2; t++) {
                    MMA_BF16(O[4*pp+2*t],   ph[j][0], ph[j][1], ph[j][2], ph[j][3],
                             vl[t][0], vl[t][1]);
                    MMA_BF16(O[4*pp+2*t+1], ph[j][0], ph[j][1], ph[j][2], ph[j][3],
                             vl[t][2], vl[t][3]);
                }
                // term pl*vh
#pragma unroll
                for (int t = 0; t < 2; t++) {
                    MMA_BF16(O[4*pp+2*t],   pl[j][0], pl[j][1], pl[j][2], pl[j][3],
                             vh[t][0], vh[t][1]);
                    MMA_BF16(O[4*pp+2*t+1], pl[j][0], pl[j][1], pl[j][2], pl[j][3],
                             vh[t][2], vh[t][3]);
                }
            }
        }
        __syncthreads();
    }

    const float inv0 = 1.0f / ls0, inv1 = 1.0f / ls1;
    const int row0 = qt * 128 + w * 16 + q4;
    const size_t o0 = ((size_t)b * LL + row0) * CC + h * HD;
    const size_t o1 = o0 + 8 * CC;
#pragma unroll
    for (int nt = 0; nt < 8; nt++) {
        int cc = nt * 8 + 2 * l3;
        uint32_t hw, lw;
        split2(O[nt][0] * inv0, O[nt][1] * inv0, hw, lw);
        *(uint32_t*)(g_aoh + o0 + cc) = hw;
        *(uint32_t*)(g_aol + o0 + cc) = lw;
        split2(O[nt][2] * inv1, O[nt][3] * inv1, hw, lw);
        *(uint32_t*)(g_aoh + o1 + cc) = hw;
        *(uint32_t*)(g_aol + o1 + cc) = lw;
    }
}

// ---------------------------------------------------------------------------
extern "C" void kernel_launch(void* const* d_in, const int* in_sizes, int n_in,
                              void* d_out, int out_size)
{
    const float* x      = (const float*)d_in[0];
    const float* w_qkv  = (const float*)d_in[1];
    const float* qgam   = (const float*)d_in[2];
    const float* kgam   = (const float*)d_in[3];
    const float* w_out  = (const float*)d_in[4];
    float* out = (float*)d_out;

    float* qkv; cudaGetSymbolAddress((void**)&qkv, g_qkv);
    __nv_bfloat16 *xh, *xl, *wqh, *wql, *woh, *wol, *aoh, *aol;
    cudaGetSymbolAddress((void**)&xh, g_xh);   cudaGetSymbolAddress((void**)&xl, g_xl);
    cudaGetSymbolAddress((void**)&wqh, g_wqh); cudaGetSymbolAddress((void**)&wql, g_wql);
    cudaGetSymbolAddress((void**)&woh, g_woh); cudaGetSymbolAddress((void**)&wol, g_wol);
    cudaGetSymbolAddress((void**)&aoh, g_aoh); cudaGetSymbolAddress((void**)&aol, g_aol);

    cudaFuncSetAttribute(gemm_bf3_kernel,
                         cudaFuncAttributeMaxDynamicSharedMemorySize, 2 * GSTG);
    cudaFuncSetAttribute(attn_mma_kernel,
                         cudaFuncAttributeMaxDynamicSharedMemorySize, 2 * ASTAGE);

    // 0) pre-split inputs
    split_kernel<<<(M_TOT * CC / 4 + 255) / 256, 256>>>(x, xh, xl, M_TOT * CC / 4);
    split_kernel<<<(NQKV * CC / 4 + 255) / 256, 256>>>(w_qkv, wqh, wql, NQKV * CC / 4);
    split_kernel<<<(CC * CC / 4 + 255) / 256, 256>>>(w_out, woh, wol, CC * CC / 4);

    // 1) QKV projection
    gemm_bf3_kernel<<<dim3(NQKV / 128, M_TOT / 128), 256, 2 * GSTG>>>(
        xh, xl, wqh, wql, qkv, M_TOT, NQKV, CC);

    // 2) RMSNorm + RoPE + bf16 split
    qkv_post_kernel<<<(BB * LL * NH) / 8, 256>>>(qgam, kgam);

    // 3) Flash attention
    attn_mma_kernel<<<dim3(LL / 128, NH, BB), 256, 2 * ASTAGE>>>();

    // 4) Output projection
    gemm_bf3_kernel<<<dim3(CC / 128, M_TOT / 128), 256, 2 * GSTG>>>(
        aoh, aol, woh, wol, out, M_TOT, CC, CC);
}

// round 8
// speedup vs baseline: 3.6344x; 1.3558x over previous
#include <cuda_runtime.h>
#include <cuda_fp16.h>
#include <cstdint>
#include <math.h>

#define BB 8
#define LL 1024
#define CC 768
#define NH 12
#define HD 64
#define M_TOT (BB*LL)      /* 8192 */
#define NQKV (3*CC)        /* 2304 */

// ---------------- scratch (device globals: no allocation allowed) ----------
__device__ float g_qkv[(size_t)M_TOT * NQKV];
// fp16 operands: A-side needs hi+lo, B-side hi only
__device__ __half g_xh[(size_t)M_TOT * CC],  g_xl[(size_t)M_TOT * CC];
__device__ __half g_wqh[(size_t)NQKV * CC];
__device__ __half g_woh[(size_t)CC * CC];
__device__ __half g_aoh[(size_t)M_TOT * CC], g_aol[(size_t)M_TOT * CC];
__device__ __half g_qh[(size_t)BB*NH*LL*HD], g_ql[(size_t)BB*NH*LL*HD];
__device__ __half g_kh[(size_t)BB*NH*LL*HD];
__device__ __half g_vh[(size_t)BB*NH*LL*HD];

// ---------------------------------------------------------------------------
__device__ __forceinline__ float ex2f(float x) {
    float y;
    asm("ex2.approx.ftz.f32 %0, %1;" : "=f"(y) : "f"(x));
    return y;
}
__device__ __forceinline__ uint32_t smem_u32(const void* p) {
    uint32_t a;
    asm("{ .reg .u64 t; cvta.to.shared.u64 t, %1; cvt.u32.u64 %0, t; }"
        : "=r"(a) : "l"(p));
    return a;
}
// split fp32 pair -> packed fp16 hi word + fp16 lo (residual) word
__device__ __forceinline__ void split2h(float a, float b, uint32_t& hi, uint32_t& lo) {
    __half ha = __float2half_rn(a);
    __half hb = __float2half_rn(b);
    float ra = a - __half2float(ha);
    float rb = b - __half2float(hb);
    __half la = __float2half_rn(ra);
    __half lb = __float2half_rn(rb);
    hi = ((uint32_t)*(uint16_t*)&hb << 16) | (uint32_t)*(uint16_t*)&ha;
    lo = ((uint32_t)*(uint16_t*)&lb << 16) | (uint32_t)*(uint16_t*)&la;
}

#define MMA_F16(Cr, A0, A1, A2, A3, B0, B1) \
    asm volatile("mma.sync.aligned.m16n8k16.row.col.f32.f16.f16.f32 " \
        "{%0,%1,%2,%3}, {%4,%5,%6,%7}, {%8,%9}, {%0,%1,%2,%3};" \
        : "+f"((Cr)[0]), "+f"((Cr)[1]), "+f"((Cr)[2]), "+f"((Cr)[3]) \
        : "r"(A0), "r"(A1), "r"(A2), "r"(A3), "r"(B0), "r"(B1))

#define LDSM_X4(r0, r1, r2, r3, addr) \
    asm volatile("ldmatrix.sync.aligned.m8n8.x4.shared.b16 {%0,%1,%2,%3}, [%4];" \
        : "=r"(r0), "=r"(r1), "=r"(r2), "=r"(r3) : "r"(addr))

#define LDSM_X4_T(r0, r1, r2, r3, addr) \
    asm volatile("ldmatrix.sync.aligned.m8n8.x4.trans.shared.b16 {%0,%1,%2,%3}, [%4];" \
        : "=r"(r0), "=r"(r1), "=r"(r2), "=r"(r3) : "r"(addr))

#define CP_ASYNC16(dst, src) \
    asm volatile("cp.async.cg.shared.global [%0], [%1], 16;" \
                 :: "r"(dst), "l"(src) : "memory")
#define CP_COMMIT() asm volatile("cp.async.commit_group;" ::: "memory")
#define CP_WAIT0()  asm volatile("cp.async.wait_group 0;" ::: "memory")
#define CP_WAIT1()  asm volatile("cp.async.wait_group 1;" ::: "memory")

// ===========================================================================
// split: fp32 -> fp16 hi/lo (A-side operands)
// ===========================================================================
__global__ __launch_bounds__(256) void split_kernel(
    const float* __restrict__ src, __half* __restrict__ h,
    __half* __restrict__ l, int n4)
{
    int i = blockIdx.x * 256 + threadIdx.x;
    if (i < n4) {
        float4 v = ((const float4*)src)[i];
        uint32_t h0, l0, h1, l1;
        split2h(v.x, v.y, h0, l0);
        split2h(v.z, v.w, h1, l1);
        ((uint2*)h)[i] = make_uint2(h0, h1);
        ((uint2*)l)[i] = make_uint2(l0, l1);
    }
}
// cvt: fp32 -> fp16 (B-side operands, hi only)
__global__ __launch_bounds__(256) void cvt_kernel(
    const float* __restrict__ src, __half* __restrict__ h, int n4)
{
    int i = blockIdx.x * 256 + threadIdx.x;
    if (i < n4) {
        float4 v = ((const float4*)src)[i];
        __half2 a = __floats2half2_rn(v.x, v.y);
        __half2 b = __floats2half2_rn(v.z, v.w);
        ((__half2*)h)[2*i]   = a;
        ((__half2*)h)[2*i+1] = b;
    }
}

// ===========================================================================
// Pipelined fp16x2 GEMM (NT): C = (Ah+Al)*Bh^T, fp32 out.
// BM=BN=128, BK=32, 256 thr = 8 warps (2x4), warp tile 64x32, 2 CTAs/SM.
// Stage (30720B): Ah@0 Al@10240 Bh@20480, 128 rows x 80B.
// ===========================================================================
#define GSTG 30720

__global__ __launch_bounds__(256, 2) void gemm_2t_kernel(
    const __half* __restrict__ Ah, const __half* __restrict__ Al,
    const __half* __restrict__ Bh,
    float* __restrict__ C, int M, int N, int K)
{
    extern __shared__ uint8_t smraw[];
    const uint32_t sbase = smem_u32(smraw);

    const int tid  = threadIdx.x;
    const int wid  = tid >> 5;
    const int lane = tid & 31;
    const int wm = wid & 1;
    const int wn = wid >> 1;
    const int row0 = blockIdx.y * 128;
    const int col0 = blockIdx.x * 128;
    const int q4 = lane >> 2;
    const int l3 = lane & 3;
    const int lr16  = lane & 15;
    const int lhalf = (lane >> 4) * 16;

    float c[4][4][4];
#pragma unroll
    for (int m = 0; m < 4; m++)
#pragma unroll
        for (int n = 0; n < 4; n++)
#pragma unroll
            for (int q = 0; q < 4; q++) c[m][n][q] = 0.f;

    const int nch = K / 32;

    {
        uint32_t dst = sbase;
#pragma unroll
        for (int j = 0; j < 6; j++) {
            int i = tid + 256 * j;
            int a = i >> 9, r = (i >> 2) & 127, cc = i & 3;
            const __half* base = (a == 0) ? Ah : (a == 1) ? Al : Bh;
            int grow = ((a < 2) ? row0 : col0) + r;
            CP_ASYNC16(dst + a * 10240 + r * 80 + cc * 16,
                       base + (size_t)grow * K + cc * 8);
        }
        CP_COMMIT();
    }

#pragma unroll 1
    for (int ch = 0; ch < nch; ch++) {
        if (ch + 1 < nch) {
            uint32_t dst = sbase + ((ch + 1) & 1) * GSTG;
            const int k0 = (ch + 1) * 32;
#pragma unroll
            for (int j = 0; j < 6; j++) {
                int i = tid + 256 * j;
                int a = i >> 9, r = (i >> 2) & 127, cc = i & 3;
                const __half* base = (a == 0) ? Ah : (a == 1) ? Al : Bh;
                int grow = ((a < 2) ? row0 : col0) + r;
                CP_ASYNC16(dst + a * 10240 + r * 80 + cc * 16,
                           base + (size_t)grow * K + k0 + cc * 8);
            }
            CP_COMMIT();
            CP_WAIT1();
        } else {
            CP_WAIT0();
        }
        __syncthreads();

        const uint32_t sst = sbase + (ch & 1) * GSTG;

#pragma unroll
        for (int ks = 0; ks < 2; ks++) {
            uint32_t ah[4][4], al[4][4];
#pragma unroll
            for (int m = 0; m < 4; m++) {
                uint32_t arow = sst + (wm * 64 + m * 16 + lr16) * 80 + lhalf + ks * 32;
                LDSM_X4(ah[m][0], ah[m][1], ah[m][2], ah[m][3], arow);
                LDSM_X4(al[m][0], al[m][1], al[m][2], al[m][3], arow + 10240);
            }
#pragma unroll
            for (int np = 0; np < 2; np++) {
                uint32_t brow = sst + 20480 + (wn * 32 + np * 16 + lr16) * 80 + lhalf + ks * 32;
                uint32_t h0, h1, h2, h3;
                LDSM_X4(h0, h1, h2, h3, brow);
                // term hh — 8 independent MMAs
#pragma unroll
                for (int m = 0; m < 4; m++)
                    MMA_F16(c[m][2*np],   ah[m][0], ah[m][1], ah[m][2], ah[m][3], h0, h2);
#pragma unroll
                for (int m = 0; m < 4; m++)
                    MMA_F16(c[m][2*np+1], ah[m][0], ah[m][1], ah[m][2], ah[m][3], h1, h3);
                // term lh
#pragma unroll
                for (int m = 0; m < 4; m++)
                    MMA_F16(c[m][2*np],   al[m][0], al[m][1], al[m][2], al[m][3], h0, h2);
#pragma unroll
                for (int m = 0; m < 4; m++)
                    MMA_F16(c[m][2*np+1], al[m][0], al[m][1], al[m][2], al[m][3], h1, h3);
            }
        }
        __syncthreads();
    }

#pragma unroll
    for (int m = 0; m < 4; m++) {
        const int r = row0 + wm * 64 + m * 16 + q4;
#pragma unroll
        for (int n = 0; n < 4; n++) {
            const int cc = col0 + wn * 32 + n * 8 + l3 * 2;
            *(float2*)(C + (size_t)r * N + cc)       = make_float2(c[m][n][0], c[m][n][1]);
            *(float2*)(C + (size_t)(r + 8) * N + cc) = make_float2(c[m][n][2], c[m][n][3]);
        }
    }
}

// ---------------------------------------------------------------------------
// QKV epilogue: RMSNorm + RoPE; q -> fp16 hi/lo, k/v -> fp16 hi. [b,h,l,e].
// ---------------------------------------------------------------------------
__global__ __launch_bounds__(256) void qkv_post_kernel(
    const float* __restrict__ qg, const float* __restrict__ kg)
{
    const int widx = blockIdx.x * 8 + (threadIdx.x >> 5);
    const int lane = threadIdx.x & 31;
    const int h = widx % NH;
    const int l = (widx / NH) % LL;
    const int b = widx / (NH * LL);

    const float* rowp = g_qkv + (size_t)(b * LL + l) * NQKV + h * HD;
    const float ifr = exp2f(-13.287712379549449f * (float)lane * (1.0f / 32.0f));
    const float ang = (float)l * ifr;
    const float cs = cosf(ang), sn = sinf(ang);
    const size_t dsto = ((size_t)(b * NH + h) * LL + l) * HD;
    const float QS = 0.125f * 1.4426950408889634f;

    {
        float x1 = rowp[lane], x2 = rowp[lane + 32];
        float ss = x1 * x1 + x2 * x2;
#pragma unroll
        for (int o = 16; o; o >>= 1) ss += __shfl_xor_sync(0xffffffffu, ss, o);
        float r = rsqrtf(ss * (1.0f / HD) + 1e-6f);
        float n1 = x1 * r * qg[lane], n2 = x2 * r * qg[lane + 32];
        float v1 = (n1 * cs - n2 * sn) * QS;
        float v2 = (n1 * sn + n2 * cs) * QS;
        __half h1 = __float2half_rn(v1), h2 = __float2half_rn(v2);
        g_qh[dsto + lane]      = h1;
        g_qh[dsto + lane + 32] = h2;
        g_ql[dsto + lane]      = __float2half_rn(v1 - __half2float(h1));
        g_ql[dsto + lane + 32] = __float2half_rn(v2 - __half2float(h2));
    }
    {
        float x1 = rowp[CC + lane], x2 = rowp[CC + lane + 32];
        float ss = x1 * x1 + x2 * x2;
#pragma unroll
        for (int o = 16; o; o >>= 1) ss += __shfl_xor_sync(0xffffffffu, ss, o);
        float r = rsqrtf(ss * (1.0f / HD) + 1e-6f);
        float n1 = x1 * r * kg[lane], n2 = x2 * r * kg[lane + 32];
        g_kh[dsto + lane]      = __float2half_rn(n1 * cs - n2 * sn);
        g_kh[dsto + lane + 32] = __float2half_rn(n1 * sn + n2 * cs);
    }
    g_vh[dsto + lane]      = __float2half_rn(rowp[2 * CC + lane]);
    g_vh[dsto + lane + 32] = __float2half_rn(rowp[2 * CC + lane + 32]);
}

// ===========================================================================
// Flash attention via mma.sync fp16x2.
// Q (hi+lo) staged once; per-kt stages hold Kh + Vh only (18432B each).
// ===========================================================================
#define ASTG  18432      /* per-stage: Kh 64x144 @0, Vh @9216 */
#define AROW  144
#define AROWW 36

__global__ __launch_bounds__(256) void attn_mma_kernel()
{
    extern __shared__ uint8_t smraw[];
    uint32_t* smw = (uint32_t*)smraw;
    const uint32_t sbase = smem_u32(smraw);

    const int tid  = threadIdx.x;
    const int w    = tid >> 5;
    const int lane = tid & 31;
    const int q4   = lane >> 2;
    const int l3   = lane & 3;
    const int qt = blockIdx.x, h = blockIdx.y, b = blockIdx.z;

    const size_t hb = (size_t)(b * NH + h) * LL * HD;
    const __half* Qh = g_qh + hb + (size_t)qt * 128 * HD;
    const __half* Ql = g_ql + hb + (size_t)qt * 128 * HD;
    const __half* Kh = g_kh + hb;
    const __half* Vh = g_vh + hb;

    // stage Q: qh 128x144 @0, ql @18432
#pragma unroll
    for (int t = 0; t < 8; t++) {
        int i = tid + 256 * t;
        int a = i >> 10, r = (i >> 3) & 127, c = i & 7;
        const __half* src = (a ? Ql : Qh) + (size_t)r * HD + c * 8;
        CP_ASYNC16(sbase + a * 18432 + r * AROW + c * 16, src);
    }
    CP_COMMIT(); CP_WAIT0();
    __syncthreads();

    uint32_t qhf[4][4], qlf[4][4];
#pragma unroll
    for (int ks = 0; ks < 4; ks++) {
        int base = (w * 16 + q4) * AROWW + ks * 8 + l3;
        qhf[ks][0] = smw[base];                qhf[ks][1] = smw[base + 8 * AROWW];
        qhf[ks][2] = smw[base + 4];            qhf[ks][3] = smw[base + 8 * AROWW + 4];
        qlf[ks][0] = smw[4608 + base];         qlf[ks][1] = smw[4608 + base + 8 * AROWW];
        qlf[ks][2] = smw[4608 + base + 4];     qlf[ks][3] = smw[4608 + base + 8 * AROWW + 4];
    }
    __syncthreads();

    float m0 = -1e30f, m1 = -1e30f, ls0 = 0.f, ls1 = 0.f;
    float O[8][4];
#pragma unroll
    for (int n = 0; n < 8; n++)
#pragma unroll
        for (int q = 0; q < 4; q++) O[n][q] = 0.f;

    // issue kt=0 loads into stage 0
#pragma unroll
    for (int t = 0; t < 4; t++) {
        int i = tid + 256 * t;
        int a = i >> 9, r = (i >> 3) & 63, c = i & 7;
        const __half* base = (a == 0) ? Kh : Vh;
        CP_ASYNC16(sbase + a * 9216 + r * AROW + c * 16,
                   base + (size_t)r * HD + c * 8);
    }
    CP_COMMIT();

#pragma unroll 1
    for (int kt = 0; kt < 16; kt++) {
        if (kt < 15) {
            uint32_t dst = sbase + ((kt + 1) & 1) * ASTG;
            const int r0 = (kt + 1) * 64;
#pragma unroll
            for (int t = 0; t < 4; t++) {
                int i = tid + 256 * t;
                int a = i >> 9, r = (i >> 3) & 63, c = i & 7;
                const __half* base = (a == 0) ? Kh : Vh;
                CP_ASYNC16(dst + a * 9216 + r * AROW + c * 16,
                           base + (size_t)(r0 + r) * HD + c * 8);
            }
            CP_COMMIT();
            CP_WAIT1();
        } else {
            CP_WAIT0();
        }
        __syncthreads();

        const uint32_t* KW = smw + (kt & 1) * (ASTG / 4);
        const uint32_t vbase = sbase + (kt & 1) * ASTG + 9216;

        // ---- S = Q K^T (2-term), term-outer over groups of 4 nt ----
        float S[8][4];
#pragma unroll
        for (int n = 0; n < 8; n++)
#pragma unroll
            for (int q = 0; q < 4; q++) S[n][q] = 0.f;

#pragma unroll
        for (int ks = 0; ks < 4; ks++) {
#pragma unroll
            for (int g = 0; g < 2; g++) {
                uint32_t bh[4][2];
#pragma unroll
                for (int j = 0; j < 4; j++) {
                    int kb = ((g * 4 + j) * 8 + q4) * AROWW + ks * 8 + l3;
                    bh[j][0] = KW[kb];  bh[j][1] = KW[kb + 4];
                }
#pragma unroll
                for (int j = 0; j < 4; j++)
                    MMA_F16(S[g*4+j], qhf[ks][0], qhf[ks][1], qhf[ks][2], qhf[ks][3],
                            bh[j][0], bh[j][1]);
#pragma unroll
                for (int j = 0; j < 4; j++)
                    MMA_F16(S[g*4+j], qlf[ks][0], qlf[ks][1], qlf[ks][2], qlf[ks][3],
                            bh[j][0], bh[j][1]);
            }
        }

        // ---- online softmax (log2 domain) ----
        float mx0 = -1e30f, mx1 = -1e30f;
#pragma unroll
        for (int nt = 0; nt < 8; nt++) {
            mx0 = fmaxf(mx0, fmaxf(S[nt][0], S[nt][1]));
            mx1 = fmaxf(mx1, fmaxf(S[nt][2], S[nt][3]));
        }
        mx0 = fmaxf(mx0, __shfl_xor_sync(0xffffffffu, mx0, 1));
        mx0 = fmaxf(mx0, __shfl_xor_sync(0xffffffffu, mx0, 2));
        mx1 = fmaxf(mx1, __shfl_xor_sync(0xffffffffu, mx1, 1));
        mx1 = fmaxf(mx1, __shfl_xor_sync(0xffffffffu, mx1, 2));
        float mn0 = fmaxf(m0, mx0), mn1 = fmaxf(m1, mx1);
        float a0 = ex2f(m0 - mn0), a1 = ex2f(m1 - mn1);
        float rs0 = 0.f, rs1 = 0.f;
#pragma unroll
        for (int nt = 0; nt < 8; nt++) {
            S[nt][0] = ex2f(S[nt][0] - mn0); S[nt][1] = ex2f(S[nt][1] - mn0);
            S[nt][2] = ex2f(S[nt][2] - mn1); S[nt][3] = ex2f(S[nt][3] - mn1);
            rs0 += S[nt][0] + S[nt][1];
            rs1 += S[nt][2] + S[nt][3];
        }
        rs0 += __shfl_xor_sync(0xffffffffu, rs0, 1);
        rs0 += __shfl_xor_sync(0xffffffffu, rs0, 2);
        rs1 += __shfl_xor_sync(0xffffffffu, rs1, 1);
        rs1 += __shfl_xor_sync(0xffffffffu, rs1, 2);
        ls0 = ls0 * a0 + rs0;  ls1 = ls1 * a1 + rs1;
        m0 = mn0;  m1 = mn1;
#pragma unroll
        for (int nt = 0; nt < 8; nt++) {
            O[nt][0] *= a0; O[nt][1] *= a0;
            O[nt][2] *= a1; O[nt][3] *= a1;
        }

        // ---- pack P fragments (fp16 hi/lo) ----
        uint32_t ph[4][4], pl[4][4];
#pragma unroll
        for (int j = 0; j < 4; j++) {
            split2h(S[2*j][0],   S[2*j][1],   ph[j][0], pl[j][0]);
            split2h(S[2*j][2],   S[2*j][3],   ph[j][1], pl[j][1]);
            split2h(S[2*j+1][0], S[2*j+1][1], ph[j][2], pl[j][2]);
            split2h(S[2*j+1][2], S[2*j+1][3], ph[j][3], pl[j][3]);
        }

        // ---- O += P V (2-term), V hi only ----
        const uint32_t lrow = (lane & 15);
        const uint32_t lcol = ((lane >> 4) & 1) * 16;
#pragma unroll
        for (int j = 0; j < 4; j++) {
            uint32_t va = vbase + (16 * j + lrow) * AROW + lcol;
#pragma unroll
            for (int pp = 0; pp < 2; pp++) {
                uint32_t vh[2][4];
#pragma unroll
                for (int t = 0; t < 2; t++) {
                    uint32_t addr = va + (pp * 2 + t) * 32;
                    LDSM_X4_T(vh[t][0], vh[t][1], vh[t][2], vh[t][3], addr);
                }
                // term ph*vh — 4 independent
#pragma unroll
                for (int t = 0; t < 2; t++) {
                    MMA_F16(O[4*pp+2*t],   ph[j][0], ph[j][1], ph[j][2], ph[j][3],
                            vh[t][0], vh[t][1]);
                    MMA_F16(O[4*pp+2*t+1], ph[j][0], ph[j][1], ph[j][2], ph[j][3],
                            vh[t][2], vh[t][3]);
                }
                // term pl*vh
#pragma unroll
                for (int t = 0; t < 2; t++) {
                    MMA_F16(O[4*pp+2*t],   pl[j][0], pl[j][1], pl[j][2], pl[j][3],
                            vh[t][0], vh[t][1]);
                    MMA_F16(O[4*pp+2*t+1], pl[j][0], pl[j][1], pl[j][2], pl[j][3],
                            vh[t][2], vh[t][3]);
                }
            }
        }
        __syncthreads();
    }

    // ---- epilogue: normalize, split to fp16 hi/lo, write [b, l, c] ----
    const float inv0 = 1.0f / ls0, inv1 = 1.0f / ls1;
    const int row0 = qt * 128 + w * 16 + q4;
    const size_t o0 = ((size_t)b * LL + row0) * CC + h * HD;
    const size_t o1 = o0 + 8 * CC;
#pragma unroll
    for (int nt = 0; nt < 8; nt++) {
        int cc = nt * 8 + 2 * l3;
        uint32_t hw, lw;
        split2h(O[nt][0] * inv0, O[nt][1] * inv0, hw, lw);
        *(uint32_t*)(g_aoh + o0 + cc) = hw;
        *(uint32_t*)(g_aol + o0 + cc) = lw;
        split2h(O[nt][2] * inv1, O[nt][3] * inv1, hw, lw);
        *(uint32_t*)(g_aoh + o1 + cc) = hw;
        *(uint32_t*)(g_aol + o1 + cc) = lw;
    }
}

// ---------------------------------------------------------------------------
extern "C" void kernel_launch(void* const* d_in, const int* in_sizes, int n_in,
                              void* d_out, int out_size)
{
    const float* x      = (const float*)d_in[0];
    const float* w_qkv  = (const float*)d_in[1];
    const float* qgam   = (const float*)d_in[2];
    const float* kgam   = (const float*)d_in[3];
    const float* w_out  = (const float*)d_in[4];
    float* out = (float*)d_out;

    float* qkv; cudaGetSymbolAddress((void**)&qkv, g_qkv);
    __half *xh, *xl, *wqh, *woh, *aoh, *aol;
    cudaGetSymbolAddress((void**)&xh, g_xh);   cudaGetSymbolAddress((void**)&xl, g_xl);
    cudaGetSymbolAddress((void**)&wqh, g_wqh);
    cudaGetSymbolAddress((void**)&woh, g_woh);
    cudaGetSymbolAddress((void**)&aoh, g_aoh); cudaGetSymbolAddress((void**)&aol, g_aol);

    cudaFuncSetAttribute(gemm_2t_kernel,
                         cudaFuncAttributeMaxDynamicSharedMemorySize, 2 * GSTG);
    cudaFuncSetAttribute(attn_mma_kernel,
                         cudaFuncAttributeMaxDynamicSharedMemorySize, 2 * ASTG);

    // 0) prepare operands: x -> hi/lo, weights -> hi only
    split_kernel<<<(M_TOT * CC / 4 + 255) / 256, 256>>>(x, xh, xl, M_TOT * CC / 4);
    cvt_kernel<<<(NQKV * CC / 4 + 255) / 256, 256>>>(w_qkv, wqh, NQKV * CC / 4);
    cvt_kernel<<<(CC * CC / 4 + 255) / 256, 256>>>(w_out, woh, CC * CC / 4);

    // 1) QKV projection (fp16x2)
    gemm_2t_kernel<<<dim3(NQKV / 128, M_TOT / 128), 256, 2 * GSTG>>>(
        xh, xl, wqh, qkv, M_TOT, NQKV, CC);

    // 2) RMSNorm + RoPE + fp16 split
    qkv_post_kernel<<<(BB * LL * NH) / 8, 256>>>(qgam, kgam);

    // 3) Flash attention (fp16x2)
    attn_mma_kernel<<<dim3(LL / 128, NH, BB), 256, 2 * ASTG>>>();

    // 4) Output projection (fp16x2)
    gemm_2t_kernel<<<dim3(CC / 128, M_TOT / 128), 256, 2 * GSTG>>>(
        aoh, aol, woh, out, M_TOT, CC, CC);
}

// round 9
// speedup vs baseline: 3.7192x; 1.0234x over previous
#include <cuda_runtime.h>
#include <cuda_fp16.h>
#include <cstdint>
#include <math.h>

#define BB 8
#define LL 1024
#define CC 768
#define NH 12
#define HD 64
#define M_TOT (BB*LL)      /* 8192 */
#define NQKV (3*CC)        /* 2304 */

// ---------------- scratch (device globals: no allocation allowed) ----------
__device__ float g_qkv[(size_t)M_TOT * NQKV];
__device__ __half g_xh[(size_t)M_TOT * CC],  g_xl[(size_t)M_TOT * CC];
__device__ __half g_wqh[(size_t)NQKV * CC];
__device__ __half g_woh[(size_t)CC * CC];
__device__ __half g_aoh[(size_t)M_TOT * CC], g_aol[(size_t)M_TOT * CC];
__device__ __half g_qh[(size_t)BB*NH*LL*HD], g_ql[(size_t)BB*NH*LL*HD];
__device__ __half g_kh[(size_t)BB*NH*LL*HD];
__device__ __half g_vh[(size_t)BB*NH*LL*HD];

// ---------------------------------------------------------------------------
__device__ __forceinline__ float ex2f(float x) {
    float y;
    asm("ex2.approx.ftz.f32 %0, %1;" : "=f"(y) : "f"(x));
    return y;
}
__device__ __forceinline__ uint32_t smem_u32(const void* p) {
    uint32_t a;
    asm("{ .reg .u64 t; cvta.to.shared.u64 t, %1; cvt.u32.u64 %0, t; }"
        : "=r"(a) : "l"(p));
    return a;
}
__device__ __forceinline__ void split2h(float a, float b, uint32_t& hi, uint32_t& lo) {
    __half ha = __float2half_rn(a);
    __half hb = __float2half_rn(b);
    float ra = a - __half2float(ha);
    float rb = b - __half2float(hb);
    __half la = __float2half_rn(ra);
    __half lb = __float2half_rn(rb);
    hi = ((uint32_t)*(uint16_t*)&hb << 16) | (uint32_t)*(uint16_t*)&ha;
    lo = ((uint32_t)*(uint16_t*)&lb << 16) | (uint32_t)*(uint16_t*)&la;
}

// fp32-accumulator MMA (hi term)
#define MMA_F16(Cr, A0, A1, A2, A3, B0, B1) \
    asm volatile("mma.sync.aligned.m16n8k16.row.col.f32.f16.f16.f32 " \
        "{%0,%1,%2,%3}, {%4,%5,%6,%7}, {%8,%9}, {%0,%1,%2,%3};" \
        : "+f"((Cr)[0]), "+f"((Cr)[1]), "+f"((Cr)[2]), "+f"((Cr)[3]) \
        : "r"(A0), "r"(A1), "r"(A2), "r"(A3), "r"(B0), "r"(B1))

// fp16-accumulator MMA (lo term) — D/C are 2 packed b16x2 regs
#define MMA_F16ACC(C0, C1, A0, A1, A2, A3, B0, B1) \
    asm volatile("mma.sync.aligned.m16n8k16.row.col.f16.f16.f16.f16 " \
        "{%0,%1}, {%2,%3,%4,%5}, {%6,%7}, {%0,%1};" \
        : "+r"(C0), "+r"(C1) \
        : "r"(A0), "r"(A1), "r"(A2), "r"(A3), "r"(B0), "r"(B1))

#define LDSM_X4(r0, r1, r2, r3, addr) \
    asm volatile("ldmatrix.sync.aligned.m8n8.x4.shared.b16 {%0,%1,%2,%3}, [%4];" \
        : "=r"(r0), "=r"(r1), "=r"(r2), "=r"(r3) : "r"(addr))

#define LDSM_X4_T(r0, r1, r2, r3, addr) \
    asm volatile("ldmatrix.sync.aligned.m8n8.x4.trans.shared.b16 {%0,%1,%2,%3}, [%4];" \
        : "=r"(r0), "=r"(r1), "=r"(r2), "=r"(r3) : "r"(addr))

#define CP_ASYNC16(dst, src) \
    asm volatile("cp.async.cg.shared.global [%0], [%1], 16;" \
                 :: "r"(dst), "l"(src) : "memory")
#define CP_COMMIT() asm volatile("cp.async.commit_group;" ::: "memory")
#define CP_WAIT0()  asm volatile("cp.async.wait_group 0;" ::: "memory")
#define CP_WAIT1()  asm volatile("cp.async.wait_group 1;" ::: "memory")

// ===========================================================================
// prep kernels
// ===========================================================================
__global__ __launch_bounds__(256) void split_kernel(
    const float* __restrict__ src, __half* __restrict__ h,
    __half* __restrict__ l, int n4)
{
    int i = blockIdx.x * 256 + threadIdx.x;
    if (i < n4) {
        float4 v = ((const float4*)src)[i];
        uint32_t h0, l0, h1, l1;
        split2h(v.x, v.y, h0, l0);
        split2h(v.z, v.w, h1, l1);
        ((uint2*)h)[i] = make_uint2(h0, h1);
        ((uint2*)l)[i] = make_uint2(l0, l1);
    }
}
__global__ __launch_bounds__(256) void cvt_kernel(
    const float* __restrict__ src, __half* __restrict__ h, int n4)
{
    int i = blockIdx.x * 256 + threadIdx.x;
    if (i < n4) {
        float4 v = ((const float4*)src)[i];
        ((__half2*)h)[2*i]   = __floats2half2_rn(v.x, v.y);
        ((__half2*)h)[2*i+1] = __floats2half2_rn(v.z, v.w);
    }
}

// ===========================================================================
// Pipelined fp16x2 GEMM (NT): C = Ah*Bh^T (fp32 acc) + Al*Bh^T (fp16 acc).
// BM=BN=128, BK=32, 256 thr = 8 warps (2x4), warp tile 64x32.
// Stage (30720B): Ah@0 Al@10240 Bh@20480, 128 rows x 80B.
// ===========================================================================
#define GSTG 30720

__global__ __launch_bounds__(256) void gemm_2t_kernel(
    const __half* __restrict__ Ah, const __half* __restrict__ Al,
    const __half* __restrict__ Bh,
    float* __restrict__ C, int M, int N, int K)
{
    extern __shared__ uint8_t smraw[];
    const uint32_t sbase = smem_u32(smraw);

    const int tid  = threadIdx.x;
    const int wid  = tid >> 5;
    const int lane = tid & 31;
    const int wm = wid & 1;
    const int wn = wid >> 1;
    const int row0 = blockIdx.y * 128;
    const int col0 = blockIdx.x * 128;
    const int q4 = lane >> 2;
    const int l3 = lane & 3;
    const int lr16  = lane & 15;
    const int lhalf = (lane >> 4) * 16;

    float c[4][4][4];
    uint32_t cl[4][4][2];
#pragma unroll
    for (int m = 0; m < 4; m++)
#pragma unroll
        for (int n = 0; n < 4; n++) {
#pragma unroll
            for (int q = 0; q < 4; q++) c[m][n][q] = 0.f;
            cl[m][n][0] = 0u; cl[m][n][1] = 0u;
        }

    const int nch = K / 32;

    {
        uint32_t dst = sbase;
#pragma unroll
        for (int j = 0; j < 6; j++) {
            int i = tid + 256 * j;
            int a = i >> 9, r = (i >> 2) & 127, cc = i & 3;
            const __half* base = (a == 0) ? Ah : (a == 1) ? Al : Bh;
            int grow = ((a < 2) ? row0 : col0) + r;
            CP_ASYNC16(dst + a * 10240 + r * 80 + cc * 16,
                       base + (size_t)grow * K + cc * 8);
        }
        CP_COMMIT();
    }

#pragma unroll 1
    for (int ch = 0; ch < nch; ch++) {
        if (ch + 1 < nch) {
            uint32_t dst = sbase + ((ch + 1) & 1) * GSTG;
            const int k0 = (ch + 1) * 32;
#pragma unroll
            for (int j = 0; j < 6; j++) {
                int i = tid + 256 * j;
                int a = i >> 9, r = (i >> 2) & 127, cc = i & 3;
                const __half* base = (a == 0) ? Ah : (a == 1) ? Al : Bh;
                int grow = ((a < 2) ? row0 : col0) + r;
                CP_ASYNC16(dst + a * 10240 + r * 80 + cc * 16,
                           base + (size_t)grow * K + k0 + cc * 8);
            }
            CP_COMMIT();
            CP_WAIT1();
        } else {
            CP_WAIT0();
        }
        __syncthreads();

        const uint32_t sst = sbase + (ch & 1) * GSTG;

#pragma unroll
        for (int ks = 0; ks < 2; ks++) {
            uint32_t ah[4][4], al[4][4];
#pragma unroll
            for (int m = 0; m < 4; m++) {
                uint32_t arow = sst + (wm * 64 + m * 16 + lr16) * 80 + lhalf + ks * 32;
                LDSM_X4(ah[m][0], ah[m][1], ah[m][2], ah[m][3], arow);
                LDSM_X4(al[m][0], al[m][1], al[m][2], al[m][3], arow + 10240);
            }
#pragma unroll
            for (int np = 0; np < 2; np++) {
                uint32_t brow = sst + 20480 + (wn * 32 + np * 16 + lr16) * 80 + lhalf + ks * 32;
                uint32_t h0, h1, h2, h3;
                LDSM_X4(h0, h1, h2, h3, brow);
                // hi term: fp32 accumulators
#pragma unroll
                for (int m = 0; m < 4; m++)
                    MMA_F16(c[m][2*np],   ah[m][0], ah[m][1], ah[m][2], ah[m][3], h0, h2);
#pragma unroll
                for (int m = 0; m < 4; m++)
                    MMA_F16(c[m][2*np+1], ah[m][0], ah[m][1], ah[m][2], ah[m][3], h1, h3);
                // lo term: fp16 accumulators
#pragma unroll
                for (int m = 0; m < 4; m++)
                    MMA_F16ACC(cl[m][2*np][0],   cl[m][2*np][1],
                               al[m][0], al[m][1], al[m][2], al[m][3], h0, h2);
#pragma unroll
                for (int m = 0; m < 4; m++)
                    MMA_F16ACC(cl[m][2*np+1][0], cl[m][2*np+1][1],
                               al[m][0], al[m][1], al[m][2], al[m][3], h1, h3);
            }
        }
        __syncthreads();
    }

#pragma unroll
    for (int m = 0; m < 4; m++) {
        const int r = row0 + wm * 64 + m * 16 + q4;
#pragma unroll
        for (int n = 0; n < 4; n++) {
            float2 lo0 = __half22float2(*(__half2*)&cl[m][n][0]);
            float2 lo1 = __half22float2(*(__half2*)&cl[m][n][1]);
            const int cc = col0 + wn * 32 + n * 8 + l3 * 2;
            *(float2*)(C + (size_t)r * N + cc) =
                make_float2(c[m][n][0] + lo0.x, c[m][n][1] + lo0.y);
            *(float2*)(C + (size_t)(r + 8) * N + cc) =
                make_float2(c[m][n][2] + lo1.x, c[m][n][3] + lo1.y);
        }
    }
}

// ---------------------------------------------------------------------------
// QKV epilogue: RMSNorm + RoPE; q -> fp16 hi/lo, k/v -> fp16 hi. [b,h,l,e].
// ---------------------------------------------------------------------------
__global__ __launch_bounds__(256) void qkv_post_kernel(
    const float* __restrict__ qg, const float* __restrict__ kg)
{
    const int widx = blockIdx.x * 8 + (threadIdx.x >> 5);
    const int lane = threadIdx.x & 31;
    const int h = widx % NH;
    const int l = (widx / NH) % LL;
    const int b = widx / (NH * LL);

    const float* rowp = g_qkv + (size_t)(b * LL + l) * NQKV + h * HD;
    const float ifr = exp2f(-13.287712379549449f * (float)lane * (1.0f / 32.0f));
    const float ang = (float)l * ifr;
    const float cs = cosf(ang), sn = sinf(ang);
    const size_t dsto = ((size_t)(b * NH + h) * LL + l) * HD;
    const float QS = 0.125f * 1.4426950408889634f;

    {
        float x1 = rowp[lane], x2 = rowp[lane + 32];
        float ss = x1 * x1 + x2 * x2;
#pragma unroll
        for (int o = 16; o; o >>= 1) ss += __shfl_xor_sync(0xffffffffu, ss, o);
        float r = rsqrtf(ss * (1.0f / HD) + 1e-6f);
        float n1 = x1 * r * qg[lane], n2 = x2 * r * qg[lane + 32];
        float v1 = (n1 * cs - n2 * sn) * QS;
        float v2 = (n1 * sn + n2 * cs) * QS;
        __half h1 = __float2half_rn(v1), h2 = __float2half_rn(v2);
        g_qh[dsto + lane]      = h1;
        g_qh[dsto + lane + 32] = h2;
        g_ql[dsto + lane]      = __float2half_rn(v1 - __half2float(h1));
        g_ql[dsto + lane + 32] = __float2half_rn(v2 - __half2float(h2));
    }
    {
        float x1 = rowp[CC + lane], x2 = rowp[CC + lane + 32];
        float ss = x1 * x1 + x2 * x2;
#pragma unroll
        for (int o = 16; o; o >>= 1) ss += __shfl_xor_sync(0xffffffffu, ss, o);
        float r = rsqrtf(ss * (1.0f / HD) + 1e-6f);
        float n1 = x1 * r * kg[lane], n2 = x2 * r * kg[lane + 32];
        g_kh[dsto + lane]      = __float2half_rn(n1 * cs - n2 * sn);
        g_kh[dsto + lane + 32] = __float2half_rn(n1 * sn + n2 * cs);
    }
    g_vh[dsto + lane]      = __float2half_rn(rowp[2 * CC + lane]);
    g_vh[dsto + lane + 32] = __float2half_rn(rowp[2 * CC + lane + 32]);
}

// ===========================================================================
// Flash attention fp16x2, lo terms in fp16 accumulators.
// ===========================================================================
#define ASTG  18432
#define AROW  144
#define AROWW 36

__global__ __launch_bounds__(256) void attn_mma_kernel()
{
    extern __shared__ uint8_t smraw[];
    uint32_t* smw = (uint32_t*)smraw;
    const uint32_t sbase = smem_u32(smraw);

    const int tid  = threadIdx.x;
    const int w    = tid >> 5;
    const int lane = tid & 31;
    const int q4   = lane >> 2;
    const int l3   = lane & 3;
    const int qt = blockIdx.x, h = blockIdx.y, b = blockIdx.z;

    const size_t hb = (size_t)(b * NH + h) * LL * HD;
    const __half* Qh = g_qh + hb + (size_t)qt * 128 * HD;
    const __half* Ql = g_ql + hb + (size_t)qt * 128 * HD;
    const __half* Kh = g_kh + hb;
    const __half* Vh = g_vh + hb;

#pragma unroll
    for (int t = 0; t < 8; t++) {
        int i = tid + 256 * t;
        int a = i >> 10, r = (i >> 3) & 127, c = i & 7;
        const __half* src = (a ? Ql : Qh) + (size_t)r * HD + c * 8;
        CP_ASYNC16(sbase + a * 18432 + r * AROW + c * 16, src);
    }
    CP_COMMIT(); CP_WAIT0();
    __syncthreads();

    uint32_t qhf[4][4], qlf[4][4];
#pragma unroll
    for (int ks = 0; ks < 4; ks++) {
        int base = (w * 16 + q4) * AROWW + ks * 8 + l3;
        qhf[ks][0] = smw[base];                qhf[ks][1] = smw[base + 8 * AROWW];
        qhf[ks][2] = smw[base + 4];            qhf[ks][3] = smw[base + 8 * AROWW + 4];
        qlf[ks][0] = smw[4608 + base];         qlf[ks][1] = smw[4608 + base + 8 * AROWW];
        qlf[ks][2] = smw[4608 + base + 4];     qlf[ks][3] = smw[4608 + base + 8 * AROWW + 4];
    }
    __syncthreads();

    float m0 = -1e30f, m1 = -1e30f, ls0 = 0.f, ls1 = 0.f;
    float O[8][4];
    uint32_t Ol[8][2];
#pragma unroll
    for (int n = 0; n < 8; n++) {
#pragma unroll
        for (int q = 0; q < 4; q++) O[n][q] = 0.f;
        Ol[n][0] = 0u; Ol[n][1] = 0u;
    }

#pragma unroll
    for (int t = 0; t < 4; t++) {
        int i = tid + 256 * t;
        int a = i >> 9, r = (i >> 3) & 63, c = i & 7;
        const __half* base = (a == 0) ? Kh : Vh;
        CP_ASYNC16(sbase + a * 9216 + r * AROW + c * 16,
                   base + (size_t)r * HD + c * 8);
    }
    CP_COMMIT();

#pragma unroll 1
    for (int kt = 0; kt < 16; kt++) {
        if (kt < 15) {
            uint32_t dst = sbase + ((kt + 1) & 1) * ASTG;
            const int r0 = (kt + 1) * 64;
#pragma unroll
            for (int t = 0; t < 4; t++) {
                int i = tid + 256 * t;
                int a = i >> 9, r = (i >> 3) & 63, c = i & 7;
                const __half* base = (a == 0) ? Kh : Vh;
                CP_ASYNC16(dst + a * 9216 + r * AROW + c * 16,
                           base + (size_t)(r0 + r) * HD + c * 8);
            }
            CP_COMMIT();
            CP_WAIT1();
        } else {
            CP_WAIT0();
        }
        __syncthreads();

        const uint32_t* KW = smw + (kt & 1) * (ASTG / 4);
        const uint32_t vbase = sbase + (kt & 1) * ASTG + 9216;

        // ---- S = Q K^T: hi in fp32 acc, lo in fp16 acc ----
        float S[8][4];
        uint32_t Sl[8][2];
#pragma unroll
        for (int n = 0; n < 8; n++) {
#pragma unroll
            for (int q = 0; q < 4; q++) S[n][q] = 0.f;
            Sl[n][0] = 0u; Sl[n][1] = 0u;
        }

#pragma unroll
        for (int ks = 0; ks < 4; ks++) {
#pragma unroll
            for (int g = 0; g < 2; g++) {
                uint32_t bh[4][2];
#pragma unroll
                for (int j = 0; j < 4; j++) {
                    int kb = ((g * 4 + j) * 8 + q4) * AROWW + ks * 8 + l3;
                    bh[j][0] = KW[kb];  bh[j][1] = KW[kb + 4];
                }
#pragma unroll
                for (int j = 0; j < 4; j++)
                    MMA_F16(S[g*4+j], qhf[ks][0], qhf[ks][1], qhf[ks][2], qhf[ks][3],
                            bh[j][0], bh[j][1]);
#pragma unroll
                for (int j = 0; j < 4; j++)
                    MMA_F16ACC(Sl[g*4+j][0], Sl[g*4+j][1],
                               qlf[ks][0], qlf[ks][1], qlf[ks][2], qlf[ks][3],
                               bh[j][0], bh[j][1]);
            }
        }
        // promote lo into fp32 S
#pragma unroll
        for (int nt = 0; nt < 8; nt++) {
            float2 lo0 = __half22float2(*(__half2*)&Sl[nt][0]);
            float2 lo1 = __half22float2(*(__half2*)&Sl[nt][1]);
            S[nt][0] += lo0.x; S[nt][1] += lo0.y;
            S[nt][2] += lo1.x; S[nt][3] += lo1.y;
        }

        // ---- online softmax (log2 domain) ----
        float mx0 = -1e30f, mx1 = -1e30f;
#pragma unroll
        for (int nt = 0; nt < 8; nt++) {
            mx0 = fmaxf(mx0, fmaxf(S[nt][0], S[nt][1]));
            mx1 = fmaxf(mx1, fmaxf(S[nt][2], S[nt][3]));
        }
        mx0 = fmaxf(mx0, __shfl_xor_sync(0xffffffffu, mx0, 1));
        mx0 = fmaxf(mx0, __shfl_xor_sync(0xffffffffu, mx0, 2));
        mx1 = fmaxf(mx1, __shfl_xor_sync(0xffffffffu, mx1, 1));
        mx1 = fmaxf(mx1, __shfl_xor_sync(0xffffffffu, mx1, 2));
        float mn0 = fmaxf(m0, mx0), mn1 = fmaxf(m1, mx1);
        float a0 = ex2f(m0 - mn0), a1 = ex2f(m1 - mn1);
        float rs0 = 0.f, rs1 = 0.f;
#pragma unroll
        for (int nt = 0; nt < 8; nt++) {
            S[nt][0] = ex2f(S[nt][0] - mn0); S[nt][1] = ex2f(S[nt][1] - mn0);
            S[nt][2] = ex2f(S[nt][2] - mn1); S[nt][3] = ex2f(S[nt][3] - mn1);
            rs0 += S[nt][0] + S[nt][1];
            rs1 += S[nt][2] + S[nt][3];
        }
        rs0 += __shfl_xor_sync(0xffffffffu, rs0, 1);
        rs0 += __shfl_xor_sync(0xffffffffu, rs0, 2);
        rs1 += __shfl_xor_sync(0xffffffffu, rs1, 1);
        rs1 += __shfl_xor_sync(0xffffffffu, rs1, 2);
        ls0 = ls0 * a0 + rs0;  ls1 = ls1 * a1 + rs1;
        m0 = mn0;  m1 = mn1;
        __half2 a0h = __float2half2_rn(a0);
        __half2 a1h = __float2half2_rn(a1);
#pragma unroll
        for (int nt = 0; nt < 8; nt++) {
            O[nt][0] *= a0; O[nt][1] *= a0;
            O[nt][2] *= a1; O[nt][3] *= a1;
            *(__half2*)&Ol[nt][0] = __hmul2(*(__half2*)&Ol[nt][0], a0h);
            *(__half2*)&Ol[nt][1] = __hmul2(*(__half2*)&Ol[nt][1], a1h);
        }

        // ---- pack P fragments (fp16 hi/lo) ----
        uint32_t ph[4][4], pl[4][4];
#pragma unroll
        for (int j = 0; j < 4; j++) {
            split2h(S[2*j][0],   S[2*j][1],   ph[j][0], pl[j][0]);
            split2h(S[2*j][2],   S[2*j][3],   ph[j][1], pl[j][1]);
            split2h(S[2*j+1][0], S[2*j+1][1], ph[j][2], pl[j][2]);
            split2h(S[2*j+1][2], S[2*j+1][3], ph[j][3], pl[j][3]);
        }

        // ---- O += P V: hi in fp32 acc, lo in fp16 acc ----
        const uint32_t lrow = (lane & 15);
        const uint32_t lcol = ((lane >> 4) & 1) * 16;
#pragma unroll
        for (int j = 0; j < 4; j++) {
            uint32_t va = vbase + (16 * j + lrow) * AROW + lcol;
#pragma unroll
            for (int pp = 0; pp < 2; pp++) {
                uint32_t vh[2][4];
#pragma unroll
                for (int t = 0; t < 2; t++) {
                    uint32_t addr = va + (pp * 2 + t) * 32;
                    LDSM_X4_T(vh[t][0], vh[t][1], vh[t][2], vh[t][3], addr);
                }
#pragma unroll
                for (int t = 0; t < 2; t++) {
                    MMA_F16(O[4*pp+2*t],   ph[j][0], ph[j][1], ph[j][2], ph[j][3],
                            vh[t][0], vh[t][1]);
                    MMA_F16(O[4*pp+2*t+1], ph[j][0], ph[j][1], ph[j][2], ph[j][3],
                            vh[t][2], vh[t][3]);
                }
#pragma unroll
                for (int t = 0; t < 2; t++) {
                    MMA_F16ACC(Ol[4*pp+2*t][0],   Ol[4*pp+2*t][1],
                               pl[j][0], pl[j][1], pl[j][2], pl[j][3],
                               vh[t][0], vh[t][1]);
                    MMA_F16ACC(Ol[4*pp+2*t+1][0], Ol[4*pp+2*t+1][1],
                               pl[j][0], pl[j][1], pl[j][2], pl[j][3],
                               vh[t][2], vh[t][3]);
                }
            }
        }
        __syncthreads();
    }

    // ---- epilogue: promote lo, normalize, split, write [b, l, c] ----
    const float inv0 = 1.0f / ls0, inv1 = 1.0f / ls1;
    const int row0 = qt * 128 + w * 16 + q4;
    const size_t o0 = ((size_t)b * LL + row0) * CC + h * HD;
    const size_t o1 = o0 + 8 * CC;
#pragma unroll
    for (int nt = 0; nt < 8; nt++) {
        float2 lo0 = __half22float2(*(__half2*)&Ol[nt][0]);
        float2 lo1 = __half22float2(*(__half2*)&Ol[nt][1]);
        int cc = nt * 8 + 2 * l3;
        uint32_t hw, lw;
        split2h((O[nt][0] + lo0.x) * inv0, (O[nt][1] + lo0.y) * inv0, hw, lw);
        *(uint32_t*)(g_aoh + o0 + cc) = hw;
        *(uint32_t*)(g_aol + o0 + cc) = lw;
        split2h((O[nt][2] + lo1.x) * inv1, (O[nt][3] + lo1.y) * inv1, hw, lw);
        *(uint32_t*)(g_aoh + o1 + cc) = hw;
        *(uint32_t*)(g_aol + o1 + cc) = lw;
    }
}

// ---------------------------------------------------------------------------
extern "C" void kernel_launch(void* const* d_in, const int* in_sizes, int n_in,
                              void* d_out, int out_size)
{
    const float* x      = (const float*)d_in[0];
    const float* w_qkv  = (const float*)d_in[1];
    const float* qgam   = (const float*)d_in[2];
    const float* kgam   = (const float*)d_in[3];
    const float* w_out  = (const float*)d_in[4];
    float* out = (float*)d_out;

    float* qkv; cudaGetSymbolAddress((void**)&qkv, g_qkv);
    __half *xh, *xl, *wqh, *woh, *aoh, *aol;
    cudaGetSymbolAddress((void**)&xh, g_xh);   cudaGetSymbolAddress((void**)&xl, g_xl);
    cudaGetSymbolAddress((void**)&wqh, g_wqh);
    cudaGetSymbolAddress((void**)&woh, g_woh);
    cudaGetSymbolAddress((void**)&aoh, g_aoh); cudaGetSymbolAddress((void**)&aol, g_aol);

    cudaFuncSetAttribute(gemm_2t_kernel,
                         cudaFuncAttributeMaxDynamicSharedMemorySize, 2 * GSTG);
    cudaFuncSetAttribute(attn_mma_kernel,
                         cudaFuncAttributeMaxDynamicSharedMemorySize, 2 * ASTG);

    // 0) prepare operands
    split_kernel<<<(M_TOT * CC / 4 + 255) / 256, 256>>>(x, xh, xl, M_TOT * CC / 4);
    cvt_kernel<<<(NQKV * CC / 4 + 255) / 256, 256>>>(w_qkv, wqh, NQKV * CC / 4);
    cvt_kernel<<<(CC * CC / 4 + 255) / 256, 256>>>(w_out, woh, CC * CC / 4);

    // 1) QKV projection
    gemm_2t_kernel<<<dim3(NQKV / 128, M_TOT / 128), 256, 2 * GSTG>>>(
        xh, xl, wqh, qkv, M_TOT, NQKV, CC);

    // 2) RMSNorm + RoPE + fp16 split
    qkv_post_kernel<<<(BB * LL * NH) / 8, 256>>>(qgam, kgam);

    // 3) Flash attention
    attn_mma_kernel<<<dim3(LL / 128, NH, BB), 256, 2 * ASTG>>>();

    // 4) Output projection
    gemm_2t_kernel<<<dim3(CC / 128, M_TOT / 128), 256, 2 * GSTG>>>(
        aoh, aol, woh, out, M_TOT, CC, CC);
}

// round 10
// speedup vs baseline: 3.9199x; 1.0540x over previous
#include <cuda_runtime.h>
#include <cuda_fp16.h>
#include <cstdint>
#include <math.h>

#define BB 8
#define LL 1024
#define CC 768
#define NH 12
#define HD 64
#define M_TOT (BB*LL)      /* 8192 */
#define NQKV (3*CC)        /* 2304 */

// ---------------- scratch (device globals: no allocation allowed) ----------
__device__ float g_qkv[(size_t)M_TOT * NQKV];
__device__ __half g_xh[(size_t)M_TOT * CC],  g_xl[(size_t)M_TOT * CC];
__device__ __half g_wqh[(size_t)NQKV * CC];
__device__ __half g_woh[(size_t)CC * CC];
__device__ __half g_aoh[(size_t)M_TOT * CC], g_aol[(size_t)M_TOT * CC];
__device__ __half g_qh[(size_t)BB*NH*LL*HD], g_ql[(size_t)BB*NH*LL*HD];
__device__ __half g_kh[(size_t)BB*NH*LL*HD];
__device__ __half g_vh[(size_t)BB*NH*LL*HD];

// ---------------------------------------------------------------------------
__device__ __forceinline__ float ex2f(float x) {
    float y;
    asm("ex2.approx.ftz.f32 %0, %1;" : "=f"(y) : "f"(x));
    return y;
}
__device__ __forceinline__ uint32_t smem_u32(const void* p) {
    uint32_t a;
    asm("{ .reg .u64 t; cvta.to.shared.u64 t, %1; cvt.u32.u64 %0, t; }"
        : "=r"(a) : "l"(p));
    return a;
}
__device__ __forceinline__ void split2h(float a, float b, uint32_t& hi, uint32_t& lo) {
    __half ha = __float2half_rn(a);
    __half hb = __float2half_rn(b);
    float ra = a - __half2float(ha);
    float rb = b - __half2float(hb);
    __half la = __float2half_rn(ra);
    __half lb = __float2half_rn(rb);
    hi = ((uint32_t)*(uint16_t*)&hb << 16) | (uint32_t)*(uint16_t*)&ha;
    lo = ((uint32_t)*(uint16_t*)&lb << 16) | (uint32_t)*(uint16_t*)&la;
}

#define MMA_F16(Cr, A0, A1, A2, A3, B0, B1) \
    asm volatile("mma.sync.aligned.m16n8k16.row.col.f32.f16.f16.f32 " \
        "{%0,%1,%2,%3}, {%4,%5,%6,%7}, {%8,%9}, {%0,%1,%2,%3};" \
        : "+f"((Cr)[0]), "+f"((Cr)[1]), "+f"((Cr)[2]), "+f"((Cr)[3]) \
        : "r"(A0), "r"(A1), "r"(A2), "r"(A3), "r"(B0), "r"(B1))

#define LDSM_X4(r0, r1, r2, r3, addr) \
    asm volatile("ldmatrix.sync.aligned.m8n8.x4.shared.b16 {%0,%1,%2,%3}, [%4];" \
        : "=r"(r0), "=r"(r1), "=r"(r2), "=r"(r3) : "r"(addr))

#define LDSM_X4_T(r0, r1, r2, r3, addr) \
    asm volatile("ldmatrix.sync.aligned.m8n8.x4.trans.shared.b16 {%0,%1,%2,%3}, [%4];" \
        : "=r"(r0), "=r"(r1), "=r"(r2), "=r"(r3) : "r"(addr))

#define CP_ASYNC16(dst, src) \
    asm volatile("cp.async.cg.shared.global [%0], [%1], 16;" \
                 :: "r"(dst), "l"(src) : "memory")
#define CP_COMMIT() asm volatile("cp.async.commit_group;" ::: "memory")
#define CP_WAIT0()  asm volatile("cp.async.wait_group 0;" ::: "memory")
#define CP_WAIT1()  asm volatile("cp.async.wait_group 1;" ::: "memory")

// ===========================================================================
// prep kernels
// ===========================================================================
__global__ __launch_bounds__(256) void split_kernel(
    const float* __restrict__ src, __half* __restrict__ h,
    __half* __restrict__ l, int n4)
{
    int i = blockIdx.x * 256 + threadIdx.x;
    if (i < n4) {
        float4 v = ((const float4*)src)[i];
        uint32_t h0, l0, h1, l1;
        split2h(v.x, v.y, h0, l0);
        split2h(v.z, v.w, h1, l1);
        ((uint2*)h)[i] = make_uint2(h0, h1);
        ((uint2*)l)[i] = make_uint2(l0, l1);
    }
}
__global__ __launch_bounds__(256) void cvt_kernel(
    const float* __restrict__ src, __half* __restrict__ h, int n4)
{
    int i = blockIdx.x * 256 + threadIdx.x;
    if (i < n4) {
        float4 v = ((const float4*)src)[i];
        ((__half2*)h)[2*i]   = __floats2half2_rn(v.x, v.y);
        ((__half2*)h)[2*i+1] = __floats2half2_rn(v.z, v.w);
    }
}

// ===========================================================================
// Pipelined fp16 GEMM (NT): C = Ah*Bh^T (+ Al*Bh^T for cols < n_two).
// BM=BN=128, BK=32, 256 thr = 8 warps (2x4), warp tile 64x32.
// Stage (30720B): Ah@0 Al@10240 Bh@20480, 128 rows x 80B.
// CTAs with col0 >= n_two run single-term (skip Al loads + lo MMAs).
// ===========================================================================
#define GSTG 30720

__global__ __launch_bounds__(256) void gemm_2t_kernel(
    const __half* __restrict__ Ah, const __half* __restrict__ Al,
    const __half* __restrict__ Bh,
    float* __restrict__ C, int M, int N, int K, int n_two)
{
    extern __shared__ uint8_t smraw[];
    const uint32_t sbase = smem_u32(smraw);

    const int tid  = threadIdx.x;
    const int wid  = tid >> 5;
    const int lane = tid & 31;
    const int wm = wid & 1;
    const int wn = wid >> 1;
    const int row0 = blockIdx.y * 128;
    const int col0 = blockIdx.x * 128;
    const int q4 = lane >> 2;
    const int l3 = lane & 3;
    const int lr16  = lane & 15;
    const int lhalf = (lane >> 4) * 16;
    const bool two_term = (col0 < n_two);

    float c[4][4][4];
#pragma unroll
    for (int m = 0; m < 4; m++)
#pragma unroll
        for (int n = 0; n < 4; n++)
#pragma unroll
            for (int q = 0; q < 4; q++) c[m][n][q] = 0.f;

    const int nch = K / 32;

    {
        uint32_t dst = sbase;
#pragma unroll
        for (int j = 0; j < 6; j++) {
            int i = tid + 256 * j;
            int a = i >> 9, r = (i >> 2) & 127, cc = i & 3;
            if (a == 1 && !two_term) continue;
            const __half* base = (a == 0) ? Ah : (a == 1) ? Al : Bh;
            int grow = ((a < 2) ? row0 : col0) + r;
            CP_ASYNC16(dst + a * 10240 + r * 80 + cc * 16,
                       base + (size_t)grow * K + cc * 8);
        }
        CP_COMMIT();
    }

#pragma unroll 1
    for (int ch = 0; ch < nch; ch++) {
        if (ch + 1 < nch) {
            uint32_t dst = sbase + ((ch + 1) & 1) * GSTG;
            const int k0 = (ch + 1) * 32;
#pragma unroll
            for (int j = 0; j < 6; j++) {
                int i = tid + 256 * j;
                int a = i >> 9, r = (i >> 2) & 127, cc = i & 3;
                if (a == 1 && !two_term) continue;
                const __half* base = (a == 0) ? Ah : (a == 1) ? Al : Bh;
                int grow = ((a < 2) ? row0 : col0) + r;
                CP_ASYNC16(dst + a * 10240 + r * 80 + cc * 16,
                           base + (size_t)grow * K + k0 + cc * 8);
            }
            CP_COMMIT();
            CP_WAIT1();
        } else {
            CP_WAIT0();
        }
        __syncthreads();

        const uint32_t sst = sbase + (ch & 1) * GSTG;

#pragma unroll
        for (int ks = 0; ks < 2; ks++) {
            uint32_t ah[4][4], al[4][4];
#pragma unroll
            for (int m = 0; m < 4; m++) {
                uint32_t arow = sst + (wm * 64 + m * 16 + lr16) * 80 + lhalf + ks * 32;
                LDSM_X4(ah[m][0], ah[m][1], ah[m][2], ah[m][3], arow);
                if (two_term)
                    LDSM_X4(al[m][0], al[m][1], al[m][2], al[m][3], arow + 10240);
            }
#pragma unroll
            for (int np = 0; np < 2; np++) {
                uint32_t brow = sst + 20480 + (wn * 32 + np * 16 + lr16) * 80 + lhalf + ks * 32;
                uint32_t h0, h1, h2, h3;
                LDSM_X4(h0, h1, h2, h3, brow);
                // hi term
#pragma unroll
                for (int m = 0; m < 4; m++)
                    MMA_F16(c[m][2*np],   ah[m][0], ah[m][1], ah[m][2], ah[m][3], h0, h2);
#pragma unroll
                for (int m = 0; m < 4; m++)
                    MMA_F16(c[m][2*np+1], ah[m][0], ah[m][1], ah[m][2], ah[m][3], h1, h3);
                // lo term (Q columns only)
                if (two_term) {
#pragma unroll
                    for (int m = 0; m < 4; m++)
                        MMA_F16(c[m][2*np],   al[m][0], al[m][1], al[m][2], al[m][3], h0, h2);
#pragma unroll
                    for (int m = 0; m < 4; m++)
                        MMA_F16(c[m][2*np+1], al[m][0], al[m][1], al[m][2], al[m][3], h1, h3);
                }
            }
        }
        __syncthreads();
    }

#pragma unroll
    for (int m = 0; m < 4; m++) {
        const int r = row0 + wm * 64 + m * 16 + q4;
#pragma unroll
        for (int n = 0; n < 4; n++) {
            const int cc = col0 + wn * 32 + n * 8 + l3 * 2;
            *(float2*)(C + (size_t)r * N + cc)       = make_float2(c[m][n][0], c[m][n][1]);
            *(float2*)(C + (size_t)(r + 8) * N + cc) = make_float2(c[m][n][2], c[m][n][3]);
        }
    }
}

// ---------------------------------------------------------------------------
// QKV epilogue: RMSNorm + RoPE; q -> fp16 hi/lo, k/v -> fp16 hi. [b,h,l,e].
// ---------------------------------------------------------------------------
__global__ __launch_bounds__(256) void qkv_post_kernel(
    const float* __restrict__ qg, const float* __restrict__ kg)
{
    const int widx = blockIdx.x * 8 + (threadIdx.x >> 5);
    const int lane = threadIdx.x & 31;
    const int h = widx % NH;
    const int l = (widx / NH) % LL;
    const int b = widx / (NH * LL);

    const float* rowp = g_qkv + (size_t)(b * LL + l) * NQKV + h * HD;
    const float ifr = exp2f(-13.287712379549449f * (float)lane * (1.0f / 32.0f));
    const float ang = (float)l * ifr;
    const float cs = cosf(ang), sn = sinf(ang);
    const size_t dsto = ((size_t)(b * NH + h) * LL + l) * HD;
    const float QS = 0.125f * 1.4426950408889634f;

    {
        float x1 = rowp[lane], x2 = rowp[lane + 32];
        float ss = x1 * x1 + x2 * x2;
#pragma unroll
        for (int o = 16; o; o >>= 1) ss += __shfl_xor_sync(0xffffffffu, ss, o);
        float r = rsqrtf(ss * (1.0f / HD) + 1e-6f);
        float n1 = x1 * r * qg[lane], n2 = x2 * r * qg[lane + 32];
        float v1 = (n1 * cs - n2 * sn) * QS;
        float v2 = (n1 * sn + n2 * cs) * QS;
        __half h1 = __float2half_rn(v1), h2 = __float2half_rn(v2);
        g_qh[dsto + lane]      = h1;
        g_qh[dsto + lane + 32] = h2;
        g_ql[dsto + lane]      = __float2half_rn(v1 - __half2float(h1));
        g_ql[dsto + lane + 32] = __float2half_rn(v2 - __half2float(h2));
    }
    {
        float x1 = rowp[CC + lane], x2 = rowp[CC + lane + 32];
        float ss = x1 * x1 + x2 * x2;
#pragma unroll
        for (int o = 16; o; o >>= 1) ss += __shfl_xor_sync(0xffffffffu, ss, o);
        float r = rsqrtf(ss * (1.0f / HD) + 1e-6f);
        float n1 = x1 * r * kg[lane], n2 = x2 * r * kg[lane + 32];
        g_kh[dsto + lane]      = __float2half_rn(n1 * cs - n2 * sn);
        g_kh[dsto + lane + 32] = __float2half_rn(n1 * sn + n2 * cs);
    }
    g_vh[dsto + lane]      = __float2half_rn(rowp[2 * CC + lane]);
    g_vh[dsto + lane + 32] = __float2half_rn(rowp[2 * CC + lane + 32]);
}

// ===========================================================================
// Flash attention fp16x2 (round-9 core, fp32 accumulators for hi, fp32 for lo
// reverted — acc type proven neutral; keep the simpler all-fp32-acc form).
// ===========================================================================
#define ASTG  18432
#define AROW  144
#define AROWW 36

__global__ __launch_bounds__(256) void attn_mma_kernel()
{
    extern __shared__ uint8_t smraw[];
    uint32_t* smw = (uint32_t*)smraw;
    const uint32_t sbase = smem_u32(smraw);

    const int tid  = threadIdx.x;
    const int w    = tid >> 5;
    const int lane = tid & 31;
    const int q4   = lane >> 2;
    const int l3   = lane & 3;
    const int qt = blockIdx.x, h = blockIdx.y, b = blockIdx.z;

    const size_t hb = (size_t)(b * NH + h) * LL * HD;
    const __half* Qh = g_qh + hb + (size_t)qt * 128 * HD;
    const __half* Ql = g_ql + hb + (size_t)qt * 128 * HD;
    const __half* Kh = g_kh + hb;
    const __half* Vh = g_vh + hb;

#pragma unroll
    for (int t = 0; t < 8; t++) {
        int i = tid + 256 * t;
        int a = i >> 10, r = (i >> 3) & 127, c = i & 7;
        const __half* src = (a ? Ql : Qh) + (size_t)r * HD + c * 8;
        CP_ASYNC16(sbase + a * 18432 + r * AROW + c * 16, src);
    }
    CP_COMMIT(); CP_WAIT0();
    __syncthreads();

    uint32_t qhf[4][4], qlf[4][4];
#pragma unroll
    for (int ks = 0; ks < 4; ks++) {
        int base = (w * 16 + q4) * AROWW + ks * 8 + l3;
        qhf[ks][0] = smw[base];                qhf[ks][1] = smw[base + 8 * AROWW];
        qhf[ks][2] = smw[base + 4];            qhf[ks][3] = smw[base + 8 * AROWW + 4];
        qlf[ks][0] = smw[4608 + base];         qlf[ks][1] = smw[4608 + base + 8 * AROWW];
        qlf[ks][2] = smw[4608 + base + 4];     qlf[ks][3] = smw[4608 + base + 8 * AROWW + 4];
    }
    __syncthreads();

    float m0 = -1e30f, m1 = -1e30f, ls0 = 0.f, ls1 = 0.f;
    float O[8][4];
#pragma unroll
    for (int n = 0; n < 8; n++)
#pragma unroll
        for (int q = 0; q < 4; q++) O[n][q] = 0.f;

#pragma unroll
    for (int t = 0; t < 4; t++) {
        int i = tid + 256 * t;
        int a = i >> 9, r = (i >> 3) & 63, c = i & 7;
        const __half* base = (a == 0) ? Kh : Vh;
        CP_ASYNC16(sbase + a * 9216 + r * AROW + c * 16,
                   base + (size_t)r * HD + c * 8);
    }
    CP_COMMIT();

#pragma unroll 1
    for (int kt = 0; kt < 16; kt++) {
        if (kt < 15) {
            uint32_t dst = sbase + ((kt + 1) & 1) * ASTG;
            const int r0 = (kt + 1) * 64;
#pragma unroll
            for (int t = 0; t < 4; t++) {
                int i = tid + 256 * t;
                int a = i >> 9, r = (i >> 3) & 63, c = i & 7;
                const __half* base = (a == 0) ? Kh : Vh;
                CP_ASYNC16(dst + a * 9216 + r * AROW + c * 16,
                           base + (size_t)(r0 + r) * HD + c * 8);
            }
            CP_COMMIT();
            CP_WAIT1();
        } else {
            CP_WAIT0();
        }
        __syncthreads();

        const uint32_t* KW = smw + (kt & 1) * (ASTG / 4);
        const uint32_t vbase = sbase + (kt & 1) * ASTG + 9216;

        // ---- S = Q K^T (2-term), term-outer ----
        float S[8][4];
#pragma unroll
        for (int n = 0; n < 8; n++)
#pragma unroll
            for (int q = 0; q < 4; q++) S[n][q] = 0.f;

#pragma unroll
        for (int ks = 0; ks < 4; ks++) {
#pragma unroll
            for (int g = 0; g < 2; g++) {
                uint32_t bh[4][2];
#pragma unroll
                for (int j = 0; j < 4; j++) {
                    int kb = ((g * 4 + j) * 8 + q4) * AROWW + ks * 8 + l3;
                    bh[j][0] = KW[kb];  bh[j][1] = KW[kb + 4];
                }
#pragma unroll
                for (int j = 0; j < 4; j++)
                    MMA_F16(S[g*4+j], qhf[ks][0], qhf[ks][1], qhf[ks][2], qhf[ks][3],
                            bh[j][0], bh[j][1]);
#pragma unroll
                for (int j = 0; j < 4; j++)
                    MMA_F16(S[g*4+j], qlf[ks][0], qlf[ks][1], qlf[ks][2], qlf[ks][3],
                            bh[j][0], bh[j][1]);
            }
        }

        // ---- online softmax (log2 domain) ----
        float mx0 = -1e30f, mx1 = -1e30f;
#pragma unroll
        for (int nt = 0; nt < 8; nt++) {
            mx0 = fmaxf(mx0, fmaxf(S[nt][0], S[nt][1]));
            mx1 = fmaxf(mx1, fmaxf(S[nt][2], S[nt][3]));
        }
        mx0 = fmaxf(mx0, __shfl_xor_sync(0xffffffffu, mx0, 1));
        mx0 = fmaxf(mx0, __shfl_xor_sync(0xffffffffu, mx0, 2));
        mx1 = fmaxf(mx1, __shfl_xor_sync(0xffffffffu, mx1, 1));
        mx1 = fmaxf(mx1, __shfl_xor_sync(0xffffffffu, mx1, 2));
        float mn0 = fmaxf(m0, mx0), mn1 = fmaxf(m1, mx1);
        float a0 = ex2f(m0 - mn0), a1 = ex2f(m1 - mn1);
        float rs0 = 0.f, rs1 = 0.f;
#pragma unroll
        for (int nt = 0; nt < 8; nt++) {
            S[nt][0] = ex2f(S[nt][0] - mn0); S[nt][1] = ex2f(S[nt][1] - mn0);
            S[nt][2] = ex2f(S[nt][2] - mn1); S[nt][3] = ex2f(S[nt][3] - mn1);
            rs0 += S[nt][0] + S[nt][1];
            rs1 += S[nt][2] + S[nt][3];
        }
        rs0 += __shfl_xor_sync(0xffffffffu, rs0, 1);
        rs0 += __shfl_xor_sync(0xffffffffu, rs0, 2);
        rs1 += __shfl_xor_sync(0xffffffffu, rs1, 1);
        rs1 += __shfl_xor_sync(0xffffffffu, rs1, 2);
        ls0 = ls0 * a0 + rs0;  ls1 = ls1 * a1 + rs1;
        m0 = mn0;  m1 = mn1;
#pragma unroll
        for (int nt = 0; nt < 8; nt++) {
            O[nt][0] *= a0; O[nt][1] *= a0;
            O[nt][2] *= a1; O[nt][3] *= a1;
        }

        // ---- pack P fragments (fp16 hi/lo) ----
        uint32_t ph[4][4], pl[4][4];
#pragma unroll
        for (int j = 0; j < 4; j++) {
            split2h(S[2*j][0],   S[2*j][1],   ph[j][0], pl[j][0]);
            split2h(S[2*j][2],   S[2*j][3],   ph[j][1], pl[j][1]);
            split2h(S[2*j+1][0], S[2*j+1][1], ph[j][2], pl[j][2]);
            split2h(S[2*j+1][2], S[2*j+1][3], ph[j][3], pl[j][3]);
        }

        // ---- O += P V (2-term), term-outer ----
        const uint32_t lrow = (lane & 15);
        const uint32_t lcol = ((lane >> 4) & 1) * 16;
#pragma unroll
        for (int j = 0; j < 4; j++) {
            uint32_t va = vbase + (16 * j + lrow) * AROW + lcol;
#pragma unroll
            for (int pp = 0; pp < 2; pp++) {
                uint32_t vh[2][4];
#pragma unroll
                for (int t = 0; t < 2; t++) {
                    uint32_t addr = va + (pp * 2 + t) * 32;
                    LDSM_X4_T(vh[t][0], vh[t][1], vh[t][2], vh[t][3], addr);
                }
#pragma unroll
                for (int t = 0; t < 2; t++) {
                    MMA_F16(O[4*pp+2*t],   ph[j][0], ph[j][1], ph[j][2], ph[j][3],
                            vh[t][0], vh[t][1]);
                    MMA_F16(O[4*pp+2*t+1], ph[j][0], ph[j][1], ph[j][2], ph[j][3],
                            vh[t][2], vh[t][3]);
                }
#pragma unroll
                for (int t = 0; t < 2; t++) {
                    MMA_F16(O[4*pp+2*t],   pl[j][0], pl[j][1], pl[j][2], pl[j][3],
                            vh[t][0], vh[t][1]);
                    MMA_F16(O[4*pp+2*t+1], pl[j][0], pl[j][1], pl[j][2], pl[j][3],
                            vh[t][2], vh[t][3]);
                }
            }
        }
        __syncthreads();
    }

    // ---- epilogue: normalize, split, write [b, l, c] ----
    const float inv0 = 1.0f / ls0, inv1 = 1.0f / ls1;
    const int row0 = qt * 128 + w * 16 + q4;
    const size_t o0 = ((size_t)b * LL + row0) * CC + h * HD;
    const size_t o1 = o0 + 8 * CC;
#pragma unroll
    for (int nt = 0; nt < 8; nt++) {
        int cc = nt * 8 + 2 * l3;
        uint32_t hw, lw;
        split2h(O[nt][0] * inv0, O[nt][1] * inv0, hw, lw);
        *(uint32_t*)(g_aoh + o0 + cc) = hw;
        *(uint32_t*)(g_aol + o0 + cc) = lw;
        split2h(O[nt][2] * inv1, O[nt][3] * inv1, hw, lw);
        *(uint32_t*)(g_aoh + o1 + cc) = hw;
        *(uint32_t*)(g_aol + o1 + cc) = lw;
    }
}

// ---------------------------------------------------------------------------
extern "C" void kernel_launch(void* const* d_in, const int* in_sizes, int n_in,
                              void* d_out, int out_size)
{
    const float* x      = (const float*)d_in[0];
    const float* w_qkv  = (const float*)d_in[1];
    const float* qgam   = (const float*)d_in[2];
    const float* kgam   = (const float*)d_in[3];
    const float* w_out  = (const float*)d_in[4];
    float* out = (float*)d_out;

    float* qkv; cudaGetSymbolAddress((void**)&qkv, g_qkv);
    __half *xh, *xl, *wqh, *woh, *aoh, *aol;
    cudaGetSymbolAddress((void**)&xh, g_xh);   cudaGetSymbolAddress((void**)&xl, g_xl);
    cudaGetSymbolAddress((void**)&wqh, g_wqh);
    cudaGetSymbolAddress((void**)&woh, g_woh);
    cudaGetSymbolAddress((void**)&aoh, g_aoh); cudaGetSymbolAddress((void**)&aol, g_aol);

    cudaFuncSetAttribute(gemm_2t_kernel,
                         cudaFuncAttributeMaxDynamicSharedMemorySize, 2 * GSTG);
    cudaFuncSetAttribute(attn_mma_kernel,
                         cudaFuncAttributeMaxDynamicSharedMemorySize, 2 * ASTG);

    // 0) prepare operands
    split_kernel<<<(M_TOT * CC / 4 + 255) / 256, 256>>>(x, xh, xl, M_TOT * CC / 4);
    cvt_kernel<<<(NQKV * CC / 4 + 255) / 256, 256>>>(w_qkv, wqh, NQKV * CC / 4);
    cvt_kernel<<<(CC * CC / 4 + 255) / 256, 256>>>(w_out, woh, CC * CC / 4);

    // 1) QKV projection: Q columns (first 768) 2-term, K/V columns 1-term
    gemm_2t_kernel<<<dim3(NQKV / 128, M_TOT / 128), 256, 2 * GSTG>>>(
        xh, xl, wqh, qkv, M_TOT, NQKV, CC, CC);

    // 2) RMSNorm + RoPE + fp16 split
    qkv_post_kernel<<<(BB * LL * NH) / 8, 256>>>(qgam, kgam);

    // 3) Flash attention
    attn_mma_kernel<<<dim3(LL / 128, NH, BB), 256, 2 * ASTG>>>();

    // 4) Output projection: all columns 2-term
    gemm_2t_kernel<<<dim3(CC / 128, M_TOT / 128), 256, 2 * GSTG>>>(
        aoh, aol, woh, out, M_TOT, CC, CC, CC);
}

// round 11
// speedup vs baseline: 4.5774x; 1.1677x over previous
#include <cuda_runtime.h>
#include <cuda_fp16.h>
#include <cstdint>
#include <math.h>

#define BB 8
#define LL 1024
#define CC 768
#define NH 12
#define HD 64
#define M_TOT (BB*LL)      /* 8192 */
#define NQKV (3*CC)        /* 2304 */

// ---------------- scratch (device globals: no allocation allowed) ----------
__device__ float g_qkv[(size_t)M_TOT * NQKV];
__device__ __half g_xh[(size_t)M_TOT * CC],  g_xl[(size_t)M_TOT * CC];
__device__ __half g_wqh[(size_t)NQKV * CC];
__device__ __half g_woh[(size_t)CC * CC];
__device__ __half g_aoh[(size_t)M_TOT * CC], g_aol[(size_t)M_TOT * CC];
__device__ __half g_qh[(size_t)BB*NH*LL*HD], g_ql[(size_t)BB*NH*LL*HD];
__device__ __half g_kh[(size_t)BB*NH*LL*HD];
__device__ __half g_vh[(size_t)BB*NH*LL*HD];

// ---------------------------------------------------------------------------
__device__ __forceinline__ float ex2f(float x) {
    float y;
    asm("ex2.approx.ftz.f32 %0, %1;" : "=f"(y) : "f"(x));
    return y;
}
__device__ __forceinline__ uint32_t smem_u32(const void* p) {
    uint32_t a;
    asm("{ .reg .u64 t; cvta.to.shared.u64 t, %1; cvt.u32.u64 %0, t; }"
        : "=r"(a) : "l"(p));
    return a;
}
__device__ __forceinline__ void split2h(float a, float b, uint32_t& hi, uint32_t& lo) {
    __half ha = __float2half_rn(a);
    __half hb = __float2half_rn(b);
    float ra = a - __half2float(ha);
    float rb = b - __half2float(hb);
    __half la = __float2half_rn(ra);
    __half lb = __float2half_rn(rb);
    hi = ((uint32_t)*(uint16_t*)&hb << 16) | (uint32_t)*(uint16_t*)&ha;
    lo = ((uint32_t)*(uint16_t*)&lb << 16) | (uint32_t)*(uint16_t*)&la;
}
__device__ __forceinline__ uint32_t pack2h(float a, float b) {
    __half2 v = __floats2half2_rn(a, b);
    return *(uint32_t*)&v;
}

#define MMA_F16(Cr, A0, A1, A2, A3, B0, B1) \
    asm volatile("mma.sync.aligned.m16n8k16.row.col.f32.f16.f16.f32 " \
        "{%0,%1,%2,%3}, {%4,%5,%6,%7}, {%8,%9}, {%0,%1,%2,%3};" \
        : "+f"((Cr)[0]), "+f"((Cr)[1]), "+f"((Cr)[2]), "+f"((Cr)[3]) \
        : "r"(A0), "r"(A1), "r"(A2), "r"(A3), "r"(B0), "r"(B1))

#define LDSM_X4(r0, r1, r2, r3, addr) \
    asm volatile("ldmatrix.sync.aligned.m8n8.x4.shared.b16 {%0,%1,%2,%3}, [%4];" \
        : "=r"(r0), "=r"(r1), "=r"(r2), "=r"(r3) : "r"(addr))

#define LDSM_X4_T(r0, r1, r2, r3, addr) \
    asm volatile("ldmatrix.sync.aligned.m8n8.x4.trans.shared.b16 {%0,%1,%2,%3}, [%4];" \
        : "=r"(r0), "=r"(r1), "=r"(r2), "=r"(r3) : "r"(addr))

#define CP_ASYNC16(dst, src) \
    asm volatile("cp.async.cg.shared.global [%0], [%1], 16;" \
                 :: "r"(dst), "l"(src) : "memory")
#define CP_COMMIT() asm volatile("cp.async.commit_group;" ::: "memory")
#define CP_WAIT0()  asm volatile("cp.async.wait_group 0;" ::: "memory")
#define CP_WAIT1()  asm volatile("cp.async.wait_group 1;" ::: "memory")

// ===========================================================================
// prep kernels
// ===========================================================================
__global__ __launch_bounds__(256) void split_kernel(
    const float* __restrict__ src, __half* __restrict__ h,
    __half* __restrict__ l, int n4)
{
    int i = blockIdx.x * 256 + threadIdx.x;
    if (i < n4) {
        float4 v = ((const float4*)src)[i];
        uint32_t h0, l0, h1, l1;
        split2h(v.x, v.y, h0, l0);
        split2h(v.z, v.w, h1, l1);
        ((uint2*)h)[i] = make_uint2(h0, h1);
        ((uint2*)l)[i] = make_uint2(l0, l1);
    }
}
__global__ __launch_bounds__(256) void cvt_kernel(
    const float* __restrict__ src, __half* __restrict__ h, int n4)
{
    int i = blockIdx.x * 256 + threadIdx.x;
    if (i < n4) {
        float4 v = ((const float4*)src)[i];
        ((__half2*)h)[2*i]   = __floats2half2_rn(v.x, v.y);
        ((__half2*)h)[2*i+1] = __floats2half2_rn(v.z, v.w);
    }
}

// ===========================================================================
// Pipelined fp16 GEMM (NT): C = Ah*Bh^T (+ Al*Bh^T for cols < n_two).
// ===========================================================================
#define GSTG 30720

__global__ __launch_bounds__(256) void gemm_2t_kernel(
    const __half* __restrict__ Ah, const __half* __restrict__ Al,
    const __half* __restrict__ Bh,
    float* __restrict__ C, int M, int N, int K, int n_two)
{
    extern __shared__ uint8_t smraw[];
    const uint32_t sbase = smem_u32(smraw);

    const int tid  = threadIdx.x;
    const int wid  = tid >> 5;
    const int lane = tid & 31;
    const int wm = wid & 1;
    const int wn = wid >> 1;
    const int row0 = blockIdx.y * 128;
    const int col0 = blockIdx.x * 128;
    const int q4 = lane >> 2;
    const int l3 = lane & 3;
    const int lr16  = lane & 15;
    const int lhalf = (lane >> 4) * 16;
    const bool two_term = (col0 < n_two);

    float c[4][4][4];
#pragma unroll
    for (int m = 0; m < 4; m++)
#pragma unroll
        for (int n = 0; n < 4; n++)
#pragma unroll
            for (int q = 0; q < 4; q++) c[m][n][q] = 0.f;

    const int nch = K / 32;

    {
        uint32_t dst = sbase;
#pragma unroll
        for (int j = 0; j < 6; j++) {
            int i = tid + 256 * j;
            int a = i >> 9, r = (i >> 2) & 127, cc = i & 3;
            if (a == 1 && !two_term) continue;
            const __half* base = (a == 0) ? Ah : (a == 1) ? Al : Bh;
            int grow = ((a < 2) ? row0 : col0) + r;
            CP_ASYNC16(dst + a * 10240 + r * 80 + cc * 16,
                       base + (size_t)grow * K + cc * 8);
        }
        CP_COMMIT();
    }

#pragma unroll 1
    for (int ch = 0; ch < nch; ch++) {
        if (ch + 1 < nch) {
            uint32_t dst = sbase + ((ch + 1) & 1) * GSTG;
            const int k0 = (ch + 1) * 32;
#pragma unroll
            for (int j = 0; j < 6; j++) {
                int i = tid + 256 * j;
                int a = i >> 9, r = (i >> 2) & 127, cc = i & 3;
                if (a == 1 && !two_term) continue;
                const __half* base = (a == 0) ? Ah : (a == 1) ? Al : Bh;
                int grow = ((a < 2) ? row0 : col0) + r;
                CP_ASYNC16(dst + a * 10240 + r * 80 + cc * 16,
                           base + (size_t)grow * K + k0 + cc * 8);
            }
            CP_COMMIT();
            CP_WAIT1();
        } else {
            CP_WAIT0();
        }
        __syncthreads();

        const uint32_t sst = sbase + (ch & 1) * GSTG;

#pragma unroll
        for (int ks = 0; ks < 2; ks++) {
            uint32_t ah[4][4], al[4][4];
#pragma unroll
            for (int m = 0; m < 4; m++) {
                uint32_t arow = sst + (wm * 64 + m * 16 + lr16) * 80 + lhalf + ks * 32;
                LDSM_X4(ah[m][0], ah[m][1], ah[m][2], ah[m][3], arow);
                if (two_term)
                    LDSM_X4(al[m][0], al[m][1], al[m][2], al[m][3], arow + 10240);
            }
#pragma unroll
            for (int np = 0; np < 2; np++) {
                uint32_t brow = sst + 20480 + (wn * 32 + np * 16 + lr16) * 80 + lhalf + ks * 32;
                uint32_t h0, h1, h2, h3;
                LDSM_X4(h0, h1, h2, h3, brow);
#pragma unroll
                for (int m = 0; m < 4; m++)
                    MMA_F16(c[m][2*np],   ah[m][0], ah[m][1], ah[m][2], ah[m][3], h0, h2);
#pragma unroll
                for (int m = 0; m < 4; m++)
                    MMA_F16(c[m][2*np+1], ah[m][0], ah[m][1], ah[m][2], ah[m][3], h1, h3);
                if (two_term) {
#pragma unroll
                    for (int m = 0; m < 4; m++)
                        MMA_F16(c[m][2*np],   al[m][0], al[m][1], al[m][2], al[m][3], h0, h2);
#pragma unroll
                    for (int m = 0; m < 4; m++)
                        MMA_F16(c[m][2*np+1], al[m][0], al[m][1], al[m][2], al[m][3], h1, h3);
                }
            }
        }
        __syncthreads();
    }

#pragma unroll
    for (int m = 0; m < 4; m++) {
        const int r = row0 + wm * 64 + m * 16 + q4;
#pragma unroll
        for (int n = 0; n < 4; n++) {
            const int cc = col0 + wn * 32 + n * 8 + l3 * 2;
            *(float2*)(C + (size_t)r * N + cc)       = make_float2(c[m][n][0], c[m][n][1]);
            *(float2*)(C + (size_t)(r + 8) * N + cc) = make_float2(c[m][n][2], c[m][n][3]);
        }
    }
}

// ---------------------------------------------------------------------------
// QKV epilogue: RMSNorm + RoPE; q -> fp16 hi/lo, k/v -> fp16 hi. [b,h,l,e].
// ---------------------------------------------------------------------------
__global__ __launch_bounds__(256) void qkv_post_kernel(
    const float* __restrict__ qg, const float* __restrict__ kg)
{
    const int widx = blockIdx.x * 8 + (threadIdx.x >> 5);
    const int lane = threadIdx.x & 31;
    const int h = widx % NH;
    const int l = (widx / NH) % LL;
    const int b = widx / (NH * LL);

    const float* rowp = g_qkv + (size_t)(b * LL + l) * NQKV + h * HD;
    const float ifr = exp2f(-13.287712379549449f * (float)lane * (1.0f / 32.0f));
    const float ang = (float)l * ifr;
    const float cs = cosf(ang), sn = sinf(ang);
    const size_t dsto = ((size_t)(b * NH + h) * LL + l) * HD;
    const float QS = 0.125f * 1.4426950408889634f;

    {
        float x1 = rowp[lane], x2 = rowp[lane + 32];
        float ss = x1 * x1 + x2 * x2;
#pragma unroll
        for (int o = 16; o; o >>= 1) ss += __shfl_xor_sync(0xffffffffu, ss, o);
        float r = rsqrtf(ss * (1.0f / HD) + 1e-6f);
        float n1 = x1 * r * qg[lane], n2 = x2 * r * qg[lane + 32];
        float v1 = (n1 * cs - n2 * sn) * QS;
        float v2 = (n1 * sn + n2 * cs) * QS;
        __half h1 = __float2half_rn(v1), h2 = __float2half_rn(v2);
        g_qh[dsto + lane]      = h1;
        g_qh[dsto + lane + 32] = h2;
        g_ql[dsto + lane]      = __float2half_rn(v1 - __half2float(h1));
        g_ql[dsto + lane + 32] = __float2half_rn(v2 - __half2float(h2));
    }
    {
        float x1 = rowp[CC + lane], x2 = rowp[CC + lane + 32];
        float ss = x1 * x1 + x2 * x2;
#pragma unroll
        for (int o = 16; o; o >>= 1) ss += __shfl_xor_sync(0xffffffffu, ss, o);
        float r = rsqrtf(ss * (1.0f / HD) + 1e-6f);
        float n1 = x1 * r * kg[lane], n2 = x2 * r * kg[lane + 32];
        g_kh[dsto + lane]      = __float2half_rn(n1 * cs - n2 * sn);
        g_kh[dsto + lane + 32] = __float2half_rn(n1 * sn + n2 * cs);
    }
    g_vh[dsto + lane]      = __float2half_rn(rowp[2 * CC + lane]);
    g_vh[dsto + lane + 32] = __float2half_rn(rowp[2 * CC + lane + 32]);
}

// ===========================================================================
// Flash attention: S = QK^T 2-term, PV 1-term (P single-rounded fp16).
// ===========================================================================
#define ASTG  18432
#define AROW  144
#define AROWW 36

__global__ __launch_bounds__(256) void attn_mma_kernel()
{
    extern __shared__ uint8_t smraw[];
    uint32_t* smw = (uint32_t*)smraw;
    const uint32_t sbase = smem_u32(smraw);

    const int tid  = threadIdx.x;
    const int w    = tid >> 5;
    const int lane = tid & 31;
    const int q4   = lane >> 2;
    const int l3   = lane & 3;
    const int qt = blockIdx.x, h = blockIdx.y, b = blockIdx.z;

    const size_t hb = (size_t)(b * NH + h) * LL * HD;
    const __half* Qh = g_qh + hb + (size_t)qt * 128 * HD;
    const __half* Ql = g_ql + hb + (size_t)qt * 128 * HD;
    const __half* Kh = g_kh + hb;
    const __half* Vh = g_vh + hb;

#pragma unroll
    for (int t = 0; t < 8; t++) {
        int i = tid + 256 * t;
        int a = i >> 10, r = (i >> 3) & 127, c = i & 7;
        const __half* src = (a ? Ql : Qh) + (size_t)r * HD + c * 8;
        CP_ASYNC16(sbase + a * 18432 + r * AROW + c * 16, src);
    }
    CP_COMMIT(); CP_WAIT0();
    __syncthreads();

    uint32_t qhf[4][4], qlf[4][4];
#pragma unroll
    for (int ks = 0; ks < 4; ks++) {
        int base = (w * 16 + q4) * AROWW + ks * 8 + l3;
        qhf[ks][0] = smw[base];                qhf[ks][1] = smw[base + 8 * AROWW];
        qhf[ks][2] = smw[base + 4];            qhf[ks][3] = smw[base + 8 * AROWW + 4];
        qlf[ks][0] = smw[4608 + base];         qlf[ks][1] = smw[4608 + base + 8 * AROWW];
        qlf[ks][2] = smw[4608 + base + 4];     qlf[ks][3] = smw[4608 + base + 8 * AROWW + 4];
    }
    __syncthreads();

    float m0 = -1e30f, m1 = -1e30f, ls0 = 0.f, ls1 = 0.f;
    float O[8][4];
#pragma unroll
    for (int n = 0; n < 8; n++)
#pragma unroll
        for (int q = 0; q < 4; q++) O[n][q] = 0.f;

#pragma unroll
    for (int t = 0; t < 4; t++) {
        int i = tid + 256 * t;
        int a = i >> 9, r = (i >> 3) & 63, c = i & 7;
        const __half* base = (a == 0) ? Kh : Vh;
        CP_ASYNC16(sbase + a * 9216 + r * AROW + c * 16,
                   base + (size_t)r * HD + c * 8);
    }
    CP_COMMIT();

#pragma unroll 1
    for (int kt = 0; kt < 16; kt++) {
        if (kt < 15) {
            uint32_t dst = sbase + ((kt + 1) & 1) * ASTG;
            const int r0 = (kt + 1) * 64;
#pragma unroll
            for (int t = 0; t < 4; t++) {
                int i = tid + 256 * t;
                int a = i >> 9, r = (i >> 3) & 63, c = i & 7;
                const __half* base = (a == 0) ? Kh : Vh;
                CP_ASYNC16(dst + a * 9216 + r * AROW + c * 16,
                           base + (size_t)(r0 + r) * HD + c * 8);
            }
            CP_COMMIT();
            CP_WAIT1();
        } else {
            CP_WAIT0();
        }
        __syncthreads();

        const uint32_t* KW = smw + (kt & 1) * (ASTG / 4);
        const uint32_t vbase = sbase + (kt & 1) * ASTG + 9216;

        // ---- S = Q K^T (2-term), term-outer ----
        float S[8][4];
#pragma unroll
        for (int n = 0; n < 8; n++)
#pragma unroll
            for (int q = 0; q < 4; q++) S[n][q] = 0.f;

#pragma unroll
        for (int ks = 0; ks < 4; ks++) {
#pragma unroll
            for (int g = 0; g < 2; g++) {
                uint32_t bh[4][2];
#pragma unroll
                for (int j = 0; j < 4; j++) {
                    int kb = ((g * 4 + j) * 8 + q4) * AROWW + ks * 8 + l3;
                    bh[j][0] = KW[kb];  bh[j][1] = KW[kb + 4];
                }
#pragma unroll
                for (int j = 0; j < 4; j++)
                    MMA_F16(S[g*4+j], qhf[ks][0], qhf[ks][1], qhf[ks][2], qhf[ks][3],
                            bh[j][0], bh[j][1]);
#pragma unroll
                for (int j = 0; j < 4; j++)
                    MMA_F16(S[g*4+j], qlf[ks][0], qlf[ks][1], qlf[ks][2], qlf[ks][3],
                            bh[j][0], bh[j][1]);
            }
        }

        // ---- online softmax (log2 domain) ----
        float mx0 = -1e30f, mx1 = -1e30f;
#pragma unroll
        for (int nt = 0; nt < 8; nt++) {
            mx0 = fmaxf(mx0, fmaxf(S[nt][0], S[nt][1]));
            mx1 = fmaxf(mx1, fmaxf(S[nt][2], S[nt][3]));
        }
        mx0 = fmaxf(mx0, __shfl_xor_sync(0xffffffffu, mx0, 1));
        mx0 = fmaxf(mx0, __shfl_xor_sync(0xffffffffu, mx0, 2));
        mx1 = fmaxf(mx1, __shfl_xor_sync(0xffffffffu, mx1, 1));
        mx1 = fmaxf(mx1, __shfl_xor_sync(0xffffffffu, mx1, 2));
        float mn0 = fmaxf(m0, mx0), mn1 = fmaxf(m1, mx1);
        float a0 = ex2f(m0 - mn0), a1 = ex2f(m1 - mn1);
        float rs0 = 0.f, rs1 = 0.f;
#pragma unroll
        for (int nt = 0; nt < 8; nt++) {
            S[nt][0] = ex2f(S[nt][0] - mn0); S[nt][1] = ex2f(S[nt][1] - mn0);
            S[nt][2] = ex2f(S[nt][2] - mn1); S[nt][3] = ex2f(S[nt][3] - mn1);
            rs0 += S[nt][0] + S[nt][1];
            rs1 += S[nt][2] + S[nt][3];
        }
        rs0 += __shfl_xor_sync(0xffffffffu, rs0, 1);
        rs0 += __shfl_xor_sync(0xffffffffu, rs0, 2);
        rs1 += __shfl_xor_sync(0xffffffffu, rs1, 1);
        rs1 += __shfl_xor_sync(0xffffffffu, rs1, 2);
        ls0 = ls0 * a0 + rs0;  ls1 = ls1 * a1 + rs1;
        m0 = mn0;  m1 = mn1;
#pragma unroll
        for (int nt = 0; nt < 8; nt++) {
            O[nt][0] *= a0; O[nt][1] *= a0;
            O[nt][2] *= a1; O[nt][3] *= a1;
        }

        // ---- pack P fragments (single-rounded fp16) ----
        uint32_t ph[4][4];
#pragma unroll
        for (int j = 0; j < 4; j++) {
            ph[j][0] = pack2h(S[2*j][0],   S[2*j][1]);
            ph[j][1] = pack2h(S[2*j][2],   S[2*j][3]);
            ph[j][2] = pack2h(S[2*j+1][0], S[2*j+1][1]);
            ph[j][3] = pack2h(S[2*j+1][2], S[2*j+1][3]);
        }

        // ---- O += P V (1-term) ----
        const uint32_t lrow = (lane & 15);
        const uint32_t lcol = ((lane >> 4) & 1) * 16;
#pragma unroll
        for (int j = 0; j < 4; j++) {
            uint32_t va = vbase + (16 * j + lrow) * AROW + lcol;
#pragma unroll
            for (int pp = 0; pp < 2; pp++) {
                uint32_t vh[2][4];
#pragma unroll
                for (int t = 0; t < 2; t++) {
                    uint32_t addr = va + (pp * 2 + t) * 32;
                    LDSM_X4_T(vh[t][0], vh[t][1], vh[t][2], vh[t][3], addr);
                }
#pragma unroll
                for (int t = 0; t < 2; t++) {
                    MMA_F16(O[4*pp+2*t],   ph[j][0], ph[j][1], ph[j][2], ph[j][3],
                            vh[t][0], vh[t][1]);
                    MMA_F16(O[4*pp+2*t+1], ph[j][0], ph[j][1], ph[j][2], ph[j][3],
                            vh[t][2], vh[t][3]);
                }
            }
        }
        __syncthreads();
    }

    // ---- epilogue: normalize, split, write [b, l, c] ----
    const float inv0 = 1.0f / ls0, inv1 = 1.0f / ls1;
    const int row0 = qt * 128 + w * 16 + q4;
    const size_t o0 = ((size_t)b * LL + row0) * CC + h * HD;
    const size_t o1 = o0 + 8 * CC;
#pragma unroll
    for (int nt = 0; nt < 8; nt++) {
        int cc = nt * 8 + 2 * l3;
        uint32_t hw, lw;
        split2h(O[nt][0] * inv0, O[nt][1] * inv0, hw, lw);
        *(uint32_t*)(g_aoh + o0 + cc) = hw;
        *(uint32_t*)(g_aol + o0 + cc) = lw;
        split2h(O[nt][2] * inv1, O[nt][3] * inv1, hw, lw);
        *(uint32_t*)(g_aoh + o1 + cc) = hw;
        *(uint32_t*)(g_aol + o1 + cc) = lw;
    }
}

// ---------------------------------------------------------------------------
extern "C" void kernel_launch(void* const* d_in, const int* in_sizes, int n_in,
                              void* d_out, int out_size)
{
    const float* x      = (const float*)d_in[0];
    const float* w_qkv  = (const float*)d_in[1];
    const float* qgam   = (const float*)d_in[2];
    const float* kgam   = (const float*)d_in[3];
    const float* w_out  = (const float*)d_in[4];
    float* out = (float*)d_out;

    float* qkv; cudaGetSymbolAddress((void**)&qkv, g_qkv);
    __half *xh, *xl, *wqh, *woh, *aoh, *aol;
    cudaGetSymbolAddress((void**)&xh, g_xh);   cudaGetSymbolAddress((void**)&xl, g_xl);
    cudaGetSymbolAddress((void**)&wqh, g_wqh);
    cudaGetSymbolAddress((void**)&woh, g_woh);
    cudaGetSymbolAddress((void**)&aoh, g_aoh); cudaGetSymbolAddress((void**)&aol, g_aol);

    cudaFuncSetAttribute(gemm_2t_kernel,
                         cudaFuncAttributeMaxDynamicSharedMemorySize, 2 * GSTG);
    cudaFuncSetAttribute(attn_mma_kernel,
                         cudaFuncAttributeMaxDynamicSharedMemorySize, 2 * ASTG);

    // 0) prepare operands
    split_kernel<<<(M_TOT * CC / 4 + 255) / 256, 256>>>(x, xh, xl, M_TOT * CC / 4);
    cvt_kernel<<<(NQKV * CC / 4 + 255) / 256, 256>>>(w_qkv, wqh, NQKV * CC / 4);
    cvt_kernel<<<(CC * CC / 4 + 255) / 256, 256>>>(w_out, woh, CC * CC / 4);

    // 1) QKV projection: Q columns 2-term, K/V columns 1-term
    gemm_2t_kernel<<<dim3(NQKV / 128, M_TOT / 128), 256, 2 * GSTG>>>(
        xh, xl, wqh, qkv, M_TOT, NQKV, CC, CC);

    // 2) RMSNorm + RoPE + fp16 split
    qkv_post_kernel<<<(BB * LL * NH) / 8, 256>>>(qgam, kgam);

    // 3) Flash attention (S 2-term, PV 1-term)
    attn_mma_kernel<<<dim3(LL / 128, NH, BB), 256, 2 * ASTG>>>();

    // 4) Output projection: 2-term
    gemm_2t_kernel<<<dim3(CC / 128, M_TOT / 128), 256, 2 * GSTG>>>(
        aoh, aol, woh, out, M_TOT, CC, CC, CC);
}

// round 12
// speedup vs baseline: 5.2075x; 1.1377x over previous
#include <cuda_runtime.h>
#include <cuda_fp16.h>
#include <cstdint>
#include <math.h>

#define BB 8
#define LL 1024
#define CC 768
#define NH 12
#define HD 64
#define M_TOT (BB*LL)      /* 8192 */
#define NQKV (3*CC)        /* 2304 */

// ---------------- scratch (device globals: no allocation allowed) ----------
__device__ float g_qkv[(size_t)M_TOT * NQKV];   // only Q/K cols written now
__device__ __half g_xh[(size_t)M_TOT * CC],  g_xl[(size_t)M_TOT * CC];
__device__ __half g_wqh[(size_t)NQKV * CC];
__device__ __half g_woh[(size_t)CC * CC];
__device__ __half g_aoh[(size_t)M_TOT * CC];
__device__ __half g_qh[(size_t)BB*NH*LL*HD], g_ql[(size_t)BB*NH*LL*HD];
__device__ __half g_kh[(size_t)BB*NH*LL*HD];
__device__ __half g_vh[(size_t)BB*NH*LL*HD];

// ---------------------------------------------------------------------------
__device__ __forceinline__ float ex2f(float x) {
    float y;
    asm("ex2.approx.ftz.f32 %0, %1;" : "=f"(y) : "f"(x));
    return y;
}
__device__ __forceinline__ uint32_t smem_u32(const void* p) {
    uint32_t a;
    asm("{ .reg .u64 t; cvta.to.shared.u64 t, %1; cvt.u32.u64 %0, t; }"
        : "=r"(a) : "l"(p));
    return a;
}
__device__ __forceinline__ void split2h(float a, float b, uint32_t& hi, uint32_t& lo) {
    __half ha = __float2half_rn(a);
    __half hb = __float2half_rn(b);
    float ra = a - __half2float(ha);
    float rb = b - __half2float(hb);
    __half la = __float2half_rn(ra);
    __half lb = __float2half_rn(rb);
    hi = ((uint32_t)*(uint16_t*)&hb << 16) | (uint32_t)*(uint16_t*)&ha;
    lo = ((uint32_t)*(uint16_t*)&lb << 16) | (uint32_t)*(uint16_t*)&la;
}
__device__ __forceinline__ uint32_t pack2h(float a, float b) {
    __half2 v = __floats2half2_rn(a, b);
    return *(uint32_t*)&v;
}

#define MMA_F16(Cr, A0, A1, A2, A3, B0, B1) \
    asm volatile("mma.sync.aligned.m16n8k16.row.col.f32.f16.f16.f32 " \
        "{%0,%1,%2,%3}, {%4,%5,%6,%7}, {%8,%9}, {%0,%1,%2,%3};" \
        : "+f"((Cr)[0]), "+f"((Cr)[1]), "+f"((Cr)[2]), "+f"((Cr)[3]) \
        : "r"(A0), "r"(A1), "r"(A2), "r"(A3), "r"(B0), "r"(B1))

#define LDSM_X4(r0, r1, r2, r3, addr) \
    asm volatile("ldmatrix.sync.aligned.m8n8.x4.shared.b16 {%0,%1,%2,%3}, [%4];" \
        : "=r"(r0), "=r"(r1), "=r"(r2), "=r"(r3) : "r"(addr))

#define LDSM_X4_T(r0, r1, r2, r3, addr) \
    asm volatile("ldmatrix.sync.aligned.m8n8.x4.trans.shared.b16 {%0,%1,%2,%3}, [%4];" \
        : "=r"(r0), "=r"(r1), "=r"(r2), "=r"(r3) : "r"(addr))

#define CP_ASYNC16(dst, src) \
    asm volatile("cp.async.cg.shared.global [%0], [%1], 16;" \
                 :: "r"(dst), "l"(src) : "memory")
#define CP_COMMIT() asm volatile("cp.async.commit_group;" ::: "memory")
#define CP_WAIT0()  asm volatile("cp.async.wait_group 0;" ::: "memory")
#define CP_WAIT1()  asm volatile("cp.async.wait_group 1;" ::: "memory")

// ===========================================================================
// prep kernels
// ===========================================================================
__global__ __launch_bounds__(256) void split_kernel(
    const float* __restrict__ src, __half* __restrict__ h,
    __half* __restrict__ l, int n4)
{
    int i = blockIdx.x * 256 + threadIdx.x;
    if (i < n4) {
        float4 v = ((const float4*)src)[i];
        uint32_t h0, l0, h1, l1;
        split2h(v.x, v.y, h0, l0);
        split2h(v.z, v.w, h1, l1);
        ((uint2*)h)[i] = make_uint2(h0, h1);
        ((uint2*)l)[i] = make_uint2(l0, l1);
    }
}
__global__ __launch_bounds__(256) void cvt_kernel(
    const float* __restrict__ src, __half* __restrict__ h, int n4)
{
    int i = blockIdx.x * 256 + threadIdx.x;
    if (i < n4) {
        float4 v = ((const float4*)src)[i];
        ((__half2*)h)[2*i]   = __floats2half2_rn(v.x, v.y);
        ((__half2*)h)[2*i+1] = __floats2half2_rn(v.z, v.w);
    }
}

// ===========================================================================
// Pipelined fp16 GEMM (NT): C = Ah*Bh^T (+ Al*Bh^T for cols < n_two).
// CTAs with col0 >= v_col0 write fp16 V-direct to g_vh[b,h,l,e] instead.
// ===========================================================================
#define GSTG 30720

__global__ __launch_bounds__(256) void gemm_2t_kernel(
    const __half* __restrict__ Ah, const __half* __restrict__ Al,
    const __half* __restrict__ Bh,
    float* __restrict__ C, int M, int N, int K, int n_two, int v_col0)
{
    extern __shared__ uint8_t smraw[];
    const uint32_t sbase = smem_u32(smraw);

    const int tid  = threadIdx.x;
    const int wid  = tid >> 5;
    const int lane = tid & 31;
    const int wm = wid & 1;
    const int wn = wid >> 1;
    const int row0 = blockIdx.y * 128;
    const int col0 = blockIdx.x * 128;
    const int q4 = lane >> 2;
    const int l3 = lane & 3;
    const int lr16  = lane & 15;
    const int lhalf = (lane >> 4) * 16;
    const bool two_term = (col0 < n_two);

    float c[4][4][4];
#pragma unroll
    for (int m = 0; m < 4; m++)
#pragma unroll
        for (int n = 0; n < 4; n++)
#pragma unroll
            for (int q = 0; q < 4; q++) c[m][n][q] = 0.f;

    const int nch = K / 32;

    {
        uint32_t dst = sbase;
#pragma unroll
        for (int j = 0; j < 6; j++) {
            int i = tid + 256 * j;
            int a = i >> 9, r = (i >> 2) & 127, cc = i & 3;
            if (a == 1 && !two_term) continue;
            const __half* base = (a == 0) ? Ah : (a == 1) ? Al : Bh;
            int grow = ((a < 2) ? row0 : col0) + r;
            CP_ASYNC16(dst + a * 10240 + r * 80 + cc * 16,
                       base + (size_t)grow * K + cc * 8);
        }
        CP_COMMIT();
    }

#pragma unroll 1
    for (int ch = 0; ch < nch; ch++) {
        if (ch + 1 < nch) {
            uint32_t dst = sbase + ((ch + 1) & 1) * GSTG;
            const int k0 = (ch + 1) * 32;
#pragma unroll
            for (int j = 0; j < 6; j++) {
                int i = tid + 256 * j;
                int a = i >> 9, r = (i >> 2) & 127, cc = i & 3;
                if (a == 1 && !two_term) continue;
                const __half* base = (a == 0) ? Ah : (a == 1) ? Al : Bh;
                int grow = ((a < 2) ? row0 : col0) + r;
                CP_ASYNC16(dst + a * 10240 + r * 80 + cc * 16,
                           base + (size_t)grow * K + k0 + cc * 8);
            }
            CP_COMMIT();
            CP_WAIT1();
        } else {
            CP_WAIT0();
        }
        __syncthreads();

        const uint32_t sst = sbase + (ch & 1) * GSTG;

#pragma unroll
        for (int ks = 0; ks < 2; ks++) {
            uint32_t ah[4][4], al[4][4];
#pragma unroll
            for (int m = 0; m < 4; m++) {
                uint32_t arow = sst + (wm * 64 + m * 16 + lr16) * 80 + lhalf + ks * 32;
                LDSM_X4(ah[m][0], ah[m][1], ah[m][2], ah[m][3], arow);
                if (two_term)
                    LDSM_X4(al[m][0], al[m][1], al[m][2], al[m][3], arow + 10240);
            }
#pragma unroll
            for (int np = 0; np < 2; np++) {
                uint32_t brow = sst + 20480 + (wn * 32 + np * 16 + lr16) * 80 + lhalf + ks * 32;
                uint32_t h0, h1, h2, h3;
                LDSM_X4(h0, h1, h2, h3, brow);
#pragma unroll
                for (int m = 0; m < 4; m++)
                    MMA_F16(c[m][2*np],   ah[m][0], ah[m][1], ah[m][2], ah[m][3], h0, h2);
#pragma unroll
                for (int m = 0; m < 4; m++)
                    MMA_F16(c[m][2*np+1], ah[m][0], ah[m][1], ah[m][2], ah[m][3], h1, h3);
                if (two_term) {
#pragma unroll
                    for (int m = 0; m < 4; m++)
                        MMA_F16(c[m][2*np],   al[m][0], al[m][1], al[m][2], al[m][3], h0, h2);
#pragma unroll
                    for (int m = 0; m < 4; m++)
                        MMA_F16(c[m][2*np+1], al[m][0], al[m][1], al[m][2], al[m][3], h1, h3);
                }
            }
        }
        __syncthreads();
    }

    if (col0 >= v_col0) {
        // V-direct: fp16 [b, h, l, e] — identical rounding to the old
        // fp32-store -> qkv_post fp16 path.
#pragma unroll
        for (int m = 0; m < 4; m++) {
            const int r = row0 + wm * 64 + m * 16 + q4;
            const int bi = r >> 10;
            const int li = r & 1023;
#pragma unroll
            for (int n = 0; n < 4; n++) {
                const int vc = col0 + wn * 32 + n * 8 + l3 * 2 - v_col0;
                const int hh = vc >> 6, ee = vc & 63;
                size_t base = ((size_t)(bi * NH + hh) * LL + li) * HD + ee;
                *(__half2*)&g_vh[base]          = __floats2half2_rn(c[m][n][0], c[m][n][1]);
                *(__half2*)&g_vh[base + 8 * HD] = __floats2half2_rn(c[m][n][2], c[m][n][3]);
            }
        }
    } else {
#pragma unroll
        for (int m = 0; m < 4; m++) {
            const int r = row0 + wm * 64 + m * 16 + q4;
#pragma unroll
            for (int n = 0; n < 4; n++) {
                const int cc = col0 + wn * 32 + n * 8 + l3 * 2;
                *(float2*)(C + (size_t)r * N + cc)       = make_float2(c[m][n][0], c[m][n][1]);
                *(float2*)(C + (size_t)(r + 8) * N + cc) = make_float2(c[m][n][2], c[m][n][3]);
            }
        }
    }
}

// ---------------------------------------------------------------------------
// QKV epilogue: RMSNorm + RoPE; q -> fp16 hi/lo, k -> fp16 hi. (V handled
// directly by the GEMM epilogue.)
// ---------------------------------------------------------------------------
__global__ __launch_bounds__(256) void qkv_post_kernel(
    const float* __restrict__ qg, const float* __restrict__ kg)
{
    const int widx = blockIdx.x * 8 + (threadIdx.x >> 5);
    const int lane = threadIdx.x & 31;
    const int h = widx % NH;
    const int l = (widx / NH) % LL;
    const int b = widx / (NH * LL);

    const float* rowp = g_qkv + (size_t)(b * LL + l) * NQKV + h * HD;
    const float ifr = exp2f(-13.287712379549449f * (float)lane * (1.0f / 32.0f));
    const float ang = (float)l * ifr;
    const float cs = cosf(ang), sn = sinf(ang);
    const size_t dsto = ((size_t)(b * NH + h) * LL + l) * HD;
    const float QS = 0.125f * 1.4426950408889634f;

    {
        float x1 = rowp[lane], x2 = rowp[lane + 32];
        float ss = x1 * x1 + x2 * x2;
#pragma unroll
        for (int o = 16; o; o >>= 1) ss += __shfl_xor_sync(0xffffffffu, ss, o);
        float r = rsqrtf(ss * (1.0f / HD) + 1e-6f);
        float n1 = x1 * r * qg[lane], n2 = x2 * r * qg[lane + 32];
        float v1 = (n1 * cs - n2 * sn) * QS;
        float v2 = (n1 * sn + n2 * cs) * QS;
        __half h1 = __float2half_rn(v1), h2 = __float2half_rn(v2);
        g_qh[dsto + lane]      = h1;
        g_qh[dsto + lane + 32] = h2;
        g_ql[dsto + lane]      = __float2half_rn(v1 - __half2float(h1));
        g_ql[dsto + lane + 32] = __float2half_rn(v2 - __half2float(h2));
    }
    {
        float x1 = rowp[CC + lane], x2 = rowp[CC + lane + 32];
        float ss = x1 * x1 + x2 * x2;
#pragma unroll
        for (int o = 16; o; o >>= 1) ss += __shfl_xor_sync(0xffffffffu, ss, o);
        float r = rsqrtf(ss * (1.0f / HD) + 1e-6f);
        float n1 = x1 * r * kg[lane], n2 = x2 * r * kg[lane + 32];
        g_kh[dsto + lane]      = __float2half_rn(n1 * cs - n2 * sn);
        g_kh[dsto + lane + 32] = __float2half_rn(n1 * sn + n2 * cs);
    }
}

// ===========================================================================
// Flash attention: S = QK^T 2-term, PV 1-term; output hi-only fp16.
// ===========================================================================
#define ASTG  18432
#define AROW  144
#define AROWW 36

__global__ __launch_bounds__(256) void attn_mma_kernel()
{
    extern __shared__ uint8_t smraw[];
    uint32_t* smw = (uint32_t*)smraw;
    const uint32_t sbase = smem_u32(smraw);

    const int tid  = threadIdx.x;
    const int w    = tid >> 5;
    const int lane = tid & 31;
    const int q4   = lane >> 2;
    const int l3   = lane & 3;
    const int qt = blockIdx.x, h = blockIdx.y, b = blockIdx.z;

    const size_t hb = (size_t)(b * NH + h) * LL * HD;
    const __half* Qh = g_qh + hb + (size_t)qt * 128 * HD;
    const __half* Ql = g_ql + hb + (size_t)qt * 128 * HD;
    const __half* Kh = g_kh + hb;
    const __half* Vh = g_vh + hb;

#pragma unroll
    for (int t = 0; t < 8; t++) {
        int i = tid + 256 * t;
        int a = i >> 10, r = (i >> 3) & 127, c = i & 7;
        const __half* src = (a ? Ql : Qh) + (size_t)r * HD + c * 8;
        CP_ASYNC16(sbase + a * 18432 + r * AROW + c * 16, src);
    }
    CP_COMMIT(); CP_WAIT0();
    __syncthreads();

    uint32_t qhf[4][4], qlf[4][4];
#pragma unroll
    for (int ks = 0; ks < 4; ks++) {
        int base = (w * 16 + q4) * AROWW + ks * 8 + l3;
        qhf[ks][0] = smw[base];                qhf[ks][1] = smw[base + 8 * AROWW];
        qhf[ks][2] = smw[base + 4];            qhf[ks][3] = smw[base + 8 * AROWW + 4];
        qlf[ks][0] = smw[4608 + base];         qlf[ks][1] = smw[4608 + base + 8 * AROWW];
        qlf[ks][2] = smw[4608 + base + 4];     qlf[ks][3] = smw[4608 + base + 8 * AROWW + 4];
    }
    __syncthreads();

    float m0 = -1e30f, m1 = -1e30f, ls0 = 0.f, ls1 = 0.f;
    float O[8][4];
#pragma unroll
    for (int n = 0; n < 8; n++)
#pragma unroll
        for (int q = 0; q < 4; q++) O[n][q] = 0.f;

#pragma unroll
    for (int t = 0; t < 4; t++) {
        int i = tid + 256 * t;
        int a = i >> 9, r = (i >> 3) & 63, c = i & 7;
        const __half* base = (a == 0) ? Kh : Vh;
        CP_ASYNC16(sbase + a * 9216 + r * AROW + c * 16,
                   base + (size_t)r * HD + c * 8);
    }
    CP_COMMIT();

#pragma unroll 1
    for (int kt = 0; kt < 16; kt++) {
        if (kt < 15) {
            uint32_t dst = sbase + ((kt + 1) & 1) * ASTG;
            const int r0 = (kt + 1) * 64;
#pragma unroll
            for (int t = 0; t < 4; t++) {
                int i = tid + 256 * t;
                int a = i >> 9, r = (i >> 3) & 63, c = i & 7;
                const __half* base = (a == 0) ? Kh : Vh;
                CP_ASYNC16(dst + a * 9216 + r * AROW + c * 16,
                           base + (size_t)(r0 + r) * HD + c * 8);
            }
            CP_COMMIT();
            CP_WAIT1();
        } else {
            CP_WAIT0();
        }
        __syncthreads();

        const uint32_t* KW = smw + (kt & 1) * (ASTG / 4);
        const uint32_t vbase = sbase + (kt & 1) * ASTG + 9216;

        // ---- S = Q K^T (2-term), term-outer ----
        float S[8][4];
#pragma unroll
        for (int n = 0; n < 8; n++)
#pragma unroll
            for (int q = 0; q < 4; q++) S[n][q] = 0.f;

#pragma unroll
        for (int ks = 0; ks < 4; ks++) {
#pragma unroll
            for (int g = 0; g < 2; g++) {
                uint32_t bh[4][2];
#pragma unroll
                for (int j = 0; j < 4; j++) {
                    int kb = ((g * 4 + j) * 8 + q4) * AROWW + ks * 8 + l3;
                    bh[j][0] = KW[kb];  bh[j][1] = KW[kb + 4];
                }
#pragma unroll
                for (int j = 0; j < 4; j++)
                    MMA_F16(S[g*4+j], qhf[ks][0], qhf[ks][1], qhf[ks][2], qhf[ks][3],
                            bh[j][0], bh[j][1]);
#pragma unroll
                for (int j = 0; j < 4; j++)
                    MMA_F16(S[g*4+j], qlf[ks][0], qlf[ks][1], qlf[ks][2], qlf[ks][3],
                            bh[j][0], bh[j][1]);
            }
        }

        // ---- online softmax (log2 domain) ----
        float mx0 = -1e30f, mx1 = -1e30f;
#pragma unroll
        for (int nt = 0; nt < 8; nt++) {
            mx0 = fmaxf(mx0, fmaxf(S[nt][0], S[nt][1]));
            mx1 = fmaxf(mx1, fmaxf(S[nt][2], S[nt][3]));
        }
        mx0 = fmaxf(mx0, __shfl_xor_sync(0xffffffffu, mx0, 1));
        mx0 = fmaxf(mx0, __shfl_xor_sync(0xffffffffu, mx0, 2));
        mx1 = fmaxf(mx1, __shfl_xor_sync(0xffffffffu, mx1, 1));
        mx1 = fmaxf(mx1, __shfl_xor_sync(0xffffffffu, mx1, 2));
        float mn0 = fmaxf(m0, mx0), mn1 = fmaxf(m1, mx1);
        float a0 = ex2f(m0 - mn0), a1 = ex2f(m1 - mn1);
        float rs0 = 0.f, rs1 = 0.f;
#pragma unroll
        for (int nt = 0; nt < 8; nt++) {
            S[nt][0] = ex2f(S[nt][0] - mn0); S[nt][1] = ex2f(S[nt][1] - mn0);
            S[nt][2] = ex2f(S[nt][2] - mn1); S[nt][3] = ex2f(S[nt][3] - mn1);
            rs0 += S[nt][0] + S[nt][1];
            rs1 += S[nt][2] + S[nt][3];
        }
        rs0 += __shfl_xor_sync(0xffffffffu, rs0, 1);
        rs0 += __shfl_xor_sync(0xffffffffu, rs0, 2);
        rs1 += __shfl_xor_sync(0xffffffffu, rs1, 1);
        rs1 += __shfl_xor_sync(0xffffffffu, rs1, 2);
        ls0 = ls0 * a0 + rs0;  ls1 = ls1 * a1 + rs1;
        m0 = mn0;  m1 = mn1;
#pragma unroll
        for (int nt = 0; nt < 8; nt++) {
            O[nt][0] *= a0; O[nt][1] *= a0;
            O[nt][2] *= a1; O[nt][3] *= a1;
        }

        // ---- pack P fragments (single-rounded fp16) ----
        uint32_t ph[4][4];
#pragma unroll
        for (int j = 0; j < 4; j++) {
            ph[j][0] = pack2h(S[2*j][0],   S[2*j][1]);
            ph[j][1] = pack2h(S[2*j][2],   S[2*j][3]);
            ph[j][2] = pack2h(S[2*j+1][0], S[2*j+1][1]);
            ph[j][3] = pack2h(S[2*j+1][2], S[2*j+1][3]);
        }

        // ---- O += P V (1-term) ----
        const uint32_t lrow = (lane & 15);
        const uint32_t lcol = ((lane >> 4) & 1) * 16;
#pragma unroll
        for (int j = 0; j < 4; j++) {
            uint32_t va = vbase + (16 * j + lrow) * AROW + lcol;
#pragma unroll
            for (int pp = 0; pp < 2; pp++) {
                uint32_t vh[2][4];
#pragma unroll
                for (int t = 0; t < 2; t++) {
                    uint32_t addr = va + (pp * 2 + t) * 32;
                    LDSM_X4_T(vh[t][0], vh[t][1], vh[t][2], vh[t][3], addr);
                }
#pragma unroll
                for (int t = 0; t < 2; t++) {
                    MMA_F16(O[4*pp+2*t],   ph[j][0], ph[j][1], ph[j][2], ph[j][3],
                            vh[t][0], vh[t][1]);
                    MMA_F16(O[4*pp+2*t+1], ph[j][0], ph[j][1], ph[j][2], ph[j][3],
                            vh[t][2], vh[t][3]);
                }
            }
        }
        __syncthreads();
    }

    // ---- epilogue: normalize, fp16 hi-only, write [b, l, c] ----
    const float inv0 = 1.0f / ls0, inv1 = 1.0f / ls1;
    const int row0 = qt * 128 + w * 16 + q4;
    const size_t o0 = ((size_t)b * LL + row0) * CC + h * HD;
    const size_t o1 = o0 + 8 * CC;
#pragma unroll
    for (int nt = 0; nt < 8; nt++) {
        int cc = nt * 8 + 2 * l3;
        *(uint32_t*)(g_aoh + o0 + cc) = pack2h(O[nt][0] * inv0, O[nt][1] * inv0);
        *(uint32_t*)(g_aoh + o1 + cc) = pack2h(O[nt][2] * inv1, O[nt][3] * inv1);
    }
}

// ---------------------------------------------------------------------------
extern "C" void kernel_launch(void* const* d_in, const int* in_sizes, int n_in,
                              void* d_out, int out_size)
{
    const float* x      = (const float*)d_in[0];
    const float* w_qkv  = (const float*)d_in[1];
    const float* qgam   = (const float*)d_in[2];
    const float* kgam   = (const float*)d_in[3];
    const float* w_out  = (const float*)d_in[4];
    float* out = (float*)d_out;

    float* qkv; cudaGetSymbolAddress((void**)&qkv, g_qkv);
    __half *xh, *xl, *wqh, *woh, *aoh;
    cudaGetSymbolAddress((void**)&xh, g_xh);   cudaGetSymbolAddress((void**)&xl, g_xl);
    cudaGetSymbolAddress((void**)&wqh, g_wqh);
    cudaGetSymbolAddress((void**)&woh, g_woh);
    cudaGetSymbolAddress((void**)&aoh, g_aoh);

    cudaFuncSetAttribute(gemm_2t_kernel,
                         cudaFuncAttributeMaxDynamicSharedMemorySize, 2 * GSTG);
    cudaFuncSetAttribute(attn_mma_kernel,
                         cudaFuncAttributeMaxDynamicSharedMemorySize, 2 * ASTG);

    // 0) prepare operands
    split_kernel<<<(M_TOT * CC / 4 + 255) / 256, 256>>>(x, xh, xl, M_TOT * CC / 4);
    cvt_kernel<<<(NQKV * CC / 4 + 255) / 256, 256>>>(w_qkv, wqh, NQKV * CC / 4);
    cvt_kernel<<<(CC * CC / 4 + 255) / 256, 256>>>(w_out, woh, CC * CC / 4);

    // 1) QKV projection: Q cols 2-term, K cols 1-term, V cols 1-term + direct
    //    fp16 [b,h,l,e] epilogue
    gemm_2t_kernel<<<dim3(NQKV / 128, M_TOT / 128), 256, 2 * GSTG>>>(
        xh, xl, wqh, qkv, M_TOT, NQKV, CC, CC, 2 * CC);

    // 2) RMSNorm + RoPE for Q/K only
    qkv_post_kernel<<<(BB * LL * NH) / 8, 256>>>(qgam, kgam);

    // 3) Flash attention (S 2-term, PV 1-term)
    attn_mma_kernel<<<dim3(LL / 128, NH, BB), 256, 2 * ASTG>>>();

    // 4) Output projection: 1-term (A single-rounded fp16)
    gemm_2t_kernel<<<dim3(CC / 128, M_TOT / 128), 256, 2 * GSTG>>>(
        aoh, aoh, woh, out, M_TOT, CC, CC, 0, CC + 1);
}

// round 13
// speedup vs baseline: 6.7759x; 1.3012x over previous
#include <cuda_runtime.h>
#include <cuda_fp16.h>
#include <cstdint>
#include <math.h>

#define BB 8
#define LL 1024
#define CC 768
#define NH 12
#define HD 64
#define M_TOT (BB*LL)      /* 8192 */
#define NQKV (3*CC)        /* 2304 */

// ---------------- scratch (device globals: no allocation allowed) ----------
__device__ float g_qkv[(size_t)M_TOT * NQKV];   // only Q/K cols written
__device__ __half g_xh[(size_t)M_TOT * CC];
__device__ __half g_wqh[(size_t)NQKV * CC];
__device__ __half g_woh[(size_t)CC * CC];
__device__ __half g_aoh[(size_t)M_TOT * CC];
__device__ __half g_qh[(size_t)BB*NH*LL*HD];
__device__ __half g_kh[(size_t)BB*NH*LL*HD];
__device__ __half g_vh[(size_t)BB*NH*LL*HD];

// ---------------------------------------------------------------------------
__device__ __forceinline__ float ex2f(float x) {
    float y;
    asm("ex2.approx.ftz.f32 %0, %1;" : "=f"(y) : "f"(x));
    return y;
}
__device__ __forceinline__ uint32_t smem_u32(const void* p) {
    uint32_t a;
    asm("{ .reg .u64 t; cvta.to.shared.u64 t, %1; cvt.u32.u64 %0, t; }"
        : "=r"(a) : "l"(p));
    return a;
}
__device__ __forceinline__ uint32_t pack2h(float a, float b) {
    __half2 v = __floats2half2_rn(a, b);
    return *(uint32_t*)&v;
}

#define MMA_F16(Cr, A0, A1, A2, A3, B0, B1) \
    asm volatile("mma.sync.aligned.m16n8k16.row.col.f32.f16.f16.f32 " \
        "{%0,%1,%2,%3}, {%4,%5,%6,%7}, {%8,%9}, {%0,%1,%2,%3};" \
        : "+f"((Cr)[0]), "+f"((Cr)[1]), "+f"((Cr)[2]), "+f"((Cr)[3]) \
        : "r"(A0), "r"(A1), "r"(A2), "r"(A3), "r"(B0), "r"(B1))

#define LDSM_X4(r0, r1, r2, r3, addr) \
    asm volatile("ldmatrix.sync.aligned.m8n8.x4.shared.b16 {%0,%1,%2,%3}, [%4];" \
        : "=r"(r0), "=r"(r1), "=r"(r2), "=r"(r3) : "r"(addr))

#define LDSM_X4_T(r0, r1, r2, r3, addr) \
    asm volatile("ldmatrix.sync.aligned.m8n8.x4.trans.shared.b16 {%0,%1,%2,%3}, [%4];" \
        : "=r"(r0), "=r"(r1), "=r"(r2), "=r"(r3) : "r"(addr))

#define CP_ASYNC16(dst, src) \
    asm volatile("cp.async.cg.shared.global [%0], [%1], 16;" \
                 :: "r"(dst), "l"(src) : "memory")
#define CP_COMMIT() asm volatile("cp.async.commit_group;" ::: "memory")
#define CP_WAIT0()  asm volatile("cp.async.wait_group 0;" ::: "memory")
#define CP_WAIT1()  asm volatile("cp.async.wait_group 1;" ::: "memory")

// ===========================================================================
// prep kernel: fp32 -> fp16 (single-rounded)
// ===========================================================================
__global__ __launch_bounds__(256) void cvt_kernel(
    const float* __restrict__ src, __half* __restrict__ h, int n4)
{
    int i = blockIdx.x * 256 + threadIdx.x;
    if (i < n4) {
        float4 v = ((const float4*)src)[i];
        ((__half2*)h)[2*i]   = __floats2half2_rn(v.x, v.y);
        ((__half2*)h)[2*i+1] = __floats2half2_rn(v.z, v.w);
    }
}

// ===========================================================================
// Pipelined fp16 1-term GEMM (NT): C = A*B^T, fp32 accumulate.
// BM=BN=128, BK=32, 256 thr = 8 warps (2x4), warp tile 64x32.
// Stage (20480B): A@0 B@10240, 128 rows x 80B.
// CTAs with col0 >= v_col0 write fp16 V-direct to g_vh[b,h,l,e].
// ===========================================================================
#define GSTG 20480

__global__ __launch_bounds__(256) void gemm_1t_kernel(
    const __half* __restrict__ Ah, const __half* __restrict__ Bh,
    float* __restrict__ C, int M, int N, int K, int v_col0)
{
    extern __shared__ uint8_t smraw[];
    const uint32_t sbase = smem_u32(smraw);

    const int tid  = threadIdx.x;
    const int wid  = tid >> 5;
    const int lane = tid & 31;
    const int wm = wid & 1;
    const int wn = wid >> 1;
    const int row0 = blockIdx.y * 128;
    const int col0 = blockIdx.x * 128;
    const int q4 = lane >> 2;
    const int l3 = lane & 3;
    const int lr16  = lane & 15;
    const int lhalf = (lane >> 4) * 16;

    float c[4][4][4];
#pragma unroll
    for (int m = 0; m < 4; m++)
#pragma unroll
        for (int n = 0; n < 4; n++)
#pragma unroll
            for (int q = 0; q < 4; q++) c[m][n][q] = 0.f;

    const int nch = K / 32;

    {
        uint32_t dst = sbase;
#pragma unroll
        for (int j = 0; j < 4; j++) {
            int i = tid + 256 * j;
            int a = i >> 9, r = (i >> 2) & 127, cc = i & 3;
            const __half* base = (a == 0) ? Ah : Bh;
            int grow = ((a == 0) ? row0 : col0) + r;
            CP_ASYNC16(dst + a * 10240 + r * 80 + cc * 16,
                       base + (size_t)grow * K + cc * 8);
        }
        CP_COMMIT();
    }

#pragma unroll 1
    for (int ch = 0; ch < nch; ch++) {
        if (ch + 1 < nch) {
            uint32_t dst = sbase + ((ch + 1) & 1) * GSTG;
            const int k0 = (ch + 1) * 32;
#pragma unroll
            for (int j = 0; j < 4; j++) {
                int i = tid + 256 * j;
                int a = i >> 9, r = (i >> 2) & 127, cc = i & 3;
                const __half* base = (a == 0) ? Ah : Bh;
                int grow = ((a == 0) ? row0 : col0) + r;
                CP_ASYNC16(dst + a * 10240 + r * 80 + cc * 16,
                           base + (size_t)grow * K + k0 + cc * 8);
            }
            CP_COMMIT();
            CP_WAIT1();
        } else {
            CP_WAIT0();
        }
        __syncthreads();

        const uint32_t sst = sbase + (ch & 1) * GSTG;

#pragma unroll
        for (int ks = 0; ks < 2; ks++) {
            uint32_t ah[4][4];
#pragma unroll
            for (int m = 0; m < 4; m++) {
                uint32_t arow = sst + (wm * 64 + m * 16 + lr16) * 80 + lhalf + ks * 32;
                LDSM_X4(ah[m][0], ah[m][1], ah[m][2], ah[m][3], arow);
            }
#pragma unroll
            for (int np = 0; np < 2; np++) {
                uint32_t brow = sst + 10240 + (wn * 32 + np * 16 + lr16) * 80 + lhalf + ks * 32;
                uint32_t h0, h1, h2, h3;
                LDSM_X4(h0, h1, h2, h3, brow);
#pragma unroll
                for (int m = 0; m < 4; m++)
                    MMA_F16(c[m][2*np],   ah[m][0], ah[m][1], ah[m][2], ah[m][3], h0, h2);
#pragma unroll
                for (int m = 0; m < 4; m++)
                    MMA_F16(c[m][2*np+1], ah[m][0], ah[m][1], ah[m][2], ah[m][3], h1, h3);
            }
        }
        __syncthreads();
    }

    if (col0 >= v_col0) {
        // V-direct: fp16 [b, h, l, e]
#pragma unroll
        for (int m = 0; m < 4; m++) {
            const int r = row0 + wm * 64 + m * 16 + q4;
            const int bi = r >> 10;
            const int li = r & 1023;
#pragma unroll
            for (int n = 0; n < 4; n++) {
                const int vc = col0 + wn * 32 + n * 8 + l3 * 2 - v_col0;
                const int hh = vc >> 6, ee = vc & 63;
                size_t base = ((size_t)(bi * NH + hh) * LL + li) * HD + ee;
                *(__half2*)&g_vh[base]          = __floats2half2_rn(c[m][n][0], c[m][n][1]);
                *(__half2*)&g_vh[base + 8 * HD] = __floats2half2_rn(c[m][n][2], c[m][n][3]);
            }
        }
    } else {
#pragma unroll
        for (int m = 0; m < 4; m++) {
            const int r = row0 + wm * 64 + m * 16 + q4;
#pragma unroll
            for (int n = 0; n < 4; n++) {
                const int cc = col0 + wn * 32 + n * 8 + l3 * 2;
                *(float2*)(C + (size_t)r * N + cc)       = make_float2(c[m][n][0], c[m][n][1]);
                *(float2*)(C + (size_t)(r + 8) * N + cc) = make_float2(c[m][n][2], c[m][n][3]);
            }
        }
    }
}

// ---------------------------------------------------------------------------
// QKV epilogue: RMSNorm + RoPE; q/k -> fp16 hi. [b,h,l,e]. (V is GEMM-direct.)
// ---------------------------------------------------------------------------
__global__ __launch_bounds__(256) void qkv_post_kernel(
    const float* __restrict__ qg, const float* __restrict__ kg)
{
    const int widx = blockIdx.x * 8 + (threadIdx.x >> 5);
    const int lane = threadIdx.x & 31;
    const int h = widx % NH;
    const int l = (widx / NH) % LL;
    const int b = widx / (NH * LL);

    const float* rowp = g_qkv + (size_t)(b * LL + l) * NQKV + h * HD;
    const float ifr = exp2f(-13.287712379549449f * (float)lane * (1.0f / 32.0f));
    const float ang = (float)l * ifr;
    const float cs = cosf(ang), sn = sinf(ang);
    const size_t dsto = ((size_t)(b * NH + h) * LL + l) * HD;
    const float QS = 0.125f * 1.4426950408889634f;

    {
        float x1 = rowp[lane], x2 = rowp[lane + 32];
        float ss = x1 * x1 + x2 * x2;
#pragma unroll
        for (int o = 16; o; o >>= 1) ss += __shfl_xor_sync(0xffffffffu, ss, o);
        float r = rsqrtf(ss * (1.0f / HD) + 1e-6f);
        float n1 = x1 * r * qg[lane], n2 = x2 * r * qg[lane + 32];
        g_qh[dsto + lane]      = __float2half_rn((n1 * cs - n2 * sn) * QS);
        g_qh[dsto + lane + 32] = __float2half_rn((n1 * sn + n2 * cs) * QS);
    }
    {
        float x1 = rowp[CC + lane], x2 = rowp[CC + lane + 32];
        float ss = x1 * x1 + x2 * x2;
#pragma unroll
        for (int o = 16; o; o >>= 1) ss += __shfl_xor_sync(0xffffffffu, ss, o);
        float r = rsqrtf(ss * (1.0f / HD) + 1e-6f);
        float n1 = x1 * r * kg[lane], n2 = x2 * r * kg[lane + 32];
        g_kh[dsto + lane]      = __float2half_rn(n1 * cs - n2 * sn);
        g_kh[dsto + lane + 32] = __float2half_rn(n1 * sn + n2 * cs);
    }
}

// ===========================================================================
// Flash attention, all single-term fp16: S = Qh Kh^T, O += P Vh.
// Q staged once (hi only); per-kt stages hold Kh + Vh (18432B each).
// ===========================================================================
#define ASTG  18432
#define AROW  144
#define AROWW 36

__global__ __launch_bounds__(256) void attn_mma_kernel()
{
    extern __shared__ uint8_t smraw[];
    uint32_t* smw = (uint32_t*)smraw;
    const uint32_t sbase = smem_u32(smraw);

    const int tid  = threadIdx.x;
    const int w    = tid >> 5;
    const int lane = tid & 31;
    const int q4   = lane >> 2;
    const int l3   = lane & 3;
    const int qt = blockIdx.x, h = blockIdx.y, b = blockIdx.z;

    const size_t hb = (size_t)(b * NH + h) * LL * HD;
    const __half* Qh = g_qh + hb + (size_t)qt * 128 * HD;
    const __half* Kh = g_kh + hb;
    const __half* Vh = g_vh + hb;

    // stage Q (hi only): 128 rows x 128B data in 144B rows
#pragma unroll
    for (int t = 0; t < 4; t++) {
        int i = tid + 256 * t;
        int r = i >> 3, c = i & 7;
        CP_ASYNC16(sbase + r * AROW + c * 16, Qh + (size_t)r * HD + c * 8);
    }
    CP_COMMIT(); CP_WAIT0();
    __syncthreads();

    uint32_t qhf[4][4];
#pragma unroll
    for (int ks = 0; ks < 4; ks++) {
        int base = (w * 16 + q4) * AROWW + ks * 8 + l3;
        qhf[ks][0] = smw[base];       qhf[ks][1] = smw[base + 8 * AROWW];
        qhf[ks][2] = smw[base + 4];   qhf[ks][3] = smw[base + 8 * AROWW + 4];
    }
    __syncthreads();

    float m0 = -1e30f, m1 = -1e30f, ls0 = 0.f, ls1 = 0.f;
    float O[8][4];
#pragma unroll
    for (int n = 0; n < 8; n++)
#pragma unroll
        for (int q = 0; q < 4; q++) O[n][q] = 0.f;

#pragma unroll
    for (int t = 0; t < 4; t++) {
        int i = tid + 256 * t;
        int a = i >> 9, r = (i >> 3) & 63, c = i & 7;
        const __half* base = (a == 0) ? Kh : Vh;
        CP_ASYNC16(sbase + a * 9216 + r * AROW + c * 16,
                   base + (size_t)r * HD + c * 8);
    }
    CP_COMMIT();

#pragma unroll 1
    for (int kt = 0; kt < 16; kt++) {
        if (kt < 15) {
            uint32_t dst = sbase + ((kt + 1) & 1) * ASTG;
            const int r0 = (kt + 1) * 64;
#pragma unroll
            for (int t = 0; t < 4; t++) {
                int i = tid + 256 * t;
                int a = i >> 9, r = (i >> 3) & 63, c = i & 7;
                const __half* base = (a == 0) ? Kh : Vh;
                CP_ASYNC16(dst + a * 9216 + r * AROW + c * 16,
                           base + (size_t)(r0 + r) * HD + c * 8);
            }
            CP_COMMIT();
            CP_WAIT1();
        } else {
            CP_WAIT0();
        }
        __syncthreads();

        const uint32_t* KW = smw + (kt & 1) * (ASTG / 4);
        const uint32_t vbase = sbase + (kt & 1) * ASTG + 9216;

        // ---- S = Q K^T (1-term) ----
        float S[8][4];
#pragma unroll
        for (int n = 0; n < 8; n++)
#pragma unroll
            for (int q = 0; q < 4; q++) S[n][q] = 0.f;

#pragma unroll
        for (int ks = 0; ks < 4; ks++) {
#pragma unroll
            for (int g = 0; g < 2; g++) {
                uint32_t bh[4][2];
#pragma unroll
                for (int j = 0; j < 4; j++) {
                    int kb = ((g * 4 + j) * 8 + q4) * AROWW + ks * 8 + l3;
                    bh[j][0] = KW[kb];  bh[j][1] = KW[kb + 4];
                }
#pragma unroll
                for (int j = 0; j < 4; j++)
                    MMA_F16(S[g*4+j], qhf[ks][0], qhf[ks][1], qhf[ks][2], qhf[ks][3],
                            bh[j][0], bh[j][1]);
            }
        }

        // ---- online softmax (log2 domain) ----
        float mx0 = -1e30f, mx1 = -1e30f;
#pragma unroll
        for (int nt = 0; nt < 8; nt++) {
            mx0 = fmaxf(mx0, fmaxf(S[nt][0], S[nt][1]));
            mx1 = fmaxf(mx1, fmaxf(S[nt][2], S[nt][3]));
        }
        mx0 = fmaxf(mx0, __shfl_xor_sync(0xffffffffu, mx0, 1));
        mx0 = fmaxf(mx0, __shfl_xor_sync(0xffffffffu, mx0, 2));
        mx1 = fmaxf(mx1, __shfl_xor_sync(0xffffffffu, mx1, 1));
        mx1 = fmaxf(mx1, __shfl_xor_sync(0xffffffffu, mx1, 2));
        float mn0 = fmaxf(m0, mx0), mn1 = fmaxf(m1, mx1);
        float a0 = ex2f(m0 - mn0), a1 = ex2f(m1 - mn1);
        float rs0 = 0.f, rs1 = 0.f;
#pragma unroll
        for (int nt = 0; nt < 8; nt++) {
            S[nt][0] = ex2f(S[nt][0] - mn0); S[nt][1] = ex2f(S[nt][1] - mn0);
            S[nt][2] = ex2f(S[nt][2] - mn1); S[nt][3] = ex2f(S[nt][3] - mn1);
            rs0 += S[nt][0] + S[nt][1];
            rs1 += S[nt][2] + S[nt][3];
        }
        rs0 += __shfl_xor_sync(0xffffffffu, rs0, 1);
        rs0 += __shfl_xor_sync(0xffffffffu, rs0, 2);
        rs1 += __shfl_xor_sync(0xffffffffu, rs1, 1);
        rs1 += __shfl_xor_sync(0xffffffffu, rs1, 2);
        ls0 = ls0 * a0 + rs0;  ls1 = ls1 * a1 + rs1;
        m0 = mn0;  m1 = mn1;
#pragma unroll
        for (int nt = 0; nt < 8; nt++) {
            O[nt][0] *= a0; O[nt][1] *= a0;
            O[nt][2] *= a1; O[nt][3] *= a1;
        }

        // ---- pack P fragments (single-rounded fp16) ----
        uint32_t ph[4][4];
#pragma unroll
        for (int j = 0; j < 4; j++) {
            ph[j][0] = pack2h(S[2*j][0],   S[2*j][1]);
            ph[j][1] = pack2h(S[2*j][2],   S[2*j][3]);
            ph[j][2] = pack2h(S[2*j+1][0], S[2*j+1][1]);
            ph[j][3] = pack2h(S[2*j+1][2], S[2*j+1][3]);
        }

        // ---- O += P V (1-term) ----
        const uint32_t lrow = (lane & 15);
        const uint32_t lcol = ((lane >> 4) & 1) * 16;
#pragma unroll
        for (int j = 0; j < 4; j++) {
            uint32_t va = vbase + (16 * j + lrow) * AROW + lcol;
#pragma unroll
            for (int pp = 0; pp < 2; pp++) {
                uint32_t vh[2][4];
#pragma unroll
                for (int t = 0; t < 2; t++) {
                    uint32_t addr = va + (pp * 2 + t) * 32;
                    LDSM_X4_T(vh[t][0], vh[t][1], vh[t][2], vh[t][3], addr);
                }
#pragma unroll
                for (int t = 0; t < 2; t++) {
                    MMA_F16(O[4*pp+2*t],   ph[j][0], ph[j][1], ph[j][2], ph[j][3],
                            vh[t][0], vh[t][1]);
                    MMA_F16(O[4*pp+2*t+1], ph[j][0], ph[j][1], ph[j][2], ph[j][3],
                            vh[t][2], vh[t][3]);
                }
            }
        }
        __syncthreads();
    }

    // ---- epilogue: normalize, fp16 hi-only, write [b, l, c] ----
    const float inv0 = 1.0f / ls0, inv1 = 1.0f / ls1;
    const int row0 = qt * 128 + w * 16 + q4;
    const size_t o0 = ((size_t)b * LL + row0) * CC + h * HD;
    const size_t o1 = o0 + 8 * CC;
#pragma unroll
    for (int nt = 0; nt < 8; nt++) {
        int cc = nt * 8 + 2 * l3;
        *(uint32_t*)(g_aoh + o0 + cc) = pack2h(O[nt][0] * inv0, O[nt][1] * inv0);
        *(uint32_t*)(g_aoh + o1 + cc) = pack2h(O[nt][2] * inv1, O[nt][3] * inv1);
    }
}

// ---------------------------------------------------------------------------
extern "C" void kernel_launch(void* const* d_in, const int* in_sizes, int n_in,
                              void* d_out, int out_size)
{
    const float* x      = (const float*)d_in[0];
    const float* w_qkv  = (const float*)d_in[1];
    const float* qgam   = (const float*)d_in[2];
    const float* kgam   = (const float*)d_in[3];
    const float* w_out  = (const float*)d_in[4];
    float* out = (float*)d_out;

    float* qkv; cudaGetSymbolAddress((void**)&qkv, g_qkv);
    __half *xh, *wqh, *woh, *aoh;
    cudaGetSymbolAddress((void**)&xh, g_xh);
    cudaGetSymbolAddress((void**)&wqh, g_wqh);
    cudaGetSymbolAddress((void**)&woh, g_woh);
    cudaGetSymbolAddress((void**)&aoh, g_aoh);

    cudaFuncSetAttribute(gemm_1t_kernel,
                         cudaFuncAttributeMaxDynamicSharedMemorySize, 2 * GSTG);
    cudaFuncSetAttribute(attn_mma_kernel,
                         cudaFuncAttributeMaxDynamicSharedMemorySize, 2 * ASTG);

    // 0) prepare operands (all single-rounded fp16)
    cvt_kernel<<<(M_TOT * CC / 4 + 255) / 256, 256>>>(x, xh, M_TOT * CC / 4);
    cvt_kernel<<<(NQKV * CC / 4 + 255) / 256, 256>>>(w_qkv, wqh, NQKV * CC / 4);
    cvt_kernel<<<(CC * CC / 4 + 255) / 256, 256>>>(w_out, woh, CC * CC / 4);

    // 1) QKV projection (1-term; V cols written fp16-direct to [b,h,l,e])
    gemm_1t_kernel<<<dim3(NQKV / 128, M_TOT / 128), 256, 2 * GSTG>>>(
        xh, wqh, qkv, M_TOT, NQKV, CC, 2 * CC);

    // 2) RMSNorm + RoPE for Q/K
    qkv_post_kernel<<<(BB * LL * NH) / 8, 256>>>(qgam, kgam);

    // 3) Flash attention (all 1-term)
    attn_mma_kernel<<<dim3(LL / 128, NH, BB), 256, 2 * ASTG>>>();

    // 4) Output projection (1-term)
    gemm_1t_kernel<<<dim3(CC / 128, M_TOT / 128), 256, 2 * GSTG>>>(
        aoh, woh, out, M_TOT, CC, CC, CC + 1);
}

// round 14
// speedup vs baseline: 6.8168x; 1.0060x over previous
#include <cuda_runtime.h>
#include <cuda_fp16.h>
#include <cstdint>
#include <math.h>

#define BB 8
#define LL 1024
#define CC 768
#define NH 12
#define HD 64
#define M_TOT (BB*LL)      /* 8192 */
#define NQKV (3*CC)        /* 2304 */
#define NQK  (2*CC)        /* 1536: Q+K columns */

// ---------------- scratch (device globals: no allocation allowed) ----------
__device__ __half g_qkh[(size_t)M_TOT * NQK];   // raw Q/K (pre-norm), fp16
__device__ __half g_xh[(size_t)M_TOT * CC];
__device__ __half g_wqh[(size_t)NQKV * CC];
__device__ __half g_woh[(size_t)CC * CC];
__device__ __half g_aoh[(size_t)M_TOT * CC];
__device__ __half g_qh[(size_t)BB*NH*LL*HD];
__device__ __half g_kh[(size_t)BB*NH*LL*HD];
__device__ __half g_vh[(size_t)BB*NH*LL*HD];

// ---------------------------------------------------------------------------
__device__ __forceinline__ float ex2f(float x) {
    float y;
    asm("ex2.approx.ftz.f32 %0, %1;" : "=f"(y) : "f"(x));
    return y;
}
__device__ __forceinline__ uint32_t smem_u32(const void* p) {
    uint32_t a;
    asm("{ .reg .u64 t; cvta.to.shared.u64 t, %1; cvt.u32.u64 %0, t; }"
        : "=r"(a) : "l"(p));
    return a;
}
__device__ __forceinline__ uint32_t pack2h(float a, float b) {
    __half2 v = __floats2half2_rn(a, b);
    return *(uint32_t*)&v;
}

#define MMA_F16(Cr, A0, A1, A2, A3, B0, B1) \
    asm volatile("mma.sync.aligned.m16n8k16.row.col.f32.f16.f16.f32 " \
        "{%0,%1,%2,%3}, {%4,%5,%6,%7}, {%8,%9}, {%0,%1,%2,%3};" \
        : "+f"((Cr)[0]), "+f"((Cr)[1]), "+f"((Cr)[2]), "+f"((Cr)[3]) \
        : "r"(A0), "r"(A1), "r"(A2), "r"(A3), "r"(B0), "r"(B1))

#define LDSM_X4(r0, r1, r2, r3, addr) \
    asm volatile("ldmatrix.sync.aligned.m8n8.x4.shared.b16 {%0,%1,%2,%3}, [%4];" \
        : "=r"(r0), "=r"(r1), "=r"(r2), "=r"(r3) : "r"(addr))

#define LDSM_X4_T(r0, r1, r2, r3, addr) \
    asm volatile("ldmatrix.sync.aligned.m8n8.x4.trans.shared.b16 {%0,%1,%2,%3}, [%4];" \
        : "=r"(r0), "=r"(r1), "=r"(r2), "=r"(r3) : "r"(addr))

#define CP_ASYNC16(dst, src) \
    asm volatile("cp.async.cg.shared.global [%0], [%1], 16;" \
                 :: "r"(dst), "l"(src) : "memory")
#define CP_COMMIT() asm volatile("cp.async.commit_group;" ::: "memory")
#define CP_WAIT0()  asm volatile("cp.async.wait_group 0;" ::: "memory")
#define CP_WAIT1()  asm volatile("cp.async.wait_group 1;" ::: "memory")
#define CP_WAIT2()  asm volatile("cp.async.wait_group 2;" ::: "memory")

// ===========================================================================
// prep kernel: fp32 -> fp16 (single-rounded)
// ===========================================================================
__global__ __launch_bounds__(256) void cvt_kernel(
    const float* __restrict__ src, __half* __restrict__ h, int n4)
{
    int i = blockIdx.x * 256 + threadIdx.x;
    if (i < n4) {
        float4 v = ((const float4*)src)[i];
        ((__half2*)h)[2*i]   = __floats2half2_rn(v.x, v.y);
        ((__half2*)h)[2*i+1] = __floats2half2_rn(v.z, v.w);
    }
}

// ===========================================================================
// Pipelined fp16 1-term GEMM (NT), 4-stage depth-2 cp.async pipeline.
// BM=BN=128, BK=32, 256 thr = 8 warps (2x4), warp tile 64x32.
// Stage (20480B): A@0 B@10240, 128 rows x 80B. 4 stages = 80KB dyn smem.
// Epilogue: QKout!=nullptr -> col0<v_col0: raw fp16 [M, v_col0];
//           col0>=v_col0: V-direct fp16 [b,h,l,e]. Else fp32 C.
// ===========================================================================
#define GSTG 20480

__global__ __launch_bounds__(256) void gemm_1t_kernel(
    const __half* __restrict__ Ah, const __half* __restrict__ Bh,
    float* __restrict__ C, __half* __restrict__ QKout,
    int M, int N, int K, int v_col0)
{
    extern __shared__ uint8_t smraw[];
    const uint32_t sbase = smem_u32(smraw);

    const int tid  = threadIdx.x;
    const int wid  = tid >> 5;
    const int lane = tid & 31;
    const int wm = wid & 1;
    const int wn = wid >> 1;
    const int row0 = blockIdx.y * 128;
    const int col0 = blockIdx.x * 128;
    const int q4 = lane >> 2;
    const int l3 = lane & 3;
    const int lr16  = lane & 15;
    const int lhalf = (lane >> 4) * 16;

    float c[4][4][4];
#pragma unroll
    for (int m = 0; m < 4; m++)
#pragma unroll
        for (int n = 0; n < 4; n++)
#pragma unroll
            for (int q = 0; q < 4; q++) c[m][n][q] = 0.f;

    const int nch = K / 32;

    // prologue: chunks 0 and 1 into stages 0 and 1
#pragma unroll
    for (int p = 0; p < 2; p++) {
        uint32_t dst = sbase + p * GSTG;
        const int k0 = p * 32;
#pragma unroll
        for (int j = 0; j < 4; j++) {
            int i = tid + 256 * j;
            int a = i >> 9, r = (i >> 2) & 127, cc = i & 3;
            const __half* base = (a == 0) ? Ah : Bh;
            int grow = ((a == 0) ? row0 : col0) + r;
            CP_ASYNC16(dst + a * 10240 + r * 80 + cc * 16,
                       base + (size_t)grow * K + k0 + cc * 8);
        }
        CP_COMMIT();
    }

#pragma unroll 1
    for (int ch = 0; ch < nch; ch++) {
        if (ch + 2 < nch) {
            uint32_t dst = sbase + ((ch + 2) & 3) * GSTG;
            const int k0 = (ch + 2) * 32;
#pragma unroll
            for (int j = 0; j < 4; j++) {
                int i = tid + 256 * j;
                int a = i >> 9, r = (i >> 2) & 127, cc = i & 3;
                const __half* base = (a == 0) ? Ah : Bh;
                int grow = ((a == 0) ? row0 : col0) + r;
                CP_ASYNC16(dst + a * 10240 + r * 80 + cc * 16,
                           base + (size_t)grow * K + k0 + cc * 8);
            }
            CP_COMMIT();
            CP_WAIT2();
        } else if (ch + 1 < nch) {
            CP_WAIT1();
        } else {
            CP_WAIT0();
        }
        __syncthreads();

        const uint32_t sst = sbase + (ch & 3) * GSTG;

#pragma unroll
        for (int ks = 0; ks < 2; ks++) {
            uint32_t ah[4][4];
#pragma unroll
            for (int m = 0; m < 4; m++) {
                uint32_t arow = sst + (wm * 64 + m * 16 + lr16) * 80 + lhalf + ks * 32;
                LDSM_X4(ah[m][0], ah[m][1], ah[m][2], ah[m][3], arow);
            }
#pragma unroll
            for (int np = 0; np < 2; np++) {
                uint32_t brow = sst + 10240 + (wn * 32 + np * 16 + lr16) * 80 + lhalf + ks * 32;
                uint32_t h0, h1, h2, h3;
                LDSM_X4(h0, h1, h2, h3, brow);
#pragma unroll
                for (int m = 0; m < 4; m++)
                    MMA_F16(c[m][2*np],   ah[m][0], ah[m][1], ah[m][2], ah[m][3], h0, h2);
#pragma unroll
                for (int m = 0; m < 4; m++)
                    MMA_F16(c[m][2*np+1], ah[m][0], ah[m][1], ah[m][2], ah[m][3], h1, h3);
            }
        }
        // no trailing sync: next issue targets stage (ch+3)&3, and stage
        // (ch&3) is re-written only at iteration ch+2 after two more syncs.
    }

    if (QKout) {
        if (col0 >= v_col0) {
            // V-direct: fp16 [b, h, l, e]
#pragma unroll
            for (int m = 0; m < 4; m++) {
                const int r = row0 + wm * 64 + m * 16 + q4;
                const int bi = r >> 10;
                const int li = r & 1023;
#pragma unroll
                for (int n = 0; n < 4; n++) {
                    const int vc = col0 + wn * 32 + n * 8 + l3 * 2 - v_col0;
                    const int hh = vc >> 6, ee = vc & 63;
                    size_t base = ((size_t)(bi * NH + hh) * LL + li) * HD + ee;
                    *(__half2*)&g_vh[base]          = __floats2half2_rn(c[m][n][0], c[m][n][1]);
                    *(__half2*)&g_vh[base + 8 * HD] = __floats2half2_rn(c[m][n][2], c[m][n][3]);
                }
            }
        } else {
            // raw Q/K: fp16 row-major [M, v_col0]
#pragma unroll
            for (int m = 0; m < 4; m++) {
                const int r = row0 + wm * 64 + m * 16 + q4;
#pragma unroll
                for (int n = 0; n < 4; n++) {
                    const int cc = col0 + wn * 32 + n * 8 + l3 * 2;
                    *(uint32_t*)&QKout[(size_t)r * v_col0 + cc] =
                        pack2h(c[m][n][0], c[m][n][1]);
                    *(uint32_t*)&QKout[(size_t)(r + 8) * v_col0 + cc] =
                        pack2h(c[m][n][2], c[m][n][3]);
                }
            }
        }
    } else {
#pragma unroll
        for (int m = 0; m < 4; m++) {
            const int r = row0 + wm * 64 + m * 16 + q4;
#pragma unroll
            for (int n = 0; n < 4; n++) {
                const int cc = col0 + wn * 32 + n * 8 + l3 * 2;
                *(float2*)(C + (size_t)r * N + cc)       = make_float2(c[m][n][0], c[m][n][1]);
                *(float2*)(C + (size_t)(r + 8) * N + cc) = make_float2(c[m][n][2], c[m][n][3]);
            }
        }
    }
}

// ---------------------------------------------------------------------------
// QKV epilogue: reads raw fp16 Q/K, RMSNorm + RoPE, writes fp16 [b,h,l,e].
// ---------------------------------------------------------------------------
__global__ __launch_bounds__(256) void qkv_post_kernel(
    const float* __restrict__ qg, const float* __restrict__ kg)
{
    const int widx = blockIdx.x * 8 + (threadIdx.x >> 5);
    const int lane = threadIdx.x & 31;
    const int h = widx % NH;
    const int l = (widx / NH) % LL;
    const int b = widx / (NH * LL);

    const __half* rowp = g_qkh + (size_t)(b * LL + l) * NQK + h * HD;
    const float ifr = exp2f(-13.287712379549449f * (float)lane * (1.0f / 32.0f));
    const float ang = (float)l * ifr;
    const float cs = cosf(ang), sn = sinf(ang);
    const size_t dsto = ((size_t)(b * NH + h) * LL + l) * HD;
    const float QS = 0.125f * 1.4426950408889634f;

    {
        float x1 = __half2float(rowp[lane]), x2 = __half2float(rowp[lane + 32]);
        float ss = x1 * x1 + x2 * x2;
#pragma unroll
        for (int o = 16; o; o >>= 1) ss += __shfl_xor_sync(0xffffffffu, ss, o);
        float r = rsqrtf(ss * (1.0f / HD) + 1e-6f);
        float n1 = x1 * r * qg[lane], n2 = x2 * r * qg[lane + 32];
        g_qh[dsto + lane]      = __float2half_rn((n1 * cs - n2 * sn) * QS);
        g_qh[dsto + lane + 32] = __float2half_rn((n1 * sn + n2 * cs) * QS);
    }
    {
        float x1 = __half2float(rowp[CC + lane]), x2 = __half2float(rowp[CC + lane + 32]);
        float ss = x1 * x1 + x2 * x2;
#pragma unroll
        for (int o = 16; o; o >>= 1) ss += __shfl_xor_sync(0xffffffffu, ss, o);
        float r = rsqrtf(ss * (1.0f / HD) + 1e-6f);
        float n1 = x1 * r * kg[lane], n2 = x2 * r * kg[lane + 32];
        g_kh[dsto + lane]      = __float2half_rn(n1 * cs - n2 * sn);
        g_kh[dsto + lane + 32] = __float2half_rn(n1 * sn + n2 * cs);
    }
}

// ===========================================================================
// Flash attention, all single-term fp16 (round-13 core, unchanged).
// ===========================================================================
#define ASTG  18432
#define AROW  144
#define AROWW 36

__global__ __launch_bounds__(256) void attn_mma_kernel()
{
    extern __shared__ uint8_t smraw[];
    uint32_t* smw = (uint32_t*)smraw;
    const uint32_t sbase = smem_u32(smraw);

    const int tid  = threadIdx.x;
    const int w    = tid >> 5;
    const int lane = tid & 31;
    const int q4   = lane >> 2;
    const int l3   = lane & 3;
    const int qt = blockIdx.x, h = blockIdx.y, b = blockIdx.z;

    const size_t hb = (size_t)(b * NH + h) * LL * HD;
    const __half* Qh = g_qh + hb + (size_t)qt * 128 * HD;
    const __half* Kh = g_kh + hb;
    const __half* Vh = g_vh + hb;

#pragma unroll
    for (int t = 0; t < 4; t++) {
        int i = tid + 256 * t;
        int r = i >> 3, c = i & 7;
        CP_ASYNC16(sbase + r * AROW + c * 16, Qh + (size_t)r * HD + c * 8);
    }
    CP_COMMIT(); CP_WAIT0();
    __syncthreads();

    uint32_t qhf[4][4];
#pragma unroll
    for (int ks = 0; ks < 4; ks++) {
        int base = (w * 16 + q4) * AROWW + ks * 8 + l3;
        qhf[ks][0] = smw[base];       qhf[ks][1] = smw[base + 8 * AROWW];
        qhf[ks][2] = smw[base + 4];   qhf[ks][3] = smw[base + 8 * AROWW + 4];
    }
    __syncthreads();

    float m0 = -1e30f, m1 = -1e30f, ls0 = 0.f, ls1 = 0.f;
    float O[8][4];
#pragma unroll
    for (int n = 0; n < 8; n++)
#pragma unroll
        for (int q = 0; q < 4; q++) O[n][q] = 0.f;

#pragma unroll
    for (int t = 0; t < 4; t++) {
        int i = tid + 256 * t;
        int a = i >> 9, r = (i >> 3) & 63, c = i & 7;
        const __half* base = (a == 0) ? Kh : Vh;
        CP_ASYNC16(sbase + a * 9216 + r * AROW + c * 16,
                   base + (size_t)r * HD + c * 8);
    }
    CP_COMMIT();

#pragma unroll 1
    for (int kt = 0; kt < 16; kt++) {
        if (kt < 15) {
            uint32_t dst = sbase + ((kt + 1) & 1) * ASTG;
            const int r0 = (kt + 1) * 64;
#pragma unroll
            for (int t = 0; t < 4; t++) {
                int i = tid + 256 * t;
                int a = i >> 9, r = (i >> 3) & 63, c = i & 7;
                const __half* base = (a == 0) ? Kh : Vh;
                CP_ASYNC16(dst + a * 9216 + r * AROW + c * 16,
                           base + (size_t)(r0 + r) * HD + c * 8);
            }
            CP_COMMIT();
            CP_WAIT1();
        } else {
            CP_WAIT0();
        }
        __syncthreads();

        const uint32_t* KW = smw + (kt & 1) * (ASTG / 4);
        const uint32_t vbase = sbase + (kt & 1) * ASTG + 9216;

        float S[8][4];
#pragma unroll
        for (int n = 0; n < 8; n++)
#pragma unroll
            for (int q = 0; q < 4; q++) S[n][q] = 0.f;

#pragma unroll
        for (int ks = 0; ks < 4; ks++) {
#pragma unroll
            for (int g = 0; g < 2; g++) {
                uint32_t bh[4][2];
#pragma unroll
                for (int j = 0; j < 4; j++) {
                    int kb = ((g * 4 + j) * 8 + q4) * AROWW + ks * 8 + l3;
                    bh[j][0] = KW[kb];  bh[j][1] = KW[kb + 4];
                }
#pragma unroll
                for (int j = 0; j < 4; j++)
                    MMA_F16(S[g*4+j], qhf[ks][0], qhf[ks][1], qhf[ks][2], qhf[ks][3],
                            bh[j][0], bh[j][1]);
            }
        }

        float mx0 = -1e30f, mx1 = -1e30f;
#pragma unroll
        for (int nt = 0; nt < 8; nt++) {
            mx0 = fmaxf(mx0, fmaxf(S[nt][0], S[nt][1]));
            mx1 = fmaxf(mx1, fmaxf(S[nt][2], S[nt][3]));
        }
        mx0 = fmaxf(mx0, __shfl_xor_sync(0xffffffffu, mx0, 1));
        mx0 = fmaxf(mx0, __shfl_xor_sync(0xffffffffu, mx0, 2));
        mx1 = fmaxf(mx1, __shfl_xor_sync(0xffffffffu, mx1, 1));
        mx1 = fmaxf(mx1, __shfl_xor_sync(0xffffffffu, mx1, 2));
        float mn0 = fmaxf(m0, mx0), mn1 = fmaxf(m1, mx1);
        float a0 = ex2f(m0 - mn0), a1 = ex2f(m1 - mn1);
        float rs0 = 0.f, rs1 = 0.f;
#pragma unroll
        for (int nt = 0; nt < 8; nt++) {
            S[nt][0] = ex2f(S[nt][0] - mn0); S[nt][1] = ex2f(S[nt][1] - mn0);
            S[nt][2] = ex2f(S[nt][2] - mn1); S[nt][3] = ex2f(S[nt][3] - mn1);
            rs0 += S[nt][0] + S[nt][1];
            rs1 += S[nt][2] + S[nt][3];
        }
        rs0 += __shfl_xor_sync(0xffffffffu, rs0, 1);
        rs0 += __shfl_xor_sync(0xffffffffu, rs0, 2);
        rs1 += __shfl_xor_sync(0xffffffffu, rs1, 1);
        rs1 += __shfl_xor_sync(0xffffffffu, rs1, 2);
        ls0 = ls0 * a0 + rs0;  ls1 = ls1 * a1 + rs1;
        m0 = mn0;  m1 = mn1;
#pragma unroll
        for (int nt = 0; nt < 8; nt++) {
            O[nt][0] *= a0; O[nt][1] *= a0;
            O[nt][2] *= a1; O[nt][3] *= a1;
        }

        uint32_t ph[4][4];
#pragma unroll
        for (int j = 0; j < 4; j++) {
            ph[j][0] = pack2h(S[2*j][0],   S[2*j][1]);
            ph[j][1] = pack2h(S[2*j][2],   S[2*j][3]);
            ph[j][2] = pack2h(S[2*j+1][0], S[2*j+1][1]);
            ph[j][3] = pack2h(S[2*j+1][2], S[2*j+1][3]);
        }

        const uint32_t lrow = (lane & 15);
        const uint32_t lcol = ((lane >> 4) & 1) * 16;
#pragma unroll
        for (int j = 0; j < 4; j++) {
            uint32_t va = vbase + (16 * j + lrow) * AROW + lcol;
#pragma unroll
            for (int pp = 0; pp < 2; pp++) {
                uint32_t vh[2][4];
#pragma unroll
                for (int t = 0; t < 2; t++) {
                    uint32_t addr = va + (pp * 2 + t) * 32;
                    LDSM_X4_T(vh[t][0], vh[t][1], vh[t][2], vh[t][3], addr);
                }
#pragma unroll
                for (int t = 0; t < 2; t++) {
                    MMA_F16(O[4*pp+2*t],   ph[j][0], ph[j][1], ph[j][2], ph[j][3],
                            vh[t][0], vh[t][1]);
                    MMA_F16(O[4*pp+2*t+1], ph[j][0], ph[j][1], ph[j][2], ph[j][3],
                            vh[t][2], vh[t][3]);
                }
            }
        }
        __syncthreads();
    }

    const float inv0 = 1.0f / ls0, inv1 = 1.0f / ls1;
    const int row0 = qt * 128 + w * 16 + q4;
    const size_t o0 = ((size_t)b * LL + row0) * CC + h * HD;
    const size_t o1 = o0 + 8 * CC;
#pragma unroll
    for (int nt = 0; nt < 8; nt++) {
        int cc = nt * 8 + 2 * l3;
        *(uint32_t*)(g_aoh + o0 + cc) = pack2h(O[nt][0] * inv0, O[nt][1] * inv0);
        *(uint32_t*)(g_aoh + o1 + cc) = pack2h(O[nt][2] * inv1, O[nt][3] * inv1);
    }
}

// ---------------------------------------------------------------------------
extern "C" void kernel_launch(void* const* d_in, const int* in_sizes, int n_in,
                              void* d_out, int out_size)
{
    const float* x      = (const float*)d_in[0];
    const float* w_qkv  = (const float*)d_in[1];
    const float* qgam   = (const float*)d_in[2];
    const float* kgam   = (const float*)d_in[3];
    const float* w_out  = (const float*)d_in[4];
    float* out = (float*)d_out;

    __half *xh, *wqh, *woh, *aoh, *qkh;
    cudaGetSymbolAddress((void**)&xh, g_xh);
    cudaGetSymbolAddress((void**)&wqh, g_wqh);
    cudaGetSymbolAddress((void**)&woh, g_woh);
    cudaGetSymbolAddress((void**)&aoh, g_aoh);
    cudaGetSymbolAddress((void**)&qkh, g_qkh);

    cudaFuncSetAttribute(gemm_1t_kernel,
                         cudaFuncAttributeMaxDynamicSharedMemorySize, 4 * GSTG);
    cudaFuncSetAttribute(attn_mma_kernel,
                         cudaFuncAttributeMaxDynamicSharedMemorySize, 2 * ASTG);

    // 0) prepare operands (all single-rounded fp16)
    cvt_kernel<<<(M_TOT * CC / 4 + 255) / 256, 256>>>(x, xh, M_TOT * CC / 4);
    cvt_kernel<<<(NQKV * CC / 4 + 255) / 256, 256>>>(w_qkv, wqh, NQKV * CC / 4);
    cvt_kernel<<<(CC * CC / 4 + 255) / 256, 256>>>(w_out, woh, CC * CC / 4);

    // 1) QKV projection (1-term): Q/K cols -> fp16 raw, V cols -> fp16 direct
    gemm_1t_kernel<<<dim3(NQKV / 128, M_TOT / 128), 256, 4 * GSTG>>>(
        xh, wqh, nullptr, qkh, M_TOT, NQKV, CC, NQK);

    // 2) RMSNorm + RoPE for Q/K (fp16 in/out)
    qkv_post_kernel<<<(BB * LL * NH) / 8, 256>>>(qgam, kgam);

    // 3) Flash attention (all 1-term)
    attn_mma_kernel<<<dim3(LL / 128, NH, BB), 256, 2 * ASTG>>>();

    // 4) Output projection (1-term, fp32 out)
    gemm_1t_kernel<<<dim3(CC / 128, M_TOT / 128), 256, 4 * GSTG>>>(
        aoh, woh, out, nullptr, M_TOT, CC, CC, 0);
}

// round 15
// speedup vs baseline: 7.0147x; 1.0290x over previous
#include <cuda_runtime.h>
#include <cuda_fp16.h>
#include <cstdint>
#include <math.h>

#define BB 8
#define LL 1024
#define CC 768
#define NH 12
#define HD 64
#define M_TOT (BB*LL)      /* 8192 */
#define NQKV (3*CC)        /* 2304 */
#define NQK  (2*CC)        /* 1536 */

// ---------------- scratch (device globals: no allocation allowed) ----------
__device__ __half g_xh[(size_t)M_TOT * CC];
__device__ __half g_wqh[(size_t)NQKV * CC];
__device__ __half g_woh[(size_t)CC * CC];
__device__ __half g_aoh[(size_t)M_TOT * CC];
__device__ __half g_qh[(size_t)BB*NH*LL*HD];
__device__ __half g_kh[(size_t)BB*NH*LL*HD];
__device__ __half g_vh[(size_t)BB*NH*LL*HD];

// ---------------------------------------------------------------------------
__device__ __forceinline__ float ex2f(float x) {
    float y;
    asm("ex2.approx.ftz.f32 %0, %1;" : "=f"(y) : "f"(x));
    return y;
}
__device__ __forceinline__ uint32_t smem_u32(const void* p) {
    uint32_t a;
    asm("{ .reg .u64 t; cvta.to.shared.u64 t, %1; cvt.u32.u64 %0, t; }"
        : "=r"(a) : "l"(p));
    return a;
}
__device__ __forceinline__ uint32_t pack2h(float a, float b) {
    __half2 v = __floats2half2_rn(a, b);
    return *(uint32_t*)&v;
}

#define MMA_F16(Cr, A0, A1, A2, A3, B0, B1) \
    asm volatile("mma.sync.aligned.m16n8k16.row.col.f32.f16.f16.f32 " \
        "{%0,%1,%2,%3}, {%4,%5,%6,%7}, {%8,%9}, {%0,%1,%2,%3};" \
        : "+f"((Cr)[0]), "+f"((Cr)[1]), "+f"((Cr)[2]), "+f"((Cr)[3]) \
        : "r"(A0), "r"(A1), "r"(A2), "r"(A3), "r"(B0), "r"(B1))

#define LDSM_X4(r0, r1, r2, r3, addr) \
    asm volatile("ldmatrix.sync.aligned.m8n8.x4.shared.b16 {%0,%1,%2,%3}, [%4];" \
        : "=r"(r0), "=r"(r1), "=r"(r2), "=r"(r3) : "r"(addr))

#define LDSM_X4_T(r0, r1, r2, r3, addr) \
    asm volatile("ldmatrix.sync.aligned.m8n8.x4.trans.shared.b16 {%0,%1,%2,%3}, [%4];" \
        : "=r"(r0), "=r"(r1), "=r"(r2), "=r"(r3) : "r"(addr))

#define CP_ASYNC16(dst, src) \
    asm volatile("cp.async.cg.shared.global [%0], [%1], 16;" \
                 :: "r"(dst), "l"(src) : "memory")
#define CP_COMMIT() asm volatile("cp.async.commit_group;" ::: "memory")
#define CP_WAIT0()  asm volatile("cp.async.wait_group 0;" ::: "memory")
#define CP_WAIT1()  asm volatile("cp.async.wait_group 1;" ::: "memory")
#define CP_WAIT2()  asm volatile("cp.async.wait_group 2;" ::: "memory")

// ===========================================================================
// merged prep: fp32 -> fp16 over three arrays in one launch
// ===========================================================================
__global__ __launch_bounds__(256) void cvt3_kernel(
    const float* __restrict__ s0, __half* __restrict__ h0, int n0,
    const float* __restrict__ s1, __half* __restrict__ h1, int n1,
    const float* __restrict__ s2, __half* __restrict__ h2, int n2)
{
    int i = blockIdx.x * 256 + threadIdx.x;
    const float* s; __half* h;
    if (i < n0)           { s = s0;  h = h0; }
    else if (i < n0 + n1) { i -= n0; s = s1; h = h1; }
    else                  { i -= n0 + n1; if (i >= n2) return; s = s2; h = h2; }
    float4 v = ((const float4*)s)[i];
    ((__half2*)h)[2*i]   = __floats2half2_rn(v.x, v.y);
    ((__half2*)h)[2*i+1] = __floats2half2_rn(v.z, v.w);
}

// ===========================================================================
// Pipelined fp16 1-term GEMM (NT), 4-stage cp.async pipeline.
// mode 0: plain fp32 C epilogue (out-proj).
// mode 1: QKV — col0 >= NQK: V-direct fp16 [b,h,l,e];
//                col0 <  NQK: fused RMSNorm+RoPE epilogue -> g_qh/g_kh.
// Stage (20480B): A@0 B@10240, 128 rows x 80B. 4 stages = 80KB dyn smem.
// ===========================================================================
#define GSTG 20480

__global__ __launch_bounds__(256) void gemm_1t_kernel(
    const __half* __restrict__ Ah, const __half* __restrict__ Bh,
    float* __restrict__ C, int mode, int M, int N, int K,
    const float* __restrict__ qg, const float* __restrict__ kg)
{
    extern __shared__ uint8_t smraw[];
    const uint32_t sbase = smem_u32(smraw);

    const int tid  = threadIdx.x;
    const int wid  = tid >> 5;
    const int lane = tid & 31;
    const int wm = wid & 1;
    const int wn = wid >> 1;
    const int row0 = blockIdx.y * 128;
    const int col0 = blockIdx.x * 128;
    const int q4 = lane >> 2;
    const int l3 = lane & 3;
    const int lr16  = lane & 15;
    const int lhalf = (lane >> 4) * 16;

    float c[4][4][4];
#pragma unroll
    for (int m = 0; m < 4; m++)
#pragma unroll
        for (int n = 0; n < 4; n++)
#pragma unroll
            for (int q = 0; q < 4; q++) c[m][n][q] = 0.f;

    const int nch = K / 32;

    // prologue: chunks 0 and 1 into stages 0 and 1
#pragma unroll
    for (int p = 0; p < 2; p++) {
        uint32_t dst = sbase + p * GSTG;
        const int k0 = p * 32;
#pragma unroll
        for (int j = 0; j < 4; j++) {
            int i = tid + 256 * j;
            int a = i >> 9, r = (i >> 2) & 127, cc = i & 3;
            const __half* base = (a == 0) ? Ah : Bh;
            int grow = ((a == 0) ? row0 : col0) + r;
            CP_ASYNC16(dst + a * 10240 + r * 80 + cc * 16,
                       base + (size_t)grow * K + k0 + cc * 8);
        }
        CP_COMMIT();
    }

#pragma unroll 1
    for (int ch = 0; ch < nch; ch++) {
        if (ch + 2 < nch) {
            uint32_t dst = sbase + ((ch + 2) & 3) * GSTG;
            const int k0 = (ch + 2) * 32;
#pragma unroll
            for (int j = 0; j < 4; j++) {
                int i = tid + 256 * j;
                int a = i >> 9, r = (i >> 2) & 127, cc = i & 3;
                const __half* base = (a == 0) ? Ah : Bh;
                int grow = ((a == 0) ? row0 : col0) + r;
                CP_ASYNC16(dst + a * 10240 + r * 80 + cc * 16,
                           base + (size_t)grow * K + k0 + cc * 8);
            }
            CP_COMMIT();
            CP_WAIT2();
        } else if (ch + 1 < nch) {
            CP_WAIT1();
        } else {
            CP_WAIT0();
        }
        __syncthreads();

        const uint32_t sst = sbase + (ch & 3) * GSTG;

#pragma unroll
        for (int ks = 0; ks < 2; ks++) {
            uint32_t ah[4][4];
#pragma unroll
            for (int m = 0; m < 4; m++) {
                uint32_t arow = sst + (wm * 64 + m * 16 + lr16) * 80 + lhalf + ks * 32;
                LDSM_X4(ah[m][0], ah[m][1], ah[m][2], ah[m][3], arow);
            }
#pragma unroll
            for (int np = 0; np < 2; np++) {
                uint32_t brow = sst + 10240 + (wn * 32 + np * 16 + lr16) * 80 + lhalf + ks * 32;
                uint32_t h0, h1, h2, h3;
                LDSM_X4(h0, h1, h2, h3, brow);
#pragma unroll
                for (int m = 0; m < 4; m++)
                    MMA_F16(c[m][2*np],   ah[m][0], ah[m][1], ah[m][2], ah[m][3], h0, h2);
#pragma unroll
                for (int m = 0; m < 4; m++)
                    MMA_F16(c[m][2*np+1], ah[m][0], ah[m][1], ah[m][2], ah[m][3], h1, h3);
            }
        }
    }

    if (mode == 0) {
        // plain fp32 epilogue
#pragma unroll
        for (int m = 0; m < 4; m++) {
            const int r = row0 + wm * 64 + m * 16 + q4;
#pragma unroll
            for (int n = 0; n < 4; n++) {
                const int cc = col0 + wn * 32 + n * 8 + l3 * 2;
                *(float2*)(C + (size_t)r * N + cc)       = make_float2(c[m][n][0], c[m][n][1]);
                *(float2*)(C + (size_t)(r + 8) * N + cc) = make_float2(c[m][n][2], c[m][n][3]);
            }
        }
        return;
    }

    if (col0 >= NQK) {
        // V-direct: fp16 [b, h, l, e]
#pragma unroll
        for (int m = 0; m < 4; m++) {
            const int r = row0 + wm * 64 + m * 16 + q4;
            const int bi = r >> 10;
            const int li = r & 1023;
#pragma unroll
            for (int n = 0; n < 4; n++) {
                const int vc = col0 + wn * 32 + n * 8 + l3 * 2 - NQK;
                const int hh = vc >> 6, ee = vc & 63;
                size_t base = ((size_t)(bi * NH + hh) * LL + li) * HD + ee;
                *(__half2*)&g_vh[base]          = __floats2half2_rn(c[m][n][0], c[m][n][1]);
                *(__half2*)&g_vh[base + 8 * HD] = __floats2half2_rn(c[m][n][2], c[m][n][3]);
            }
        }
        return;
    }

    // ---- fused RMSNorm + RoPE epilogue (Q/K columns) ----
    // Stage fp32 accumulators to smem: 128 rows x 132 floats (pad 4).
    float* sf = (float*)smraw;
    __syncthreads();   // mainloop smem reads done before overwrite
#pragma unroll
    for (int m = 0; m < 4; m++) {
        const int rr = wm * 64 + m * 16 + q4;
#pragma unroll
        for (int n = 0; n < 4; n++) {
            const int cc = wn * 32 + n * 8 + l3 * 2;
            *(float2*)&sf[rr * 132 + cc]       = make_float2(c[m][n][0], c[m][n][1]);
            *(float2*)&sf[(rr + 8) * 132 + cc] = make_float2(c[m][n][2], c[m][n][3]);
        }
    }
    __syncthreads();

    const float ifr = exp2f(-13.287712379549449f * (float)lane * (1.0f / 32.0f));
    const float QS = 0.125f * 1.4426950408889634f;
    const bool isQ = (col0 < CC);
    const float g1 = isQ ? qg[lane]      : kg[lane];
    const float g2 = isQ ? qg[lane + 32] : kg[lane + 32];
    const int hbase = (isQ ? col0 : col0 - CC) >> 6;   // head of first 64-col half

#pragma unroll 4
    for (int t = 0; t < 32; t++) {
        const int task = wid * 32 + t;      // 0..255
        const int row  = task & 127;
        const int half64 = task >> 7;       // 0 or 1
        const int gr = row0 + row;
        const int bi = gr >> 10, li = gr & 1023;

        float x1 = sf[row * 132 + half64 * 64 + lane];
        float x2 = sf[row * 132 + half64 * 64 + lane + 32];
        float ss = x1 * x1 + x2 * x2;
#pragma unroll
        for (int o = 16; o; o >>= 1) ss += __shfl_xor_sync(0xffffffffu, ss, o);
        float r = rsqrtf(ss * (1.0f / HD) + 1e-6f);

        float ang = (float)li * ifr;
        float cs = cosf(ang), sn = sinf(ang);
        float n1 = x1 * r * g1, n2 = x2 * r * g2;
        float o1 = n1 * cs - n2 * sn;
        float o2 = n1 * sn + n2 * cs;

        const int h = hbase + half64;
        const size_t d = ((size_t)(bi * NH + h) * LL + li) * HD;
        if (isQ) {
            g_qh[d + lane]      = __float2half_rn(o1 * QS);
            g_qh[d + lane + 32] = __float2half_rn(o2 * QS);
        } else {
            g_kh[d + lane]      = __float2half_rn(o1);
            g_kh[d + lane + 32] = __float2half_rn(o2);
        }
    }
}

// ===========================================================================
// Flash attention, all single-term fp16 (round-13 core, unchanged).
// ===========================================================================
#define ASTG  18432
#define AROW  144
#define AROWW 36

__global__ __launch_bounds__(256) void attn_mma_kernel()
{
    extern __shared__ uint8_t smraw[];
    uint32_t* smw = (uint32_t*)smraw;
    const uint32_t sbase = smem_u32(smraw);

    const int tid  = threadIdx.x;
    const int w    = tid >> 5;
    const int lane = tid & 31;
    const int q4   = lane >> 2;
    const int l3   = lane & 3;
    const int qt = blockIdx.x, h = blockIdx.y, b = blockIdx.z;

    const size_t hb = (size_t)(b * NH + h) * LL * HD;
    const __half* Qh = g_qh + hb + (size_t)qt * 128 * HD;
    const __half* Kh = g_kh + hb;
    const __half* Vh = g_vh + hb;

#pragma unroll
    for (int t = 0; t < 4; t++) {
        int i = tid + 256 * t;
        int r = i >> 3, c = i & 7;
        CP_ASYNC16(sbase + r * AROW + c * 16, Qh + (size_t)r * HD + c * 8);
    }
    CP_COMMIT(); CP_WAIT0();
    __syncthreads();

    uint32_t qhf[4][4];
#pragma unroll
    for (int ks = 0; ks < 4; ks++) {
        int base = (w * 16 + q4) * AROWW + ks * 8 + l3;
        qhf[ks][0] = smw[base];       qhf[ks][1] = smw[base + 8 * AROWW];
        qhf[ks][2] = smw[base + 4];   qhf[ks][3] = smw[base + 8 * AROWW + 4];
    }
    __syncthreads();

    float m0 = -1e30f, m1 = -1e30f, ls0 = 0.f, ls1 = 0.f;
    float O[8][4];
#pragma unroll
    for (int n = 0; n < 8; n++)
#pragma unroll
        for (int q = 0; q < 4; q++) O[n][q] = 0.f;

#pragma unroll
    for (int t = 0; t < 4; t++) {
        int i = tid + 256 * t;
        int a = i >> 9, r = (i >> 3) & 63, c = i & 7;
        const __half* base = (a == 0) ? Kh : Vh;
        CP_ASYNC16(sbase + a * 9216 + r * AROW + c * 16,
                   base + (size_t)r * HD + c * 8);
    }
    CP_COMMIT();

#pragma unroll 1
    for (int kt = 0; kt < 16; kt++) {
        if (kt < 15) {
            uint32_t dst = sbase + ((kt + 1) & 1) * ASTG;
            const int r0 = (kt + 1) * 64;
#pragma unroll
            for (int t = 0; t < 4; t++) {
                int i = tid + 256 * t;
                int a = i >> 9, r = (i >> 3) & 63, c = i & 7;
                const __half* base = (a == 0) ? Kh : Vh;
                CP_ASYNC16(dst + a * 9216 + r * AROW + c * 16,
                           base + (size_t)(r0 + r) * HD + c * 8);
            }
            CP_COMMIT();
            CP_WAIT1();
        } else {
            CP_WAIT0();
        }
        __syncthreads();

        const uint32_t* KW = smw + (kt & 1) * (ASTG / 4);
        const uint32_t vbase = sbase + (kt & 1) * ASTG + 9216;

        float S[8][4];
#pragma unroll
        for (int n = 0; n < 8; n++)
#pragma unroll
            for (int q = 0; q < 4; q++) S[n][q] = 0.f;

#pragma unroll
        for (int ks = 0; ks < 4; ks++) {
#pragma unroll
            for (int g = 0; g < 2; g++) {
                uint32_t bh[4][2];
#pragma unroll
                for (int j = 0; j < 4; j++) {
                    int kb = ((g * 4 + j) * 8 + q4) * AROWW + ks * 8 + l3;
                    bh[j][0] = KW[kb];  bh[j][1] = KW[kb + 4];
                }
#pragma unroll
                for (int j = 0; j < 4; j++)
                    MMA_F16(S[g*4+j], qhf[ks][0], qhf[ks][1], qhf[ks][2], qhf[ks][3],
                            bh[j][0], bh[j][1]);
            }
        }

        float mx0 = -1e30f, mx1 = -1e30f;
#pragma unroll
        for (int nt = 0; nt < 8; nt++) {
            mx0 = fmaxf(mx0, fmaxf(S[nt][0], S[nt][1]));
            mx1 = fmaxf(mx1, fmaxf(S[nt][2], S[nt][3]));
        }
        mx0 = fmaxf(mx0, __shfl_xor_sync(0xffffffffu, mx0, 1));
        mx0 = fmaxf(mx0, __shfl_xor_sync(0xffffffffu, mx0, 2));
        mx1 = fmaxf(mx1, __shfl_xor_sync(0xffffffffu, mx1, 1));
        mx1 = fmaxf(mx1, __shfl_xor_sync(0xffffffffu, mx1, 2));
        float mn0 = fmaxf(m0, mx0), mn1 = fmaxf(m1, mx1);
        float a0 = ex2f(m0 - mn0), a1 = ex2f(m1 - mn1);
        float rs0 = 0.f, rs1 = 0.f;
#pragma unroll
        for (int nt = 0; nt < 8; nt++) {
            S[nt][0] = ex2f(S[nt][0] - mn0); S[nt][1] = ex2f(S[nt][1] - mn0);
            S[nt][2] = ex2f(S[nt][2] - mn1); S[nt][3] = ex2f(S[nt][3] - mn1);
            rs0 += S[nt][0] + S[nt][1];
            rs1 += S[nt][2] + S[nt][3];
        }
        rs0 += __shfl_xor_sync(0xffffffffu, rs0, 1);
        rs0 += __shfl_xor_sync(0xffffffffu, rs0, 2);
        rs1 += __shfl_xor_sync(0xffffffffu, rs1, 1);
        rs1 += __shfl_xor_sync(0xffffffffu, rs1, 2);
        ls0 = ls0 * a0 + rs0;  ls1 = ls1 * a1 + rs1;
        m0 = mn0;  m1 = mn1;
#pragma unroll
        for (int nt = 0; nt < 8; nt++) {
            O[nt][0] *= a0; O[nt][1] *= a0;
            O[nt][2] *= a1; O[nt][3] *= a1;
        }

        uint32_t ph[4][4];
#pragma unroll
        for (int j = 0; j < 4; j++) {
            ph[j][0] = pack2h(S[2*j][0],   S[2*j][1]);
            ph[j][1] = pack2h(S[2*j][2],   S[2*j][3]);
            ph[j][2] = pack2h(S[2*j+1][0], S[2*j+1][1]);
            ph[j][3] = pack2h(S[2*j+1][2], S[2*j+1][3]);
        }

        const uint32_t lrow = (lane & 15);
        const uint32_t lcol = ((lane >> 4) & 1) * 16;
#pragma unroll
        for (int j = 0; j < 4; j++) {
            uint32_t va = vbase + (16 * j + lrow) * AROW + lcol;
#pragma unroll
            for (int pp = 0; pp < 2; pp++) {
                uint32_t vh[2][4];
#pragma unroll
                for (int t = 0; t < 2; t++) {
                    uint32_t addr = va + (pp * 2 + t) * 32;
                    LDSM_X4_T(vh[t][0], vh[t][1], vh[t][2], vh[t][3], addr);
                }
#pragma unroll
                for (int t = 0; t < 2; t++) {
                    MMA_F16(O[4*pp+2*t],   ph[j][0], ph[j][1], ph[j][2], ph[j][3],
                            vh[t][0], vh[t][1]);
                    MMA_F16(O[4*pp+2*t+1], ph[j][0], ph[j][1], ph[j][2], ph[j][3],
                            vh[t][2], vh[t][3]);
                }
            }
        }
        __syncthreads();
    }

    const float inv0 = 1.0f / ls0, inv1 = 1.0f / ls1;
    const int row0 = qt * 128 + w * 16 + q4;
    const size_t o0 = ((size_t)b * LL + row0) * CC + h * HD;
    const size_t o1 = o0 + 8 * CC;
#pragma unroll
    for (int nt = 0; nt < 8; nt++) {
        int cc = nt * 8 + 2 * l3;
        *(uint32_t*)(g_aoh + o0 + cc) = pack2h(O[nt][0] * inv0, O[nt][1] * inv0);
        *(uint32_t*)(g_aoh + o1 + cc) = pack2h(O[nt][2] * inv1, O[nt][3] * inv1);
    }
}

// ---------------------------------------------------------------------------
extern "C" void kernel_launch(void* const* d_in, const int* in_sizes, int n_in,
                              void* d_out, int out_size)
{
    const float* x      = (const float*)d_in[0];
    const float* w_qkv  = (const float*)d_in[1];
    const float* qgam   = (const float*)d_in[2];
    const float* kgam   = (const float*)d_in[3];
    const float* w_out  = (const float*)d_in[4];
    float* out = (float*)d_out;

    __half *xh, *wqh, *woh, *aoh;
    cudaGetSymbolAddress((void**)&xh, g_xh);
    cudaGetSymbolAddress((void**)&wqh, g_wqh);
    cudaGetSymbolAddress((void**)&woh, g_woh);
    cudaGetSymbolAddress((void**)&aoh, g_aoh);

    cudaFuncSetAttribute(gemm_1t_kernel,
                         cudaFuncAttributeMaxDynamicSharedMemorySize, 4 * GSTG);
    cudaFuncSetAttribute(attn_mma_kernel,
                         cudaFuncAttributeMaxDynamicSharedMemorySize, 2 * ASTG);

    // 0) prepare all fp16 operands in one launch
    const int n0 = M_TOT * CC / 4, n1 = NQKV * CC / 4, n2 = CC * CC / 4;
    cvt3_kernel<<<(n0 + n1 + n2 + 255) / 256, 256>>>(
        x, xh, n0, w_qkv, wqh, n1, w_out, woh, n2);

    // 1) QKV projection + fused RMSNorm/RoPE (Q/K) + V-direct epilogue
    gemm_1t_kernel<<<dim3(NQKV / 128, M_TOT / 128), 256, 4 * GSTG>>>(
        xh, wqh, nullptr, 1, M_TOT, NQKV, CC, qgam, kgam);

    // 2) Flash attention (all 1-term)
    attn_mma_kernel<<<dim3(LL / 128, NH, BB), 256, 2 * ASTG>>>();

    // 3) Output projection (1-term, fp32 out)
    gemm_1t_kernel<<<dim3(CC / 128, M_TOT / 128), 256, 4 * GSTG>>>(
        aoh, woh, out, 0, M_TOT, CC, CC, nullptr, nullptr);
}

// round 16
// speedup vs baseline: 7.1976x; 1.0261x over previous
#include <cuda_runtime.h>
#include <cuda_fp16.h>
#include <cstdint>
#include <math.h>

#define BB 8
#define LL 1024
#define CC 768
#define NH 12
#define HD 64
#define M_TOT (BB*LL)      /* 8192 */
#define NQKV (3*CC)        /* 2304 */
#define NQK  (2*CC)        /* 1536 */

// ---------------- scratch (device globals: no allocation allowed) ----------
__device__ __half g_xh[(size_t)M_TOT * CC];
__device__ __half g_wqh[(size_t)NQKV * CC];
__device__ __half g_woh[(size_t)CC * CC];
__device__ __half g_aoh[(size_t)M_TOT * CC];
__device__ __half g_qh[(size_t)BB*NH*LL*HD];
__device__ __half g_kh[(size_t)BB*NH*LL*HD];
__device__ __half g_vh[(size_t)BB*NH*LL*HD];

// ---------------------------------------------------------------------------
__device__ __forceinline__ float ex2f(float x) {
    float y;
    asm("ex2.approx.ftz.f32 %0, %1;" : "=f"(y) : "f"(x));
    return y;
}
__device__ __forceinline__ uint32_t smem_u32(const void* p) {
    uint32_t a;
    asm("{ .reg .u64 t; cvta.to.shared.u64 t, %1; cvt.u32.u64 %0, t; }"
        : "=r"(a) : "l"(p));
    return a;
}
__device__ __forceinline__ uint32_t pack2h(float a, float b) {
    __half2 v = __floats2half2_rn(a, b);
    return *(uint32_t*)&v;
}

#define MMA_F16(Cr, A0, A1, A2, A3, B0, B1) \
    asm volatile("mma.sync.aligned.m16n8k16.row.col.f32.f16.f16.f32 " \
        "{%0,%1,%2,%3}, {%4,%5,%6,%7}, {%8,%9}, {%0,%1,%2,%3};" \
        : "+f"((Cr)[0]), "+f"((Cr)[1]), "+f"((Cr)[2]), "+f"((Cr)[3]) \
        : "r"(A0), "r"(A1), "r"(A2), "r"(A3), "r"(B0), "r"(B1))

#define LDSM_X4(r0, r1, r2, r3, addr) \
    asm volatile("ldmatrix.sync.aligned.m8n8.x4.shared.b16 {%0,%1,%2,%3}, [%4];" \
        : "=r"(r0), "=r"(r1), "=r"(r2), "=r"(r3) : "r"(addr))

#define LDSM_X4_T(r0, r1, r2, r3, addr) \
    asm volatile("ldmatrix.sync.aligned.m8n8.x4.trans.shared.b16 {%0,%1,%2,%3}, [%4];" \
        : "=r"(r0), "=r"(r1), "=r"(r2), "=r"(r3) : "r"(addr))

#define CP_ASYNC16(dst, src) \
    asm volatile("cp.async.cg.shared.global [%0], [%1], 16;" \
                 :: "r"(dst), "l"(src) : "memory")
#define CP_COMMIT() asm volatile("cp.async.commit_group;" ::: "memory")
#define CP_WAIT0()  asm volatile("cp.async.wait_group 0;" ::: "memory")
#define CP_WAIT1()  asm volatile("cp.async.wait_group 1;" ::: "memory")

// ===========================================================================
// merged prep: fp32 -> fp16 over three arrays in one launch
// ===========================================================================
__global__ __launch_bounds__(256) void cvt3_kernel(
    const float* __restrict__ s0, __half* __restrict__ h0, int n0,
    const float* __restrict__ s1, __half* __restrict__ h1, int n1,
    const float* __restrict__ s2, __half* __restrict__ h2, int n2)
{
    int i = blockIdx.x * 256 + threadIdx.x;
    const float* s; __half* h;
    if (i < n0)           { s = s0;  h = h0; }
    else if (i < n0 + n1) { i -= n0; s = s1; h = h1; }
    else                  { i -= n0 + n1; if (i >= n2) return; s = s2; h = h2; }
    float4 v = ((const float4*)s)[i];
    ((__half2*)h)[2*i]   = __floats2half2_rn(v.x, v.y);
    ((__half2*)h)[2*i+1] = __floats2half2_rn(v.z, v.w);
}

// ===========================================================================
// Pipelined fp16 1-term GEMM (NT), BK=64, 2-stage trailing-sync pipeline
// (attention-style: 64 warp-MMAs per barrier pair, 144B rows).
// mode 0: plain fp32 C epilogue (out-proj).
// mode 1: QKV — col0 >= NQK: V-direct fp16 [b,h,l,e];
//                col0 <  NQK: fused RMSNorm+RoPE epilogue -> g_qh/g_kh.
// Stage (36864B): A@0 (128x144B), B@18432. 2 stages = 73728B dyn smem.
// ===========================================================================
#define GSTG 36864
#define GROW 144

__global__ __launch_bounds__(256) void gemm_1t_kernel(
    const __half* __restrict__ Ah, const __half* __restrict__ Bh,
    float* __restrict__ C, int mode, int M, int N, int K,
    const float* __restrict__ qg, const float* __restrict__ kg)
{
    extern __shared__ uint8_t smraw[];
    const uint32_t sbase = smem_u32(smraw);

    const int tid  = threadIdx.x;
    const int wid  = tid >> 5;
    const int lane = tid & 31;
    const int wm = wid & 1;
    const int wn = wid >> 1;
    const int row0 = blockIdx.y * 128;
    const int col0 = blockIdx.x * 128;
    const int q4 = lane >> 2;
    const int l3 = lane & 3;
    const int lr16  = lane & 15;
    const int lhalf = (lane >> 4) * 16;

    float c[4][4][4];
#pragma unroll
    for (int m = 0; m < 4; m++)
#pragma unroll
        for (int n = 0; n < 4; n++)
#pragma unroll
            for (int q = 0; q < 4; q++) c[m][n][q] = 0.f;

    const int nch = K / 64;

    // prologue: chunk 0 into stage 0
#pragma unroll
    for (int j = 0; j < 8; j++) {
        int i = tid + 256 * j;
        int a = i >> 10, r = (i >> 3) & 127, cc = i & 7;
        const __half* base = (a == 0) ? Ah : Bh;
        int grow = ((a == 0) ? row0 : col0) + r;
        CP_ASYNC16(sbase + a * 18432 + r * GROW + cc * 16,
                   base + (size_t)grow * K + cc * 8);
    }
    CP_COMMIT();

#pragma unroll 1
    for (int ch = 0; ch < nch; ch++) {
        if (ch + 1 < nch) {
            uint32_t dst = sbase + ((ch + 1) & 1) * GSTG;
            const int k0 = (ch + 1) * 64;
#pragma unroll
            for (int j = 0; j < 8; j++) {
                int i = tid + 256 * j;
                int a = i >> 10, r = (i >> 3) & 127, cc = i & 7;
                const __half* base = (a == 0) ? Ah : Bh;
                int grow = ((a == 0) ? row0 : col0) + r;
                CP_ASYNC16(dst + a * 18432 + r * GROW + cc * 16,
                           base + (size_t)grow * K + k0 + cc * 8);
            }
            CP_COMMIT();
            CP_WAIT1();
        } else {
            CP_WAIT0();
        }
        __syncthreads();

        const uint32_t sst = sbase + (ch & 1) * GSTG;

#pragma unroll
        for (int ks = 0; ks < 4; ks++) {
            uint32_t ah[4][4];
#pragma unroll
            for (int m = 0; m < 4; m++) {
                uint32_t arow = sst + (wm * 64 + m * 16 + lr16) * GROW + lhalf + ks * 32;
                LDSM_X4(ah[m][0], ah[m][1], ah[m][2], ah[m][3], arow);
            }
#pragma unroll
            for (int np = 0; np < 2; np++) {
                uint32_t brow = sst + 18432 + (wn * 32 + np * 16 + lr16) * GROW + lhalf + ks * 32;
                uint32_t h0, h1, h2, h3;
                LDSM_X4(h0, h1, h2, h3, brow);
#pragma unroll
                for (int m = 0; m < 4; m++)
                    MMA_F16(c[m][2*np],   ah[m][0], ah[m][1], ah[m][2], ah[m][3], h0, h2);
#pragma unroll
                for (int m = 0; m < 4; m++)
                    MMA_F16(c[m][2*np+1], ah[m][0], ah[m][1], ah[m][2], ah[m][3], h1, h3);
            }
        }
        __syncthreads();   // stage (ch&1) reads done before iter ch+1 overwrites
    }

    if (mode == 0) {
#pragma unroll
        for (int m = 0; m < 4; m++) {
            const int r = row0 + wm * 64 + m * 16 + q4;
#pragma unroll
            for (int n = 0; n < 4; n++) {
                const int cc = col0 + wn * 32 + n * 8 + l3 * 2;
                *(float2*)(C + (size_t)r * N + cc)       = make_float2(c[m][n][0], c[m][n][1]);
                *(float2*)(C + (size_t)(r + 8) * N + cc) = make_float2(c[m][n][2], c[m][n][3]);
            }
        }
        return;
    }

    if (col0 >= NQK) {
        // V-direct: fp16 [b, h, l, e]
#pragma unroll
        for (int m = 0; m < 4; m++) {
            const int r = row0 + wm * 64 + m * 16 + q4;
            const int bi = r >> 10;
            const int li = r & 1023;
#pragma unroll
            for (int n = 0; n < 4; n++) {
                const int vc = col0 + wn * 32 + n * 8 + l3 * 2 - NQK;
                const int hh = vc >> 6, ee = vc & 63;
                size_t base = ((size_t)(bi * NH + hh) * LL + li) * HD + ee;
                *(__half2*)&g_vh[base]          = __floats2half2_rn(c[m][n][0], c[m][n][1]);
                *(__half2*)&g_vh[base + 8 * HD] = __floats2half2_rn(c[m][n][2], c[m][n][3]);
            }
        }
        return;
    }

    // ---- fused RMSNorm + RoPE epilogue (Q/K columns) ----
    float* sf = (float*)smraw;
    __syncthreads();
#pragma unroll
    for (int m = 0; m < 4; m++) {
        const int rr = wm * 64 + m * 16 + q4;
#pragma unroll
        for (int n = 0; n < 4; n++) {
            const int cc = wn * 32 + n * 8 + l3 * 2;
            *(float2*)&sf[rr * 132 + cc]       = make_float2(c[m][n][0], c[m][n][1]);
            *(float2*)&sf[(rr + 8) * 132 + cc] = make_float2(c[m][n][2], c[m][n][3]);
        }
    }
    __syncthreads();

    const float ifr = exp2f(-13.287712379549449f * (float)lane * (1.0f / 32.0f));
    const float QS = 0.125f * 1.4426950408889634f;
    const bool isQ = (col0 < CC);
    const float g1 = isQ ? qg[lane]      : kg[lane];
    const float g2 = isQ ? qg[lane + 32] : kg[lane + 32];
    const int hbase = (isQ ? col0 : col0 - CC) >> 6;

#pragma unroll 4
    for (int t = 0; t < 32; t++) {
        const int task = wid * 32 + t;
        const int row  = task & 127;
        const int half64 = task >> 7;
        const int gr = row0 + row;
        const int bi = gr >> 10, li = gr & 1023;

        float x1 = sf[row * 132 + half64 * 64 + lane];
        float x2 = sf[row * 132 + half64 * 64 + lane + 32];
        float ss = x1 * x1 + x2 * x2;
#pragma unroll
        for (int o = 16; o; o >>= 1) ss += __shfl_xor_sync(0xffffffffu, ss, o);
        float r = rsqrtf(ss * (1.0f / HD) + 1e-6f);

        float ang = (float)li * ifr;
        float cs = cosf(ang), sn = sinf(ang);
        float n1 = x1 * r * g1, n2 = x2 * r * g2;
        float o1 = n1 * cs - n2 * sn;
        float o2 = n1 * sn + n2 * cs;

        const int h = hbase + half64;
        const size_t d = ((size_t)(bi * NH + h) * LL + li) * HD;
        if (isQ) {
            g_qh[d + lane]      = __float2half_rn(o1 * QS);
            g_qh[d + lane + 32] = __float2half_rn(o2 * QS);
        } else {
            g_kh[d + lane]      = __float2half_rn(o1);
            g_kh[d + lane + 32] = __float2half_rn(o2);
        }
    }
}

// ===========================================================================
// Flash attention, all single-term fp16 (round-13 core, unchanged).
// ===========================================================================
#define ASTG  18432
#define AROW  144
#define AROWW 36

__global__ __launch_bounds__(256) void attn_mma_kernel()
{
    extern __shared__ uint8_t smraw[];
    uint32_t* smw = (uint32_t*)smraw;
    const uint32_t sbase = smem_u32(smraw);

    const int tid  = threadIdx.x;
    const int w    = tid >> 5;
    const int lane = tid & 31;
    const int q4   = lane >> 2;
    const int l3   = lane & 3;
    const int qt = blockIdx.x, h = blockIdx.y, b = blockIdx.z;

    const size_t hb = (size_t)(b * NH + h) * LL * HD;
    const __half* Qh = g_qh + hb + (size_t)qt * 128 * HD;
    const __half* Kh = g_kh + hb;
    const __half* Vh = g_vh + hb;

#pragma unroll
    for (int t = 0; t < 4; t++) {
        int i = tid + 256 * t;
        int r = i >> 3, c = i & 7;
        CP_ASYNC16(sbase + r * AROW + c * 16, Qh + (size_t)r * HD + c * 8);
    }
    CP_COMMIT(); CP_WAIT0();
    __syncthreads();

    uint32_t qhf[4][4];
#pragma unroll
    for (int ks = 0; ks < 4; ks++) {
        int base = (w * 16 + q4) * AROWW + ks * 8 + l3;
        qhf[ks][0] = smw[base];       qhf[ks][1] = smw[base + 8 * AROWW];
        qhf[ks][2] = smw[base + 4];   qhf[ks][3] = smw[base + 8 * AROWW + 4];
    }
    __syncthreads();

    float m0 = -1e30f, m1 = -1e30f, ls0 = 0.f, ls1 = 0.f;
    float O[8][4];
#pragma unroll
    for (int n = 0; n < 8; n++)
#pragma unroll
        for (int q = 0; q < 4; q++) O[n][q] = 0.f;

#pragma unroll
    for (int t = 0; t < 4; t++) {
        int i = tid + 256 * t;
        int a = i >> 9, r = (i >> 3) & 63, c = i & 7;
        const __half* base = (a == 0) ? Kh : Vh;
        CP_ASYNC16(sbase + a * 9216 + r * AROW + c * 16,
                   base + (size_t)r * HD + c * 8);
    }
    CP_COMMIT();

#pragma unroll 1
    for (int kt = 0; kt < 16; kt++) {
        if (kt < 15) {
            uint32_t dst = sbase + ((kt + 1) & 1) * ASTG;
            const int r0 = (kt + 1) * 64;
#pragma unroll
            for (int t = 0; t < 4; t++) {
                int i = tid + 256 * t;
                int a = i >> 9, r = (i >> 3) & 63, c = i & 7;
                const __half* base = (a == 0) ? Kh : Vh;
                CP_ASYNC16(dst + a * 9216 + r * AROW + c * 16,
                           base + (size_t)(r0 + r) * HD + c * 8);
            }
            CP_COMMIT();
            CP_WAIT1();
        } else {
            CP_WAIT0();
        }
        __syncthreads();

        const uint32_t* KW = smw + (kt & 1) * (ASTG / 4);
        const uint32_t vbase = sbase + (kt & 1) * ASTG + 9216;

        float S[8][4];
#pragma unroll
        for (int n = 0; n < 8; n++)
#pragma unroll
            for (int q = 0; q < 4; q++) S[n][q] = 0.f;

#pragma unroll
        for (int ks = 0; ks < 4; ks++) {
#pragma unroll
            for (int g = 0; g < 2; g++) {
                uint32_t bh[4][2];
#pragma unroll
                for (int j = 0; j < 4; j++) {
                    int kb = ((g * 4 + j) * 8 + q4) * AROWW + ks * 8 + l3;
                    bh[j][0] = KW[kb];  bh[j][1] = KW[kb + 4];
                }
#pragma unroll
                for (int j = 0; j < 4; j++)
                    MMA_F16(S[g*4+j], qhf[ks][0], qhf[ks][1], qhf[ks][2], qhf[ks][3],
                            bh[j][0], bh[j][1]);
            }
        }

        float mx0 = -1e30f, mx1 = -1e30f;
#pragma unroll
        for (int nt = 0; nt < 8; nt++) {
            mx0 = fmaxf(mx0, fmaxf(S[nt][0], S[nt][1]));
            mx1 = fmaxf(mx1, fmaxf(S[nt][2], S[nt][3]));
        }
        mx0 = fmaxf(mx0, __shfl_xor_sync(0xffffffffu, mx0, 1));
        mx0 = fmaxf(mx0, __shfl_xor_sync(0xffffffffu, mx0, 2));
        mx1 = fmaxf(mx1, __shfl_xor_sync(0xffffffffu, mx1, 1));
        mx1 = fmaxf(mx1, __shfl_xor_sync(0xffffffffu, mx1, 2));
        float mn0 = fmaxf(m0, mx0), mn1 = fmaxf(m1, mx1);
        float a0 = ex2f(m0 - mn0), a1 = ex2f(m1 - mn1);
        float rs0 = 0.f, rs1 = 0.f;
#pragma unroll
        for (int nt = 0; nt < 8; nt++) {
            S[nt][0] = ex2f(S[nt][0] - mn0); S[nt][1] = ex2f(S[nt][1] - mn0);
            S[nt][2] = ex2f(S[nt][2] - mn1); S[nt][3] = ex2f(S[nt][3] - mn1);
            rs0 += S[nt][0] + S[nt][1];
            rs1 += S[nt][2] + S[nt][3];
        }
        rs0 += __shfl_xor_sync(0xffffffffu, rs0, 1);
        rs0 += __shfl_xor_sync(0xffffffffu, rs0, 2);
        rs1 += __shfl_xor_sync(0xffffffffu, rs1, 1);
        rs1 += __shfl_xor_sync(0xffffffffu, rs1, 2);
        ls0 = ls0 * a0 + rs0;  ls1 = ls1 * a1 + rs1;
        m0 = mn0;  m1 = mn1;
#pragma unroll
        for (int nt = 0; nt < 8; nt++) {
            O[nt][0] *= a0; O[nt][1] *= a0;
            O[nt][2] *= a1; O[nt][3] *= a1;
        }

        uint32_t ph[4][4];
#pragma unroll
        for (int j = 0; j < 4; j++) {
            ph[j][0] = pack2h(S[2*j][0],   S[2*j][1]);
            ph[j][1] = pack2h(S[2*j][2],   S[2*j][3]);
            ph[j][2] = pack2h(S[2*j+1][0], S[2*j+1][1]);
            ph[j][3] = pack2h(S[2*j+1][2], S[2*j+1][3]);
        }

        const uint32_t lrow = (lane & 15);
        const uint32_t lcol = ((lane >> 4) & 1) * 16;
#pragma unroll
        for (int j = 0; j < 4; j++) {
            uint32_t va = vbase + (16 * j + lrow) * AROW + lcol;
#pragma unroll
            for (int pp = 0; pp < 2; pp++) {
                uint32_t vh[2][4];
#pragma unroll
                for (int t = 0; t < 2; t++) {
                    uint32_t addr = va + (pp * 2 + t) * 32;
                    LDSM_X4_T(vh[t][0], vh[t][1], vh[t][2], vh[t][3], addr);
                }
#pragma unroll
                for (int t = 0; t < 2; t++) {
                    MMA_F16(O[4*pp+2*t],   ph[j][0], ph[j][1], ph[j][2], ph[j][3],
                            vh[t][0], vh[t][1]);
                    MMA_F16(O[4*pp+2*t+1], ph[j][0], ph[j][1], ph[j][2], ph[j][3],
                            vh[t][2], vh[t][3]);
                }
            }
        }
        __syncthreads();
    }

    const float inv0 = 1.0f / ls0, inv1 = 1.0f / ls1;
    const int row0 = qt * 128 + w * 16 + q4;
    const size_t o0 = ((size_t)b * LL + row0) * CC + h * HD;
    const size_t o1 = o0 + 8 * CC;
#pragma unroll
    for (int nt = 0; nt < 8; nt++) {
        int cc = nt * 8 + 2 * l3;
        *(uint32_t*)(g_aoh + o0 + cc) = pack2h(O[nt][0] * inv0, O[nt][1] * inv0);
        *(uint32_t*)(g_aoh + o1 + cc) = pack2h(O[nt][2] * inv1, O[nt][3] * inv1);
    }
}

// ---------------------------------------------------------------------------
extern "C" void kernel_launch(void* const* d_in, const int* in_sizes, int n_in,
                              void* d_out, int out_size)
{
    const float* x      = (const float*)d_in[0];
    const float* w_qkv  = (const float*)d_in[1];
    const float* qgam   = (const float*)d_in[2];
    const float* kgam   = (const float*)d_in[3];
    const float* w_out  = (const float*)d_in[4];
    float* out = (float*)d_out;

    __half *xh, *wqh, *woh, *aoh;
    cudaGetSymbolAddress((void**)&xh, g_xh);
    cudaGetSymbolAddress((void**)&wqh, g_wqh);
    cudaGetSymbolAddress((void**)&woh, g_woh);
    cudaGetSymbolAddress((void**)&aoh, g_aoh);

    cudaFuncSetAttribute(gemm_1t_kernel,
                         cudaFuncAttributeMaxDynamicSharedMemorySize, 2 * GSTG);
    cudaFuncSetAttribute(attn_mma_kernel,
                         cudaFuncAttributeMaxDynamicSharedMemorySize, 2 * ASTG);

    // 0) prepare all fp16 operands in one launch
    const int n0 = M_TOT * CC / 4, n1 = NQKV * CC / 4, n2 = CC * CC / 4;
    cvt3_kernel<<<(n0 + n1 + n2 + 255) / 256, 256>>>(
        x, xh, n0, w_qkv, wqh, n1, w_out, woh, n2);

    // 1) QKV projection + fused RMSNorm/RoPE (Q/K) + V-direct epilogue
    gemm_1t_kernel<<<dim3(NQKV / 128, M_TOT / 128), 256, 2 * GSTG>>>(
        xh, wqh, nullptr, 1, M_TOT, NQKV, CC, qgam, kgam);

    // 2) Flash attention (all 1-term)
    attn_mma_kernel<<<dim3(LL / 128, NH, BB), 256, 2 * ASTG>>>();

    // 3) Output projection (1-term, fp32 out)
    gemm_1t_kernel<<<dim3(CC / 128, M_TOT / 128), 256, 2 * GSTG>>>(
        aoh, woh, out, 0, M_TOT, CC, CC, nullptr, nullptr);
}